// round 8
// baseline (speedup 1.0000x reference)
#include <cuda_runtime.h>
#include <math.h>
#include <stdint.h>

#define BATCH 4
#define N1V 2048
#define N2V 2048
#define DIMV 512
#define NHEAD 8
#define HD 64

// Scratch (device globals: no allocation allowed in kernel_launch)
__device__ __align__(256) float g_Q   [BATCH * N1V * DIMV];
__device__ __align__(256) float g_K   [BATCH * N2V * DIMV];
__device__ __align__(256) float g_V   [BATCH * N2V * DIMV];
__device__ __align__(256) float g_CTX [BATCH * N1V * DIMV];
__device__ __align__(256) float g_U   [BATCH * N1V * DIMV];
__device__ __align__(256) float g_g1r [BATCH * N1V * DIMV];
__device__ __align__(256) float g_g2r [BATCH * N2V * DIMV];
__device__ __align__(256) float g_Wqr [DIMV * DIMV];
__device__ __align__(256) float g_Wkr [DIMV * DIMV];
__device__ __align__(256) float g_Wvr [DIMV * DIMV];
__device__ __align__(256) float g_Wor [DIMV * DIMV];
__device__ __align__(256) float g_Wr  [DIMV * DIMV];
__device__ __align__(256) float g_M   [DIMV * DIMV];     // W @ Wo (tf32-rounded)
__device__ __align__(256) float g_wbo [DIMV];            // W @ bo

// ---------------------------------------------------------------------------
__device__ __forceinline__ uint32_t f2tf(float x) {
    uint32_t u;
    asm("cvt.rna.tf32.f32 %0, %1;" : "=r"(u) : "f"(x));
    return u;
}

__device__ __forceinline__ void mma_tf32(float* c, const uint32_t* a, const uint32_t* b) {
    asm volatile(
        "mma.sync.aligned.m16n8k8.row.col.f32.tf32.tf32.f32 "
        "{%0,%1,%2,%3}, {%4,%5,%6,%7}, {%8,%9}, {%0,%1,%2,%3};\n"
        : "+f"(c[0]), "+f"(c[1]), "+f"(c[2]), "+f"(c[3])
        : "r"(a[0]), "r"(a[1]), "r"(a[2]), "r"(a[3]), "r"(b[0]), "r"(b[1]));
}

__device__ __forceinline__ void cp16(uint32_t dst_smem, const void* src) {
    asm volatile("cp.async.cg.shared.global [%0], [%1], 16;\n" :: "r"(dst_smem), "l"(src));
}
#define CP_COMMIT() asm volatile("cp.async.commit_group;\n" ::: "memory")
#define CP_WAIT(n)  asm volatile("cp.async.wait_group %0;\n" :: "n"(n) : "memory")

__device__ __forceinline__ uint32_t smaddr(const void* p) {
    return (uint32_t)__cvta_generic_to_shared(p);
}

// ---------------------------------------------------------------------------
// Elementwise tf32 pre-round
// ---------------------------------------------------------------------------
__global__ __launch_bounds__(256) void round_tf32_k(
    const float* __restrict__ in, float* __restrict__ out, int n4)
{
    const int i = blockIdx.x * 256 + threadIdx.x;
    if (i < n4) {
        float4 v = ((const float4*)in)[i];
        float4 r;
        r.x = __uint_as_float(f2tf(v.x));
        r.y = __uint_as_float(f2tf(v.y));
        r.z = __uint_as_float(f2tf(v.z));
        r.w = __uint_as_float(f2tf(v.w));
        ((float4*)out)[i] = r;
    }
}

// ---------------------------------------------------------------------------
// tf32 TC GEMM, 2-stage cp.async pipeline. Inputs must be tf32-pre-rounded.
// ---------------------------------------------------------------------------
#define AS_STRIDE 36
#define BS_STRIDE_NT 132
#define STG_U32 4608
#define GEMM_SMEM (4 * STG_U32 * 4)        // 73728 B

template<bool TRANSB>
__device__ __forceinline__ void g_prefetch(
    uint32_t* As, uint32_t* Bs, const float* A, const float* Wt,
    int m0, int n0, int k0, int K, int N, int t)
{
#pragma unroll
    for (int j = 0; j < 4; j++) {
        const int idx = t + 256 * j;
        const int row = idx >> 3, c4 = (idx & 7) << 2;
        cp16(smaddr(&As[row * AS_STRIDE + c4]),
             A + (size_t)(m0 + row) * K + k0 + c4);
    }
    if (TRANSB) {
#pragma unroll
        for (int j = 0; j < 4; j++) {
            const int idx = t + 256 * j;
            const int row = idx >> 3, c4 = (idx & 7) << 2;
            cp16(smaddr(&Bs[row * AS_STRIDE + c4]),
                 Wt + (size_t)(n0 + row) * K + k0 + c4);
        }
    } else {
#pragma unroll
        for (int j = 0; j < 4; j++) {
            const int idx = t + 256 * j;
            const int row = idx >> 5, n4 = (idx & 31) << 2;
            cp16(smaddr(&Bs[row * BS_STRIDE_NT + n4]),
                 Wt + (size_t)(k0 + row) * N + n0 + n4);
        }
    }
}

template<bool TRANSB, bool HASBIAS, bool ROUND>
__global__ __launch_bounds__(256, 2) void gemm_tc(
    const float* __restrict__ A, const float* __restrict__ Wt,
    const float* __restrict__ bias, float* __restrict__ C,
    int M, int N, int K)
{
    extern __shared__ uint32_t sm[];

    const int t    = threadIdx.x;
    const int w    = t >> 5;
    const int lane = t & 31;
    const int g    = lane >> 2;
    const int tid4 = lane & 3;
    const int m0   = blockIdx.y * 128, n0 = blockIdx.x * 128;
    const int warpM = (w >> 2) * 64;
    const int warpN = (w & 3) * 32;

    float acc[4][4][4];
#pragma unroll
    for (int mi = 0; mi < 4; mi++)
#pragma unroll
        for (int ni = 0; ni < 4; ni++)
#pragma unroll
            for (int c = 0; c < 4; c++) acc[mi][ni][c] = 0.f;

    const int nIter = K / 32;   // 16

    g_prefetch<TRANSB>(sm, sm + 2 * STG_U32, A, Wt, m0, n0, 0, K, N, t);
    CP_COMMIT();

    int st = 0;
    for (int it = 0; it < nIter; it++) {
        if (it + 1 < nIter) {
            g_prefetch<TRANSB>(sm + (st ^ 1) * STG_U32, sm + (2 + (st ^ 1)) * STG_U32,
                               A, Wt, m0, n0, (it + 1) * 32, K, N, t);
            CP_COMMIT();
            CP_WAIT(1);
        } else {
            CP_WAIT(0);
        }
        __syncthreads();

        uint32_t* As = sm + st * STG_U32;
        uint32_t* Bs = sm + (2 + st) * STG_U32;

#pragma unroll
        for (int ks = 0; ks < 4; ks++) {
            uint32_t a[4][4], b[4][2];
            const int kc = tid4 + 8 * ks;
#pragma unroll
            for (int mi = 0; mi < 4; mi++) {
                const int r = warpM + 16 * mi + g;
                a[mi][0] = As[r * AS_STRIDE + kc];
                a[mi][1] = As[(r + 8) * AS_STRIDE + kc];
                a[mi][2] = As[r * AS_STRIDE + kc + 4];
                a[mi][3] = As[(r + 8) * AS_STRIDE + kc + 4];
            }
#pragma unroll
            for (int ni = 0; ni < 4; ni++) {
                const int n = warpN + 8 * ni + g;
                if (TRANSB) {
                    b[ni][0] = Bs[n * AS_STRIDE + kc];
                    b[ni][1] = Bs[n * AS_STRIDE + kc + 4];
                } else {
                    b[ni][0] = Bs[kc * BS_STRIDE_NT + n];
                    b[ni][1] = Bs[(kc + 4) * BS_STRIDE_NT + n];
                }
            }
#pragma unroll
            for (int mi = 0; mi < 4; mi++)
#pragma unroll
                for (int ni = 0; ni < 4; ni++)
                    mma_tf32(acc[mi][ni], a[mi], b[ni]);
        }
        __syncthreads();
        st ^= 1;
    }

#pragma unroll
    for (int mi = 0; mi < 4; mi++) {
#pragma unroll
        for (int ni = 0; ni < 4; ni++) {
            const int row = m0 + warpM + 16 * mi + g;
            const int col = n0 + warpN + 8 * ni + 2 * tid4;
            float bx = 0.f, by = 0.f;
            if (HASBIAS) { bx = bias[col]; by = bias[col + 1]; }
            float v00 = acc[mi][ni][0] + bx, v01 = acc[mi][ni][1] + by;
            float v10 = acc[mi][ni][2] + bx, v11 = acc[mi][ni][3] + by;
            if (ROUND) {
                v00 = __uint_as_float(f2tf(v00)); v01 = __uint_as_float(f2tf(v01));
                v10 = __uint_as_float(f2tf(v10)); v11 = __uint_as_float(f2tf(v11));
            }
            *(float2*)(C + (size_t)row * N + col)       = make_float2(v00, v01);
            *(float2*)(C + (size_t)(row + 8) * N + col) = make_float2(v10, v11);
        }
    }
}

// ---------------------------------------------------------------------------
// Flash attention, tf32 TC. Q/K/V must be tf32-pre-rounded (raw loads).
// Block = 128 q-rows x (b,h). 256 threads, 8 warps x 16 q-rows. BKV=64.
// Q fragments in registers; Ps aliases Qs; K/V double-buffered cp.async.
// ctx written in full fp32 (feeds score dot only).
// ---------------------------------------------------------------------------
#define BQ 128
#define BKV 64
#define ASTR 68
#define KV_BASE   (BQ * ASTR)
#define V_BASE    (KV_BASE + 2 * BKV * ASTR)
#define ATTN_SMEM ((BQ * ASTR + 4 * BKV * ASTR) * 4)   // 104448 B

__device__ __forceinline__ void kv_prefetch(
    uint32_t* sm, const float* Kb, const float* Vb, int kt, int st, int t)
{
    uint32_t* Ks = sm + KV_BASE + st * BKV * ASTR;
    uint32_t* Vs = sm + V_BASE  + st * BKV * ASTR;
#pragma unroll
    for (int j = 0; j < 4; j++) {
        const int idx = t + 256 * j;
        const int row = idx >> 4, c4 = (idx & 15) << 2;
        cp16(smaddr(&Ks[row * ASTR + c4]),
             Kb + (size_t)(kt * BKV + row) * DIMV + c4);
    }
#pragma unroll
    for (int j = 0; j < 4; j++) {
        const int idx = t + 256 * j;
        const int row = idx >> 4, c4 = (idx & 15) << 2;
        cp16(smaddr(&Vs[row * ASTR + c4]),
             Vb + (size_t)(kt * BKV + row) * DIMV + c4);
    }
}

__global__ __launch_bounds__(256) void attn_tc(
    const float* __restrict__ Q, const float* __restrict__ K,
    const float* __restrict__ V, float* __restrict__ ctx)
{
    extern __shared__ uint32_t sm[];
    uint32_t* Qs = sm;     // aliased as Ps after fragment extraction
    uint32_t* Ps = sm;

    const int qb = blockIdx.x;
    const int bh = blockIdx.y;
    const int b  = bh >> 3, h = bh & 7;
    const int t  = threadIdx.x;
    const int w  = t >> 5, lane = t & 31;
    const int g  = lane >> 2, tid4 = lane & 3;

    const float* Qb = Q + ((size_t)b * N1V + qb * BQ) * DIMV + h * HD;
    const float* Kb = K + (size_t)b * N2V * DIMV + h * HD;
    const float* Vb = V + (size_t)b * N2V * DIMV + h * HD;

    // Q tile via cp.async (group 0)
#pragma unroll
    for (int j = 0; j < 8; j++) {
        const int idx = t + 256 * j;
        const int row = idx >> 4, c4 = (idx & 15) << 2;
        cp16(smaddr(&Qs[row * ASTR + c4]), Qb + (size_t)row * DIMV + c4);
    }
    CP_COMMIT();
    // KV tile 0 (group 1)
    kv_prefetch(sm, Kb, Vb, 0, 0, t);
    CP_COMMIT();

    CP_WAIT(1);          // Q done (KV0 may be in flight)
    __syncthreads();

    // Extract Q fragments (warp-private rows w*16..w*16+15)
    uint32_t qf[8][4];
    const int r = w * 16 + g;
#pragma unroll
    for (int ks = 0; ks < 8; ks++) {
        const int kc = tid4 + 8 * ks;
        qf[ks][0] = Qs[r * ASTR + kc];
        qf[ks][1] = Qs[(r + 8) * ASTR + kc];
        qf[ks][2] = Qs[r * ASTR + kc + 4];
        qf[ks][3] = Qs[(r + 8) * ASTR + kc + 4];
    }

    float m0v = -1e30f, m1v = -1e30f, l0 = 0.f, l1 = 0.f;
    float o[8][4];
#pragma unroll
    for (int ni = 0; ni < 8; ni++)
#pragma unroll
        for (int c = 0; c < 4; c++) o[ni][c] = 0.f;

    int st = 0;
    for (int kt = 0; kt < N2V / BKV; kt++) {
        CP_WAIT(0);
        __syncthreads();
        if (kt + 1 < N2V / BKV) {
            kv_prefetch(sm, Kb, Vb, kt + 1, st ^ 1, t);
            CP_COMMIT();
        }
        uint32_t* Ks = sm + KV_BASE + st * BKV * ASTR;
        uint32_t* Vs = sm + V_BASE  + st * BKV * ASTR;

        // S = Q @ K^T (16 x 64 per warp)
        float s[8][4];
#pragma unroll
        for (int ni = 0; ni < 8; ni++)
#pragma unroll
            for (int c = 0; c < 4; c++) s[ni][c] = 0.f;

#pragma unroll
        for (int ks = 0; ks < 8; ks++) {
            const int kc = tid4 + 8 * ks;
#pragma unroll
            for (int ni = 0; ni < 8; ni++) {
                uint32_t bf[2];
                const int n = 8 * ni + g;
                bf[0] = Ks[n * ASTR + kc];
                bf[1] = Ks[n * ASTR + kc + 4];
                mma_tf32(s[ni], qf[ks], bf);
            }
        }

        // online softmax
        float mx0 = -1e30f, mx1 = -1e30f;
#pragma unroll
        for (int ni = 0; ni < 8; ni++) {
#pragma unroll
            for (int c = 0; c < 4; c++) s[ni][c] *= 0.125f;   // 1/sqrt(64)
            mx0 = fmaxf(mx0, fmaxf(s[ni][0], s[ni][1]));
            mx1 = fmaxf(mx1, fmaxf(s[ni][2], s[ni][3]));
        }
        mx0 = fmaxf(mx0, __shfl_xor_sync(0xffffffffu, mx0, 1));
        mx0 = fmaxf(mx0, __shfl_xor_sync(0xffffffffu, mx0, 2));
        mx1 = fmaxf(mx1, __shfl_xor_sync(0xffffffffu, mx1, 1));
        mx1 = fmaxf(mx1, __shfl_xor_sync(0xffffffffu, mx1, 2));
        const float mn0 = fmaxf(m0v, mx0);
        const float mn1 = fmaxf(m1v, mx1);
        float sum0 = 0.f, sum1 = 0.f;
#pragma unroll
        for (int ni = 0; ni < 8; ni++) {
            s[ni][0] = __expf(s[ni][0] - mn0);
            s[ni][1] = __expf(s[ni][1] - mn0);
            s[ni][2] = __expf(s[ni][2] - mn1);
            s[ni][3] = __expf(s[ni][3] - mn1);
            sum0 += s[ni][0] + s[ni][1];
            sum1 += s[ni][2] + s[ni][3];
        }
        sum0 += __shfl_xor_sync(0xffffffffu, sum0, 1);
        sum0 += __shfl_xor_sync(0xffffffffu, sum0, 2);
        sum1 += __shfl_xor_sync(0xffffffffu, sum1, 1);
        sum1 += __shfl_xor_sync(0xffffffffu, sum1, 2);
        const float al0 = __expf(m0v - mn0);
        const float al1 = __expf(m1v - mn1);
        m0v = mn0; m1v = mn1;
        l0 = l0 * al0 + sum0;
        l1 = l1 * al1 + sum1;
#pragma unroll
        for (int ni = 0; ni < 8; ni++) {
            o[ni][0] *= al0; o[ni][1] *= al0;
            o[ni][2] *= al1; o[ni][3] *= al1;
            const int col = 2 * tid4 + 8 * ni;
            Ps[r * ASTR + col]           = f2tf(s[ni][0]);
            Ps[r * ASTR + col + 1]       = f2tf(s[ni][1]);
            Ps[(r + 8) * ASTR + col]     = f2tf(s[ni][2]);
            Ps[(r + 8) * ASTR + col + 1] = f2tf(s[ni][3]);
        }
        __syncwarp();

        // O += P @ V
#pragma unroll
        for (int ks = 0; ks < 8; ks++) {
            const int kc = tid4 + 8 * ks;
            uint32_t a[4];
            a[0] = Ps[r * ASTR + kc];
            a[1] = Ps[(r + 8) * ASTR + kc];
            a[2] = Ps[r * ASTR + kc + 4];
            a[3] = Ps[(r + 8) * ASTR + kc + 4];
#pragma unroll
            for (int ni = 0; ni < 8; ni++) {
                uint32_t bf[2];
                const int n = 8 * ni + g;
                bf[0] = Vs[kc * ASTR + n];
                bf[1] = Vs[(kc + 4) * ASTR + n];
                mma_tf32(o[ni], a, bf);
            }
        }
        __syncwarp();
        st ^= 1;
    }

    // write context (full fp32)
    const float inv0 = 1.0f / l0;
    const float inv1 = 1.0f / l1;
    const int orow = qb * BQ + w * 16 + g;
#pragma unroll
    for (int ni = 0; ni < 8; ni++) {
        const int col = h * HD + 2 * tid4 + 8 * ni;
        float2 v0 = make_float2(o[ni][0] * inv0, o[ni][1] * inv0);
        float2 v1 = make_float2(o[ni][2] * inv1, o[ni][3] * inv1);
        *(float2*)(ctx + ((size_t)b * N1V + orow) * DIMV + col)     = v0;
        *(float2*)(ctx + ((size_t)b * N1V + orow + 8) * DIMV + col) = v1;
    }
}

// ---------------------------------------------------------------------------
// wbo[a] = sum_k W[a][k] * bo[k]
// ---------------------------------------------------------------------------
__global__ __launch_bounds__(256) void gemv_wbo(
    const float* __restrict__ W, const float* __restrict__ bo,
    float* __restrict__ wbo)
{
    const int a = blockIdx.x * 8 + (threadIdx.x >> 5);
    const int lane = threadIdx.x & 31;
    float s = 0.f;
#pragma unroll
    for (int i = 0; i < 4; i++) {
        const int j = lane + 32 * i;
        float4 wv = ((const float4*)(W + (size_t)a * DIMV))[j];
        float4 bv = ((const float4*)bo)[j];
        s += wv.x * bv.x + wv.y * bv.y + wv.z * bv.z + wv.w * bv.w;
    }
#pragma unroll
    for (int off = 16; off; off >>= 1)
        s += __shfl_xor_sync(0xffffffffu, s, off);
    if (lane == 0) wbo[a] = s;
}

// ---------------------------------------------------------------------------
// out[row] = softplus( (dot(ctx[row],u[row]) + dot(g1[row],wbo)) * scale )
// ---------------------------------------------------------------------------
__global__ __launch_bounds__(128) void score_kernel(
    const float* __restrict__ ctx, const float* __restrict__ u,
    const float* __restrict__ g1, const float* __restrict__ wbo,
    const float* __restrict__ scale, float* __restrict__ out)
{
    const int row = blockIdx.x;
    const int t = threadIdx.x;
    const float4 a = ((const float4*)(ctx + (size_t)row * DIMV))[t];
    const float4 b = ((const float4*)(u   + (size_t)row * DIMV))[t];
    const float4 c = ((const float4*)(g1  + (size_t)row * DIMV))[t];
    const float4 d = ((const float4*)wbo)[t];
    float s = a.x * b.x + a.y * b.y + a.z * b.z + a.w * b.w
            + c.x * d.x + c.y * d.y + c.z * d.z + c.w * d.w;
#pragma unroll
    for (int off = 16; off; off >>= 1)
        s += __shfl_xor_sync(0xffffffffu, s, off);
    __shared__ float red[4];
    if ((t & 31) == 0) red[t >> 5] = s;
    __syncthreads();
    if (t == 0) {
        const float tot = red[0] + red[1] + red[2] + red[3];
        const float z = tot * scale[0];
        out[row] = fmaxf(z, 0.f) + log1pf(__expf(-fabsf(z)));
    }
}

// ---------------------------------------------------------------------------
extern "C" void kernel_launch(void* const* d_in, const int* in_sizes, int n_in,
                              void* d_out, int out_size)
{
    const float* g1    = (const float*)d_in[0];
    const float* g2    = (const float*)d_in[1];
    const float* Wq    = (const float*)d_in[2];
    const float* bq    = (const float*)d_in[3];
    const float* Wk    = (const float*)d_in[4];
    const float* bk    = (const float*)d_in[5];
    const float* Wv    = (const float*)d_in[6];
    const float* bv    = (const float*)d_in[7];
    const float* Wo    = (const float*)d_in[8];
    const float* bo    = (const float*)d_in[9];
    const float* Wb    = (const float*)d_in[10];
    const float* scale = (const float*)d_in[11];
    float* out = (float*)d_out;

    float *Qp, *Kp, *Vp, *CTXp, *Up;
    float *g1r, *g2r, *Wqr, *Wkr, *Wvr, *Wor, *Wr, *Mp, *wbop;
    cudaGetSymbolAddress((void**)&Qp,   g_Q);
    cudaGetSymbolAddress((void**)&Kp,   g_K);
    cudaGetSymbolAddress((void**)&Vp,   g_V);
    cudaGetSymbolAddress((void**)&CTXp, g_CTX);
    cudaGetSymbolAddress((void**)&Up,   g_U);
    cudaGetSymbolAddress((void**)&g1r,  g_g1r);
    cudaGetSymbolAddress((void**)&g2r,  g_g2r);
    cudaGetSymbolAddress((void**)&Wqr,  g_Wqr);
    cudaGetSymbolAddress((void**)&Wkr,  g_Wkr);
    cudaGetSymbolAddress((void**)&Wvr,  g_Wvr);
    cudaGetSymbolAddress((void**)&Wor,  g_Wor);
    cudaGetSymbolAddress((void**)&Wr,   g_Wr);
    cudaGetSymbolAddress((void**)&Mp,   g_M);
    cudaGetSymbolAddress((void**)&wbop, g_wbo);

    cudaFuncSetAttribute((const void*)gemm_tc<true,  true,  true >, cudaFuncAttributeMaxDynamicSharedMemorySize, GEMM_SMEM);
    cudaFuncSetAttribute((const void*)gemm_tc<false, false, false>, cudaFuncAttributeMaxDynamicSharedMemorySize, GEMM_SMEM);
    cudaFuncSetAttribute((const void*)gemm_tc<false, false, true >, cudaFuncAttributeMaxDynamicSharedMemorySize, GEMM_SMEM);
    cudaFuncSetAttribute((const void*)attn_tc, cudaFuncAttributeMaxDynamicSharedMemorySize, ATTN_SMEM);

    const int M = BATCH * N1V;                 // 8192
    const int NBIG4 = (M * DIMV) / 4;
    const int NW4   = (DIMV * DIMV) / 4;

    // tf32 pre-round (cp.async GEMMs need rounded operands)
    round_tf32_k<<<(NBIG4 + 255) / 256, 256>>>(g1, g1r, NBIG4);
    round_tf32_k<<<(NBIG4 + 255) / 256, 256>>>(g2, g2r, NBIG4);
    round_tf32_k<<<(NW4 + 255) / 256, 256>>>(Wq, Wqr, NW4);
    round_tf32_k<<<(NW4 + 255) / 256, 256>>>(Wk, Wkr, NW4);
    round_tf32_k<<<(NW4 + 255) / 256, 256>>>(Wv, Wvr, NW4);
    round_tf32_k<<<(NW4 + 255) / 256, 256>>>(Wb, Wr,  NW4);
    round_tf32_k<<<(NW4 + 255) / 256, 256>>>(Wo, Wor, NW4);

    gemv_wbo<<<DIMV / 8, 256>>>(Wb, bo, wbop);

    // M = W @ Wo (512x512x512, NN, rounded output feeds u-gemm)
    gemm_tc<false, false, true ><<<dim3(4, 4), 256, GEMM_SMEM>>>(Wr, Wor, nullptr, Mp, DIMV, DIMV, DIMV);

    dim3 gg(DIMV / 128, M / 128);              // (4, 64)
    // Q/K/V written tf32-pre-rounded so attention can stream them raw
    gemm_tc<true,  true,  true ><<<gg, 256, GEMM_SMEM>>>(g1r, Wqr, bq,      Qp, M, DIMV, DIMV);
    gemm_tc<true,  true,  true ><<<gg, 256, GEMM_SMEM>>>(g2r, Wkr, bk,      Kp, M, DIMV, DIMV);
    gemm_tc<true,  true,  true ><<<gg, 256, GEMM_SMEM>>>(g2r, Wvr, bv,      Vp, M, DIMV, DIMV);
    gemm_tc<false, false, false><<<gg, 256, GEMM_SMEM>>>(g1r, Mp,  nullptr, Up, M, DIMV, DIMV);

    attn_tc<<<dim3(N1V / BQ, BATCH * NHEAD), 256, ATTN_SMEM>>>(Qp, Kp, Vp, CTXp);

    score_kernel<<<M, 128>>>(CTXp, Up, g1, wbop, scale, out);
}

// round 10
// speedup vs baseline: 1.1325x; 1.1325x over previous
#include <cuda_runtime.h>
#include <math.h>
#include <stdint.h>

#define BATCH 4
#define N1V 2048
#define N2V 2048
#define DIMV 512
#define NHEAD 8
#define HD 64

// Scratch (device globals: no allocation allowed in kernel_launch)
__device__ __align__(256) float g_Q   [BATCH * N1V * DIMV];
__device__ __align__(256) float g_K   [BATCH * N2V * DIMV];
__device__ __align__(256) float g_V   [BATCH * N2V * DIMV];
__device__ __align__(256) float g_CTX [BATCH * N1V * DIMV];
__device__ __align__(256) float g_U   [BATCH * N1V * DIMV];
__device__ __align__(256) float g_g1r [BATCH * N1V * DIMV];
__device__ __align__(256) float g_g2r [BATCH * N2V * DIMV];
__device__ __align__(256) float g_Wqr [DIMV * DIMV];
__device__ __align__(256) float g_Wkr [DIMV * DIMV];
__device__ __align__(256) float g_Wvr [DIMV * DIMV];
__device__ __align__(256) float g_Wor [DIMV * DIMV];
__device__ __align__(256) float g_Wr  [DIMV * DIMV];
__device__ __align__(256) float g_M   [DIMV * DIMV];     // W @ Wo (tf32-rounded)
__device__ __align__(256) float g_Mt  [DIMV * DIMV];     // (W @ Wo)^T
__device__ __align__(256) float g_wbo [DIMV];            // W @ bo

// ---------------------------------------------------------------------------
__device__ __forceinline__ uint32_t f2tf(float x) {
    uint32_t u;
    asm("cvt.rna.tf32.f32 %0, %1;" : "=r"(u) : "f"(x));
    return u;
}

__device__ __forceinline__ void mma_tf32(float* c, const uint32_t* a, const uint32_t* b) {
    asm volatile(
        "mma.sync.aligned.m16n8k8.row.col.f32.tf32.tf32.f32 "
        "{%0,%1,%2,%3}, {%4,%5,%6,%7}, {%8,%9}, {%0,%1,%2,%3};\n"
        : "+f"(c[0]), "+f"(c[1]), "+f"(c[2]), "+f"(c[3])
        : "r"(a[0]), "r"(a[1]), "r"(a[2]), "r"(a[3]), "r"(b[0]), "r"(b[1]));
}

__device__ __forceinline__ void cp16(uint32_t dst_smem, const void* src) {
    asm volatile("cp.async.cg.shared.global [%0], [%1], 16;\n" :: "r"(dst_smem), "l"(src));
}
#define CP_COMMIT() asm volatile("cp.async.commit_group;\n" ::: "memory")
#define CP_WAIT(n)  asm volatile("cp.async.wait_group %0;\n" :: "n"(n) : "memory")

__device__ __forceinline__ uint32_t smaddr(const void* p) {
    return (uint32_t)__cvta_generic_to_shared(p);
}

// ---------------------------------------------------------------------------
// Elementwise tf32 pre-round (single tensor)
// ---------------------------------------------------------------------------
__global__ __launch_bounds__(256) void round_tf32_k(
    const float* __restrict__ in, float* __restrict__ out, int n4)
{
    const int i = blockIdx.x * 256 + threadIdx.x;
    if (i < n4) {
        float4 v = ((const float4*)in)[i];
        float4 r;
        r.x = __uint_as_float(f2tf(v.x));
        r.y = __uint_as_float(f2tf(v.y));
        r.z = __uint_as_float(f2tf(v.z));
        r.w = __uint_as_float(f2tf(v.w));
        ((float4*)out)[i] = r;
    }
}

// Fused tf32 pre-round for the five 512x512 weight matrices (blockIdx.y selects)
__global__ __launch_bounds__(256) void round5_k(
    const float* __restrict__ w0, const float* __restrict__ w1,
    const float* __restrict__ w2, const float* __restrict__ w3,
    const float* __restrict__ w4,
    float* __restrict__ o0, float* __restrict__ o1,
    float* __restrict__ o2, float* __restrict__ o3,
    float* __restrict__ o4)
{
    const float* in;
    float* out;
    switch (blockIdx.y) {
        case 0: in = w0; out = o0; break;
        case 1: in = w1; out = o1; break;
        case 2: in = w2; out = o2; break;
        case 3: in = w3; out = o3; break;
        default: in = w4; out = o4; break;
    }
    const int i = blockIdx.x * 256 + threadIdx.x;   // n4 = 65536, grid.x = 256
    float4 v = ((const float4*)in)[i];
    float4 r;
    r.x = __uint_as_float(f2tf(v.x));
    r.y = __uint_as_float(f2tf(v.y));
    r.z = __uint_as_float(f2tf(v.z));
    r.w = __uint_as_float(f2tf(v.w));
    ((float4*)out)[i] = r;
}

// 512x512 transpose (bit-exact), 32x32 tiles
__global__ __launch_bounds__(256) void transpose512(
    const float* __restrict__ in, float* __restrict__ out)
{
    __shared__ float tile[32][33];
    const int tx = threadIdx.x, ty = threadIdx.y;   // 32 x 8
    const int x = blockIdx.x * 32 + tx;
    const int y0 = blockIdx.y * 32 + ty;
#pragma unroll
    for (int j = 0; j < 4; j++)
        tile[ty + 8 * j][tx] = in[(size_t)(y0 + 8 * j) * DIMV + x];
    __syncthreads();
    const int x2 = blockIdx.y * 32 + tx;
    const int y2 = blockIdx.x * 32 + ty;
#pragma unroll
    for (int j = 0; j < 4; j++)
        out[(size_t)(y2 + 8 * j) * DIMV + x2] = tile[tx][ty + 8 * j];
}

// ---------------------------------------------------------------------------
// tf32 TC GEMM, 2-stage cp.async pipeline. Inputs must be tf32-pre-rounded.
// ---------------------------------------------------------------------------
#define AS_STRIDE 36
#define BS_STRIDE_NT 132
#define STG_U32 4608
#define GEMM_SMEM (4 * STG_U32 * 4)        // 73728 B

template<bool TRANSB>
__device__ __forceinline__ void g_prefetch(
    uint32_t* As, uint32_t* Bs, const float* A, const float* Wt,
    int m0, int n0, int k0, int K, int N, int t)
{
#pragma unroll
    for (int j = 0; j < 4; j++) {
        const int idx = t + 256 * j;
        const int row = idx >> 3, c4 = (idx & 7) << 2;
        cp16(smaddr(&As[row * AS_STRIDE + c4]),
             A + (size_t)(m0 + row) * K + k0 + c4);
    }
    if (TRANSB) {
#pragma unroll
        for (int j = 0; j < 4; j++) {
            const int idx = t + 256 * j;
            const int row = idx >> 3, c4 = (idx & 7) << 2;
            cp16(smaddr(&Bs[row * AS_STRIDE + c4]),
                 Wt + (size_t)(n0 + row) * K + k0 + c4);
        }
    } else {
#pragma unroll
        for (int j = 0; j < 4; j++) {
            const int idx = t + 256 * j;
            const int row = idx >> 5, n4 = (idx & 31) << 2;
            cp16(smaddr(&Bs[row * BS_STRIDE_NT + n4]),
                 Wt + (size_t)(k0 + row) * N + n0 + n4);
        }
    }
}

// Core compute shared by both GEMM kernels (TRANSB data path hardcoded where noted)
template<bool TRANSB>
__device__ __forceinline__ void gemm_body(
    uint32_t* sm, const float* A, const float* Wt,
    int m0, int n0, int K, int N, int t, float acc[4][4][4])
{
    const int lane = t & 31;
    const int w    = t >> 5;
    const int g    = lane >> 2;
    const int tid4 = lane & 3;
    const int warpM = (w >> 2) * 64;
    const int warpN = (w & 3) * 32;

    const int nIter = K / 32;

    g_prefetch<TRANSB>(sm, sm + 2 * STG_U32, A, Wt, m0, n0, 0, K, N, t);
    CP_COMMIT();

    int st = 0;
    for (int it = 0; it < nIter; it++) {
        if (it + 1 < nIter) {
            g_prefetch<TRANSB>(sm + (st ^ 1) * STG_U32, sm + (2 + (st ^ 1)) * STG_U32,
                               A, Wt, m0, n0, (it + 1) * 32, K, N, t);
            CP_COMMIT();
            CP_WAIT(1);
        } else {
            CP_WAIT(0);
        }
        __syncthreads();

        uint32_t* As = sm + st * STG_U32;
        uint32_t* Bs = sm + (2 + st) * STG_U32;

#pragma unroll
        for (int ks = 0; ks < 4; ks++) {
            uint32_t a[4][4], b[4][2];
            const int kc = tid4 + 8 * ks;
#pragma unroll
            for (int mi = 0; mi < 4; mi++) {
                const int r = warpM + 16 * mi + g;
                a[mi][0] = As[r * AS_STRIDE + kc];
                a[mi][1] = As[(r + 8) * AS_STRIDE + kc];
                a[mi][2] = As[r * AS_STRIDE + kc + 4];
                a[mi][3] = As[(r + 8) * AS_STRIDE + kc + 4];
            }
#pragma unroll
            for (int ni = 0; ni < 4; ni++) {
                const int n = warpN + 8 * ni + g;
                if (TRANSB) {
                    b[ni][0] = Bs[n * AS_STRIDE + kc];
                    b[ni][1] = Bs[n * AS_STRIDE + kc + 4];
                } else {
                    b[ni][0] = Bs[kc * BS_STRIDE_NT + n];
                    b[ni][1] = Bs[(kc + 4) * BS_STRIDE_NT + n];
                }
            }
#pragma unroll
            for (int mi = 0; mi < 4; mi++)
#pragma unroll
                for (int ni = 0; ni < 4; ni++)
                    mma_tf32(acc[mi][ni], a[mi], b[ni]);
        }
        __syncthreads();
        st ^= 1;
    }
}

template<bool TRANSB, bool HASBIAS, bool ROUND>
__global__ __launch_bounds__(256, 2) void gemm_tc(
    const float* __restrict__ A, const float* __restrict__ Wt,
    const float* __restrict__ bias, float* __restrict__ C,
    int M, int N, int K)
{
    extern __shared__ uint32_t sm[];
    const int t  = threadIdx.x;
    const int m0 = blockIdx.y * 128, n0 = blockIdx.x * 128;

    float acc[4][4][4];
#pragma unroll
    for (int mi = 0; mi < 4; mi++)
#pragma unroll
        for (int ni = 0; ni < 4; ni++)
#pragma unroll
            for (int c = 0; c < 4; c++) acc[mi][ni][c] = 0.f;

    gemm_body<TRANSB>(sm, A, Wt, m0, n0, K, N, t, acc);

    const int lane = t & 31, w = t >> 5;
    const int g = lane >> 2, tid4 = lane & 3;
    const int warpM = (w >> 2) * 64, warpN = (w & 3) * 32;
#pragma unroll
    for (int mi = 0; mi < 4; mi++) {
#pragma unroll
        for (int ni = 0; ni < 4; ni++) {
            const int row = m0 + warpM + 16 * mi + g;
            const int col = n0 + warpN + 8 * ni + 2 * tid4;
            float bx = 0.f, by = 0.f;
            if (HASBIAS) { bx = bias[col]; by = bias[col + 1]; }
            float v00 = acc[mi][ni][0] + bx, v01 = acc[mi][ni][1] + by;
            float v10 = acc[mi][ni][2] + bx, v11 = acc[mi][ni][3] + by;
            if (ROUND) {
                v00 = __uint_as_float(f2tf(v00)); v01 = __uint_as_float(f2tf(v01));
                v10 = __uint_as_float(f2tf(v10)); v11 = __uint_as_float(f2tf(v11));
            }
            *(float2*)(C + (size_t)row * N + col)       = make_float2(v00, v01);
            *(float2*)(C + (size_t)(row + 8) * N + col) = make_float2(v10, v11);
        }
    }
}

// Fused dual-output GEMM (both TRANSB): grid.x = 8.
// blockIdx.x < 4 -> (W0, b0, C0); else (W1, b1, C1). bias == nullptr -> no bias.
__global__ __launch_bounds__(256, 2) void gemm_tc2(
    const float* __restrict__ A,
    const float* __restrict__ W0, const float* __restrict__ b0, float* __restrict__ C0,
    const float* __restrict__ W1, const float* __restrict__ b1, float* __restrict__ C1,
    int M, int N, int K)
{
    extern __shared__ uint32_t sm[];
    const int t = threadIdx.x;
    const bool second = blockIdx.x >= 4;
    const float* Wt   = second ? W1 : W0;
    const float* bias = second ? b1 : b0;
    float* C          = second ? C1 : C0;
    const int m0 = blockIdx.y * 128;
    const int n0 = (blockIdx.x & 3) * 128;

    float acc[4][4][4];
#pragma unroll
    for (int mi = 0; mi < 4; mi++)
#pragma unroll
        for (int ni = 0; ni < 4; ni++)
#pragma unroll
            for (int c = 0; c < 4; c++) acc[mi][ni][c] = 0.f;

    gemm_body<true>(sm, A, Wt, m0, n0, K, N, t, acc);

    const int lane = t & 31, w = t >> 5;
    const int g = lane >> 2, tid4 = lane & 3;
    const int warpM = (w >> 2) * 64, warpN = (w & 3) * 32;
    const bool hb = (bias != nullptr);
#pragma unroll
    for (int mi = 0; mi < 4; mi++) {
#pragma unroll
        for (int ni = 0; ni < 4; ni++) {
            const int row = m0 + warpM + 16 * mi + g;
            const int col = n0 + warpN + 8 * ni + 2 * tid4;
            float bx = 0.f, by = 0.f;
            if (hb) { bx = bias[col]; by = bias[col + 1]; }
            *(float2*)(C + (size_t)row * N + col) =
                make_float2(acc[mi][ni][0] + bx, acc[mi][ni][1] + by);
            *(float2*)(C + (size_t)(row + 8) * N + col) =
                make_float2(acc[mi][ni][2] + bx, acc[mi][ni][3] + by);
        }
    }
}

// ---------------------------------------------------------------------------
// Flash attention, tf32 TC (round-6 proven version; ctx written full fp32).
// Block = 128 q-rows x (b,h). 4 warps x 32 q-rows. BKV=64.
// ---------------------------------------------------------------------------
#define BQ 128
#define BKV 64
#define AT_STRIDE 68
#define ATTN_SMEM ((BQ + BKV + BKV + BQ) * AT_STRIDE * 4)

__global__ __launch_bounds__(128) void attn_tc(
    const float* __restrict__ Q, const float* __restrict__ K,
    const float* __restrict__ V, float* __restrict__ ctx)
{
    extern __shared__ uint32_t smA[];
    uint32_t* Qs = smA;
    uint32_t* Ks = Qs + BQ * AT_STRIDE;
    uint32_t* Vs = Ks + BKV * AT_STRIDE;
    uint32_t* Ps = Vs + BKV * AT_STRIDE;

    const int qb = blockIdx.x;
    const int bh = blockIdx.y;
    const int b  = bh >> 3, h = bh & 7;
    const int t  = threadIdx.x;
    const int w  = t >> 5, lane = t & 31;
    const int g  = lane >> 2, tid4 = lane & 3;

    const float* Qb = Q + ((size_t)b * N1V + qb * BQ) * DIMV + h * HD;
    const float* Kb = K + (size_t)b * N2V * DIMV + h * HD;
    const float* Vb = V + (size_t)b * N2V * DIMV + h * HD;

#pragma unroll
    for (int j = 0; j < 16; j++) {
        const int idx = t + 128 * j;
        const int row = idx >> 4, c4 = (idx & 15) << 2;
        float4 v = *(const float4*)(Qb + (size_t)row * DIMV + c4);
        uint32_t* p = &Qs[row * AT_STRIDE + c4];
        p[0] = f2tf(v.x); p[1] = f2tf(v.y); p[2] = f2tf(v.z); p[3] = f2tf(v.w);
    }

    float m_[2][2], l_[2][2], o[2][8][4];
#pragma unroll
    for (int mi = 0; mi < 2; mi++) {
        m_[mi][0] = -1e30f; m_[mi][1] = -1e30f;
        l_[mi][0] = 0.f;    l_[mi][1] = 0.f;
#pragma unroll
        for (int ni = 0; ni < 8; ni++)
#pragma unroll
            for (int c = 0; c < 4; c++) o[mi][ni][c] = 0.f;
    }

    for (int kt = 0; kt < N2V / BKV; kt++) {
        __syncthreads();
#pragma unroll
        for (int j = 0; j < 8; j++) {
            const int idx = t + 128 * j;
            const int row = idx >> 4, c4 = (idx & 15) << 2;
            float4 kv = *(const float4*)(Kb + (size_t)(kt * BKV + row) * DIMV + c4);
            uint32_t* pk = &Ks[row * AT_STRIDE + c4];
            pk[0] = f2tf(kv.x); pk[1] = f2tf(kv.y); pk[2] = f2tf(kv.z); pk[3] = f2tf(kv.w);
            float4 vv = *(const float4*)(Vb + (size_t)(kt * BKV + row) * DIMV + c4);
            uint32_t* pv = &Vs[row * AT_STRIDE + c4];
            pv[0] = f2tf(vv.x); pv[1] = f2tf(vv.y); pv[2] = f2tf(vv.z); pv[3] = f2tf(vv.w);
        }
        __syncthreads();

        float s[2][8][4];
#pragma unroll
        for (int mi = 0; mi < 2; mi++)
#pragma unroll
            for (int ni = 0; ni < 8; ni++)
#pragma unroll
                for (int c = 0; c < 4; c++) s[mi][ni][c] = 0.f;

#pragma unroll
        for (int ks = 0; ks < 8; ks++) {
            const int kc = tid4 + 8 * ks;
            uint32_t a[2][4], bf[8][2];
#pragma unroll
            for (int mi = 0; mi < 2; mi++) {
                const int r = w * 32 + 16 * mi + g;
                a[mi][0] = Qs[r * AT_STRIDE + kc];
                a[mi][1] = Qs[(r + 8) * AT_STRIDE + kc];
                a[mi][2] = Qs[r * AT_STRIDE + kc + 4];
                a[mi][3] = Qs[(r + 8) * AT_STRIDE + kc + 4];
            }
#pragma unroll
            for (int ni = 0; ni < 8; ni++) {
                const int n = 8 * ni + g;
                bf[ni][0] = Ks[n * AT_STRIDE + kc];
                bf[ni][1] = Ks[n * AT_STRIDE + kc + 4];
            }
#pragma unroll
            for (int mi = 0; mi < 2; mi++)
#pragma unroll
                for (int ni = 0; ni < 8; ni++)
                    mma_tf32(s[mi][ni], a[mi], bf[ni]);
        }

#pragma unroll
        for (int mi = 0; mi < 2; mi++) {
            float mx0 = -1e30f, mx1 = -1e30f;
#pragma unroll
            for (int ni = 0; ni < 8; ni++) {
#pragma unroll
                for (int c = 0; c < 4; c++) s[mi][ni][c] *= 0.125f;
                mx0 = fmaxf(mx0, fmaxf(s[mi][ni][0], s[mi][ni][1]));
                mx1 = fmaxf(mx1, fmaxf(s[mi][ni][2], s[mi][ni][3]));
            }
            mx0 = fmaxf(mx0, __shfl_xor_sync(0xffffffffu, mx0, 1));
            mx0 = fmaxf(mx0, __shfl_xor_sync(0xffffffffu, mx0, 2));
            mx1 = fmaxf(mx1, __shfl_xor_sync(0xffffffffu, mx1, 1));
            mx1 = fmaxf(mx1, __shfl_xor_sync(0xffffffffu, mx1, 2));
            const float mn0 = fmaxf(m_[mi][0], mx0);
            const float mn1 = fmaxf(m_[mi][1], mx1);
            float sum0 = 0.f, sum1 = 0.f;
#pragma unroll
            for (int ni = 0; ni < 8; ni++) {
                s[mi][ni][0] = __expf(s[mi][ni][0] - mn0);
                s[mi][ni][1] = __expf(s[mi][ni][1] - mn0);
                s[mi][ni][2] = __expf(s[mi][ni][2] - mn1);
                s[mi][ni][3] = __expf(s[mi][ni][3] - mn1);
                sum0 += s[mi][ni][0] + s[mi][ni][1];
                sum1 += s[mi][ni][2] + s[mi][ni][3];
            }
            sum0 += __shfl_xor_sync(0xffffffffu, sum0, 1);
            sum0 += __shfl_xor_sync(0xffffffffu, sum0, 2);
            sum1 += __shfl_xor_sync(0xffffffffu, sum1, 1);
            sum1 += __shfl_xor_sync(0xffffffffu, sum1, 2);
            const float al0 = __expf(m_[mi][0] - mn0);
            const float al1 = __expf(m_[mi][1] - mn1);
            m_[mi][0] = mn0; m_[mi][1] = mn1;
            l_[mi][0] = l_[mi][0] * al0 + sum0;
            l_[mi][1] = l_[mi][1] * al1 + sum1;
#pragma unroll
            for (int ni = 0; ni < 8; ni++) {
                o[mi][ni][0] *= al0; o[mi][ni][1] *= al0;
                o[mi][ni][2] *= al1; o[mi][ni][3] *= al1;
            }
            const int r = w * 32 + 16 * mi + g;
#pragma unroll
            for (int ni = 0; ni < 8; ni++) {
                const int col = 2 * tid4 + 8 * ni;
                Ps[r * AT_STRIDE + col]           = f2tf(s[mi][ni][0]);
                Ps[r * AT_STRIDE + col + 1]       = f2tf(s[mi][ni][1]);
                Ps[(r + 8) * AT_STRIDE + col]     = f2tf(s[mi][ni][2]);
                Ps[(r + 8) * AT_STRIDE + col + 1] = f2tf(s[mi][ni][3]);
            }
        }
        __syncwarp();

#pragma unroll
        for (int ks = 0; ks < 8; ks++) {
            const int kc = tid4 + 8 * ks;
            uint32_t a[2][4], bf[8][2];
#pragma unroll
            for (int mi = 0; mi < 2; mi++) {
                const int r = w * 32 + 16 * mi + g;
                a[mi][0] = Ps[r * AT_STRIDE + kc];
                a[mi][1] = Ps[(r + 8) * AT_STRIDE + kc];
                a[mi][2] = Ps[r * AT_STRIDE + kc + 4];
                a[mi][3] = Ps[(r + 8) * AT_STRIDE + kc + 4];
            }
#pragma unroll
            for (int ni = 0; ni < 8; ni++) {
                const int n = 8 * ni + g;
                bf[ni][0] = Vs[kc * AT_STRIDE + n];
                bf[ni][1] = Vs[(kc + 4) * AT_STRIDE + n];
            }
#pragma unroll
            for (int mi = 0; mi < 2; mi++)
#pragma unroll
                for (int ni = 0; ni < 8; ni++)
                    mma_tf32(o[mi][ni], a[mi], bf[ni]);
        }
        __syncwarp();
    }

#pragma unroll
    for (int mi = 0; mi < 2; mi++) {
        const float inv0 = 1.0f / l_[mi][0];
        const float inv1 = 1.0f / l_[mi][1];
        const int r = qb * BQ + w * 32 + 16 * mi + g;
#pragma unroll
        for (int ni = 0; ni < 8; ni++) {
            const int col = h * HD + 2 * tid4 + 8 * ni;
            float2 v0 = make_float2(o[mi][ni][0] * inv0, o[mi][ni][1] * inv0);
            float2 v1 = make_float2(o[mi][ni][2] * inv1, o[mi][ni][3] * inv1);
            *(float2*)(ctx + ((size_t)b * N1V + r) * DIMV + col)     = v0;
            *(float2*)(ctx + ((size_t)b * N1V + r + 8) * DIMV + col) = v1;
        }
    }
}

// ---------------------------------------------------------------------------
// wbo[a] = sum_k W[a][k] * bo[k]
// ---------------------------------------------------------------------------
__global__ __launch_bounds__(256) void gemv_wbo(
    const float* __restrict__ W, const float* __restrict__ bo,
    float* __restrict__ wbo)
{
    const int a = blockIdx.x * 8 + (threadIdx.x >> 5);
    const int lane = threadIdx.x & 31;
    float s = 0.f;
#pragma unroll
    for (int i = 0; i < 4; i++) {
        const int j = lane + 32 * i;
        float4 wv = ((const float4*)(W + (size_t)a * DIMV))[j];
        float4 bv = ((const float4*)bo)[j];
        s += wv.x * bv.x + wv.y * bv.y + wv.z * bv.z + wv.w * bv.w;
    }
#pragma unroll
    for (int off = 16; off; off >>= 1)
        s += __shfl_xor_sync(0xffffffffu, s, off);
    if (lane == 0) wbo[a] = s;
}

// ---------------------------------------------------------------------------
// out[row] = softplus( (dot(ctx[row],u[row]) + dot(g1[row],wbo)) * scale )
// ---------------------------------------------------------------------------
__global__ __launch_bounds__(128) void score_kernel(
    const float* __restrict__ ctx, const float* __restrict__ u,
    const float* __restrict__ g1, const float* __restrict__ wbo,
    const float* __restrict__ scale, float* __restrict__ out)
{
    const int row = blockIdx.x;
    const int t = threadIdx.x;
    const float4 a = ((const float4*)(ctx + (size_t)row * DIMV))[t];
    const float4 b = ((const float4*)(u   + (size_t)row * DIMV))[t];
    const float4 c = ((const float4*)(g1  + (size_t)row * DIMV))[t];
    const float4 d = ((const float4*)wbo)[t];
    float s = a.x * b.x + a.y * b.y + a.z * b.z + a.w * b.w
            + c.x * d.x + c.y * d.y + c.z * d.z + c.w * d.w;
#pragma unroll
    for (int off = 16; off; off >>= 1)
        s += __shfl_xor_sync(0xffffffffu, s, off);
    __shared__ float red[4];
    if ((t & 31) == 0) red[t >> 5] = s;
    __syncthreads();
    if (t == 0) {
        const float tot = red[0] + red[1] + red[2] + red[3];
        const float z = tot * scale[0];
        out[row] = fmaxf(z, 0.f) + log1pf(__expf(-fabsf(z)));
    }
}

// ---------------------------------------------------------------------------
extern "C" void kernel_launch(void* const* d_in, const int* in_sizes, int n_in,
                              void* d_out, int out_size)
{
    const float* g1    = (const float*)d_in[0];
    const float* g2    = (const float*)d_in[1];
    const float* Wq    = (const float*)d_in[2];
    const float* bq    = (const float*)d_in[3];
    const float* Wk    = (const float*)d_in[4];
    const float* bk    = (const float*)d_in[5];
    const float* Wv    = (const float*)d_in[6];
    const float* bv    = (const float*)d_in[7];
    const float* Wo    = (const float*)d_in[8];
    const float* bo    = (const float*)d_in[9];
    const float* Wb    = (const float*)d_in[10];
    const float* scale = (const float*)d_in[11];
    float* out = (float*)d_out;

    float *Qp, *Kp, *Vp, *CTXp, *Up;
    float *g1r, *g2r, *Wqr, *Wkr, *Wvr, *Wor, *Wr, *Mp, *Mtp, *wbop;
    cudaGetSymbolAddress((void**)&Qp,   g_Q);
    cudaGetSymbolAddress((void**)&Kp,   g_K);
    cudaGetSymbolAddress((void**)&Vp,   g_V);
    cudaGetSymbolAddress((void**)&CTXp, g_CTX);
    cudaGetSymbolAddress((void**)&Up,   g_U);
    cudaGetSymbolAddress((void**)&g1r,  g_g1r);
    cudaGetSymbolAddress((void**)&g2r,  g_g2r);
    cudaGetSymbolAddress((void**)&Wqr,  g_Wqr);
    cudaGetSymbolAddress((void**)&Wkr,  g_Wkr);
    cudaGetSymbolAddress((void**)&Wvr,  g_Wvr);
    cudaGetSymbolAddress((void**)&Wor,  g_Wor);
    cudaGetSymbolAddress((void**)&Wr,   g_Wr);
    cudaGetSymbolAddress((void**)&Mp,   g_M);
    cudaGetSymbolAddress((void**)&Mtp,  g_Mt);
    cudaGetSymbolAddress((void**)&wbop, g_wbo);

    cudaFuncSetAttribute((const void*)gemm_tc<false, false, true>, cudaFuncAttributeMaxDynamicSharedMemorySize, GEMM_SMEM);
    cudaFuncSetAttribute((const void*)gemm_tc2, cudaFuncAttributeMaxDynamicSharedMemorySize, GEMM_SMEM);
    cudaFuncSetAttribute((const void*)attn_tc, cudaFuncAttributeMaxDynamicSharedMemorySize, ATTN_SMEM);

    const int M = BATCH * N1V;                 // 8192
    const int NBIG4 = (M * DIMV) / 4;

    // tf32 pre-round (cp.async GEMMs need rounded operands)
    round_tf32_k<<<(NBIG4 + 255) / 256, 256>>>(g1, g1r, NBIG4);
    round_tf32_k<<<(NBIG4 + 255) / 256, 256>>>(g2, g2r, NBIG4);
    round5_k<<<dim3(256, 5), 256>>>(Wq, Wk, Wv, Wb, Wo, Wqr, Wkr, Wvr, Wr, Wor);

    gemv_wbo<<<DIMV / 8, 256>>>(Wb, bo, wbop);

    // M = W @ Wo (512^3, NN, rounded), then Mt = M^T (bit-exact)
    gemm_tc<false, false, true><<<dim3(4, 4), 256, GEMM_SMEM>>>(Wr, Wor, nullptr, Mp, DIMV, DIMV, DIMV);
    transpose512<<<dim3(16, 16), dim3(32, 8)>>>(Mp, Mtp);

    // Fused pairs sharing the A operand: (Q,U) from g1r, (K,V) from g2r.
    dim3 gg2(8, M / 128);                      // 512 blocks each
    gemm_tc2<<<gg2, 256, GEMM_SMEM>>>(g1r, Wqr, bq, Qp, Mtp, nullptr, Up, M, DIMV, DIMV);
    gemm_tc2<<<gg2, 256, GEMM_SMEM>>>(g2r, Wkr, bk, Kp, Wvr, bv,      Vp, M, DIMV, DIMV);

    attn_tc<<<dim3(N1V / BQ, BATCH * NHEAD), 128, ATTN_SMEM>>>(Qp, Kp, Vp, CTXp);

    score_kernel<<<M, 128>>>(CTXp, Up, g1, wbop, scale, out);
}

// round 11
// speedup vs baseline: 1.1372x; 1.0041x over previous
#include <cuda_runtime.h>
#include <math.h>
#include <stdint.h>

#define BATCH 4
#define N1V 2048
#define N2V 2048
#define DIMV 512
#define NHEAD 8
#define HD 64

// Scratch (device globals: no allocation allowed in kernel_launch)
__device__ __align__(256) float g_Q   [BATCH * N1V * DIMV];
__device__ __align__(256) float g_K   [BATCH * N2V * DIMV];
__device__ __align__(256) float g_V   [BATCH * N2V * DIMV];
__device__ __align__(256) float g_CTX [BATCH * N1V * DIMV];
__device__ __align__(256) float g_U   [BATCH * N1V * DIMV];
__device__ __align__(256) float g_g1r [BATCH * N1V * DIMV];
__device__ __align__(256) float g_g2r [BATCH * N2V * DIMV];
__device__ __align__(256) float g_Wqr [DIMV * DIMV];
__device__ __align__(256) float g_Wkr [DIMV * DIMV];
__device__ __align__(256) float g_Wvr [DIMV * DIMV];
__device__ __align__(256) float g_Wor [DIMV * DIMV];
__device__ __align__(256) float g_Wr  [DIMV * DIMV];
__device__ __align__(256) float g_M   [DIMV * DIMV];     // W @ Wo (tf32-rounded)
__device__ __align__(256) float g_Mt  [DIMV * DIMV];     // (W @ Wo)^T
__device__ __align__(256) float g_wbo [DIMV];            // W @ bo

// ---------------------------------------------------------------------------
__device__ __forceinline__ uint32_t f2tf(float x) {
    uint32_t u;
    asm("cvt.rna.tf32.f32 %0, %1;" : "=r"(u) : "f"(x));
    return u;
}

__device__ __forceinline__ void mma_tf32(float* c, const uint32_t* a, const uint32_t* b) {
    asm volatile(
        "mma.sync.aligned.m16n8k8.row.col.f32.tf32.tf32.f32 "
        "{%0,%1,%2,%3}, {%4,%5,%6,%7}, {%8,%9}, {%0,%1,%2,%3};\n"
        : "+f"(c[0]), "+f"(c[1]), "+f"(c[2]), "+f"(c[3])
        : "r"(a[0]), "r"(a[1]), "r"(a[2]), "r"(a[3]), "r"(b[0]), "r"(b[1]));
}

__device__ __forceinline__ void cp16(uint32_t dst_smem, const void* src) {
    asm volatile("cp.async.cg.shared.global [%0], [%1], 16;\n" :: "r"(dst_smem), "l"(src));
}
#define CP_COMMIT() asm volatile("cp.async.commit_group;\n" ::: "memory")
#define CP_WAIT(n)  asm volatile("cp.async.wait_group %0;\n" :: "n"(n) : "memory")

__device__ __forceinline__ uint32_t smaddr(const void* p) {
    return (uint32_t)__cvta_generic_to_shared(p);
}

// ---------------------------------------------------------------------------
// Fused tf32 pre-round for g1, g2 (blockIdx.y selects)
// ---------------------------------------------------------------------------
__global__ __launch_bounds__(256) void round2_k(
    const float* __restrict__ a0, const float* __restrict__ a1,
    float* __restrict__ o0, float* __restrict__ o1)
{
    const float* in = blockIdx.y ? a1 : a0;
    float* out      = blockIdx.y ? o1 : o0;
    const int i = blockIdx.x * 256 + threadIdx.x;   // grid.x = 4096
    float4 v = ((const float4*)in)[i];
    float4 r;
    r.x = __uint_as_float(f2tf(v.x));
    r.y = __uint_as_float(f2tf(v.y));
    r.z = __uint_as_float(f2tf(v.z));
    r.w = __uint_as_float(f2tf(v.w));
    ((float4*)out)[i] = r;
}

// Fused tf32 pre-round for the five 512x512 weight matrices (blockIdx.y selects)
__global__ __launch_bounds__(256) void round5_k(
    const float* __restrict__ w0, const float* __restrict__ w1,
    const float* __restrict__ w2, const float* __restrict__ w3,
    const float* __restrict__ w4,
    float* __restrict__ o0, float* __restrict__ o1,
    float* __restrict__ o2, float* __restrict__ o3,
    float* __restrict__ o4)
{
    const float* in;
    float* out;
    switch (blockIdx.y) {
        case 0: in = w0; out = o0; break;
        case 1: in = w1; out = o1; break;
        case 2: in = w2; out = o2; break;
        case 3: in = w3; out = o3; break;
        default: in = w4; out = o4; break;
    }
    const int i = blockIdx.x * 256 + threadIdx.x;   // grid.x = 256
    float4 v = ((const float4*)in)[i];
    float4 r;
    r.x = __uint_as_float(f2tf(v.x));
    r.y = __uint_as_float(f2tf(v.y));
    r.z = __uint_as_float(f2tf(v.z));
    r.w = __uint_as_float(f2tf(v.w));
    ((float4*)out)[i] = r;
}

// 512x512 transpose (bit-exact), 32x32 tiles
__global__ __launch_bounds__(256) void transpose512(
    const float* __restrict__ in, float* __restrict__ out)
{
    __shared__ float tile[32][33];
    const int tx = threadIdx.x, ty = threadIdx.y;   // 32 x 8
    const int x = blockIdx.x * 32 + tx;
    const int y0 = blockIdx.y * 32 + ty;
#pragma unroll
    for (int j = 0; j < 4; j++)
        tile[ty + 8 * j][tx] = in[(size_t)(y0 + 8 * j) * DIMV + x];
    __syncthreads();
    const int x2 = blockIdx.y * 32 + tx;
    const int y2 = blockIdx.x * 32 + ty;
#pragma unroll
    for (int j = 0; j < 4; j++)
        out[(size_t)(y2 + 8 * j) * DIMV + x2] = tile[tx][ty + 8 * j];
}

// ---------------------------------------------------------------------------
// tf32 TC GEMM, 2-stage cp.async pipeline. Inputs must be tf32-pre-rounded.
// ---------------------------------------------------------------------------
#define AS_STRIDE 36
#define BS_STRIDE_NT 132
#define STG_U32 4608
#define GEMM_SMEM (4 * STG_U32 * 4)        // 73728 B

template<bool TRANSB>
__device__ __forceinline__ void g_prefetch(
    uint32_t* As, uint32_t* Bs, const float* A, const float* Wt,
    int m0, int n0, int k0, int K, int N, int t)
{
#pragma unroll
    for (int j = 0; j < 4; j++) {
        const int idx = t + 256 * j;
        const int row = idx >> 3, c4 = (idx & 7) << 2;
        cp16(smaddr(&As[row * AS_STRIDE + c4]),
             A + (size_t)(m0 + row) * K + k0 + c4);
    }
    if (TRANSB) {
#pragma unroll
        for (int j = 0; j < 4; j++) {
            const int idx = t + 256 * j;
            const int row = idx >> 3, c4 = (idx & 7) << 2;
            cp16(smaddr(&Bs[row * AS_STRIDE + c4]),
                 Wt + (size_t)(n0 + row) * K + k0 + c4);
        }
    } else {
#pragma unroll
        for (int j = 0; j < 4; j++) {
            const int idx = t + 256 * j;
            const int row = idx >> 5, n4 = (idx & 31) << 2;
            cp16(smaddr(&Bs[row * BS_STRIDE_NT + n4]),
                 Wt + (size_t)(k0 + row) * N + n0 + n4);
        }
    }
}

// Core compute shared by the GEMM kernels
template<bool TRANSB>
__device__ __forceinline__ void gemm_body(
    uint32_t* sm, const float* A, const float* Wt,
    int m0, int n0, int K, int N, int t, float acc[4][4][4])
{
    const int lane = t & 31;
    const int w    = t >> 5;
    const int g    = lane >> 2;
    const int tid4 = lane & 3;
    const int warpM = (w >> 2) * 64;
    const int warpN = (w & 3) * 32;

    const int nIter = K / 32;

    g_prefetch<TRANSB>(sm, sm + 2 * STG_U32, A, Wt, m0, n0, 0, K, N, t);
    CP_COMMIT();

    int st = 0;
    for (int it = 0; it < nIter; it++) {
        if (it + 1 < nIter) {
            g_prefetch<TRANSB>(sm + (st ^ 1) * STG_U32, sm + (2 + (st ^ 1)) * STG_U32,
                               A, Wt, m0, n0, (it + 1) * 32, K, N, t);
            CP_COMMIT();
            CP_WAIT(1);
        } else {
            CP_WAIT(0);
        }
        __syncthreads();

        uint32_t* As = sm + st * STG_U32;
        uint32_t* Bs = sm + (2 + st) * STG_U32;

#pragma unroll
        for (int ks = 0; ks < 4; ks++) {
            uint32_t a[4][4], b[4][2];
            const int kc = tid4 + 8 * ks;
#pragma unroll
            for (int mi = 0; mi < 4; mi++) {
                const int r = warpM + 16 * mi + g;
                a[mi][0] = As[r * AS_STRIDE + kc];
                a[mi][1] = As[(r + 8) * AS_STRIDE + kc];
                a[mi][2] = As[r * AS_STRIDE + kc + 4];
                a[mi][3] = As[(r + 8) * AS_STRIDE + kc + 4];
            }
#pragma unroll
            for (int ni = 0; ni < 4; ni++) {
                const int n = warpN + 8 * ni + g;
                if (TRANSB) {
                    b[ni][0] = Bs[n * AS_STRIDE + kc];
                    b[ni][1] = Bs[n * AS_STRIDE + kc + 4];
                } else {
                    b[ni][0] = Bs[kc * BS_STRIDE_NT + n];
                    b[ni][1] = Bs[(kc + 4) * BS_STRIDE_NT + n];
                }
            }
#pragma unroll
            for (int mi = 0; mi < 4; mi++)
#pragma unroll
                for (int ni = 0; ni < 4; ni++)
                    mma_tf32(acc[mi][ni], a[mi], b[ni]);
        }
        __syncthreads();
        st ^= 1;
    }
}

template<bool TRANSB, bool HASBIAS, bool ROUND>
__global__ __launch_bounds__(256, 2) void gemm_tc(
    const float* __restrict__ A, const float* __restrict__ Wt,
    const float* __restrict__ bias, float* __restrict__ C,
    int M, int N, int K)
{
    extern __shared__ uint32_t sm[];
    const int t  = threadIdx.x;
    const int m0 = blockIdx.y * 128, n0 = blockIdx.x * 128;

    float acc[4][4][4];
#pragma unroll
    for (int mi = 0; mi < 4; mi++)
#pragma unroll
        for (int ni = 0; ni < 4; ni++)
#pragma unroll
            for (int c = 0; c < 4; c++) acc[mi][ni][c] = 0.f;

    gemm_body<TRANSB>(sm, A, Wt, m0, n0, K, N, t, acc);

    const int lane = t & 31, w = t >> 5;
    const int g = lane >> 2, tid4 = lane & 3;
    const int warpM = (w >> 2) * 64, warpN = (w & 3) * 32;
#pragma unroll
    for (int mi = 0; mi < 4; mi++) {
#pragma unroll
        for (int ni = 0; ni < 4; ni++) {
            const int row = m0 + warpM + 16 * mi + g;
            const int col = n0 + warpN + 8 * ni + 2 * tid4;
            float bx = 0.f, by = 0.f;
            if (HASBIAS) { bx = bias[col]; by = bias[col + 1]; }
            float v00 = acc[mi][ni][0] + bx, v01 = acc[mi][ni][1] + by;
            float v10 = acc[mi][ni][2] + bx, v11 = acc[mi][ni][3] + by;
            if (ROUND) {
                v00 = __uint_as_float(f2tf(v00)); v01 = __uint_as_float(f2tf(v01));
                v10 = __uint_as_float(f2tf(v10)); v11 = __uint_as_float(f2tf(v11));
            }
            *(float2*)(C + (size_t)row * N + col)       = make_float2(v00, v01);
            *(float2*)(C + (size_t)(row + 8) * N + col) = make_float2(v10, v11);
        }
    }
}

// Fused dual-output GEMM (both TRANSB): grid.x = 8.
// blockIdx.x < 4 -> (W0, b0, C0, ROUND0 with scale0); else (W1, b1, C1, ROUND1).
// ROUNDx: output scaled by scalex then tf32-rounded (scale must be power of 2
// for bit-exact commuting with downstream mma).
template<bool ROUND0, bool ROUND1>
__global__ __launch_bounds__(256, 2) void gemm_tc2(
    const float* __restrict__ A,
    const float* __restrict__ W0, const float* __restrict__ b0, float* __restrict__ C0,
    const float* __restrict__ W1, const float* __restrict__ b1, float* __restrict__ C1,
    float scale0, float scale1,
    int M, int N, int K)
{
    extern __shared__ uint32_t sm[];
    const int t = threadIdx.x;
    const bool second = blockIdx.x >= 4;
    const float* Wt   = second ? W1 : W0;
    const float* bias = second ? b1 : b0;
    float* C          = second ? C1 : C0;
    const float scl   = second ? scale1 : scale0;
    const bool doRound = second ? ROUND1 : ROUND0;
    const int m0 = blockIdx.y * 128;
    const int n0 = (blockIdx.x & 3) * 128;

    float acc[4][4][4];
#pragma unroll
    for (int mi = 0; mi < 4; mi++)
#pragma unroll
        for (int ni = 0; ni < 4; ni++)
#pragma unroll
            for (int c = 0; c < 4; c++) acc[mi][ni][c] = 0.f;

    gemm_body<true>(sm, A, Wt, m0, n0, K, N, t, acc);

    const int lane = t & 31, w = t >> 5;
    const int g = lane >> 2, tid4 = lane & 3;
    const int warpM = (w >> 2) * 64, warpN = (w & 3) * 32;
    const bool hb = (bias != nullptr);
#pragma unroll
    for (int mi = 0; mi < 4; mi++) {
#pragma unroll
        for (int ni = 0; ni < 4; ni++) {
            const int row = m0 + warpM + 16 * mi + g;
            const int col = n0 + warpN + 8 * ni + 2 * tid4;
            float bx = 0.f, by = 0.f;
            if (hb) { bx = bias[col]; by = bias[col + 1]; }
            float v00 = acc[mi][ni][0] + bx, v01 = acc[mi][ni][1] + by;
            float v10 = acc[mi][ni][2] + bx, v11 = acc[mi][ni][3] + by;
            if (doRound) {
                v00 = __uint_as_float(f2tf(v00 * scl));
                v01 = __uint_as_float(f2tf(v01 * scl));
                v10 = __uint_as_float(f2tf(v10 * scl));
                v11 = __uint_as_float(f2tf(v11 * scl));
            }
            *(float2*)(C + (size_t)row * N + col)       = make_float2(v00, v01);
            *(float2*)(C + (size_t)(row + 8) * N + col) = make_float2(v10, v11);
        }
    }
}

// ---------------------------------------------------------------------------
// Flash attention, tf32 TC. Q/K/V pre-rounded (Q pre-scaled by 1/8).
// Block = 128 q-rows x (b,h). 4 warps x 32 q-rows. BKV=64. Raw vector loads.
// ---------------------------------------------------------------------------
#define BQ 128
#define BKV 64
#define AT_STRIDE 68
#define ATTN_SMEM ((BQ + BKV + BKV + BQ) * AT_STRIDE * 4)

__global__ __launch_bounds__(128) void attn_tc(
    const float* __restrict__ Q, const float* __restrict__ K,
    const float* __restrict__ V, float* __restrict__ ctx)
{
    extern __shared__ uint32_t smA[];
    uint32_t* Qs = smA;
    uint32_t* Ks = Qs + BQ * AT_STRIDE;
    uint32_t* Vs = Ks + BKV * AT_STRIDE;
    uint32_t* Ps = Vs + BKV * AT_STRIDE;

    const int qb = blockIdx.x;
    const int bh = blockIdx.y;
    const int b  = bh >> 3, h = bh & 7;
    const int t  = threadIdx.x;
    const int w  = t >> 5, lane = t & 31;
    const int g  = lane >> 2, tid4 = lane & 3;

    const float* Qb = Q + ((size_t)b * N1V + qb * BQ) * DIMV + h * HD;
    const float* Kb = K + (size_t)b * N2V * DIMV + h * HD;
    const float* Vb = V + (size_t)b * N2V * DIMV + h * HD;

    // Raw vectorized Q load (values already tf32-rounded & pre-scaled)
#pragma unroll
    for (int j = 0; j < 16; j++) {
        const int idx = t + 128 * j;
        const int row = idx >> 4, c4 = (idx & 15) << 2;
        *(float4*)&Qs[row * AT_STRIDE + c4] = *(const float4*)(Qb + (size_t)row * DIMV + c4);
    }

    float m_[2][2], l_[2][2], o[2][8][4];
#pragma unroll
    for (int mi = 0; mi < 2; mi++) {
        m_[mi][0] = -1e30f; m_[mi][1] = -1e30f;
        l_[mi][0] = 0.f;    l_[mi][1] = 0.f;
#pragma unroll
        for (int ni = 0; ni < 8; ni++)
#pragma unroll
            for (int c = 0; c < 4; c++) o[mi][ni][c] = 0.f;
    }

    for (int kt = 0; kt < N2V / BKV; kt++) {
        __syncthreads();
#pragma unroll
        for (int j = 0; j < 8; j++) {
            const int idx = t + 128 * j;
            const int row = idx >> 4, c4 = (idx & 15) << 2;
            *(float4*)&Ks[row * AT_STRIDE + c4] =
                *(const float4*)(Kb + (size_t)(kt * BKV + row) * DIMV + c4);
            *(float4*)&Vs[row * AT_STRIDE + c4] =
                *(const float4*)(Vb + (size_t)(kt * BKV + row) * DIMV + c4);
        }
        __syncthreads();

        float s[2][8][4];
#pragma unroll
        for (int mi = 0; mi < 2; mi++)
#pragma unroll
            for (int ni = 0; ni < 8; ni++)
#pragma unroll
                for (int c = 0; c < 4; c++) s[mi][ni][c] = 0.f;

#pragma unroll
        for (int ks = 0; ks < 8; ks++) {
            const int kc = tid4 + 8 * ks;
            uint32_t a[2][4], bf[8][2];
#pragma unroll
            for (int mi = 0; mi < 2; mi++) {
                const int r = w * 32 + 16 * mi + g;
                a[mi][0] = Qs[r * AT_STRIDE + kc];
                a[mi][1] = Qs[(r + 8) * AT_STRIDE + kc];
                a[mi][2] = Qs[r * AT_STRIDE + kc + 4];
                a[mi][3] = Qs[(r + 8) * AT_STRIDE + kc + 4];
            }
#pragma unroll
            for (int ni = 0; ni < 8; ni++) {
                const int n = 8 * ni + g;
                bf[ni][0] = Ks[n * AT_STRIDE + kc];
                bf[ni][1] = Ks[n * AT_STRIDE + kc + 4];
            }
#pragma unroll
            for (int mi = 0; mi < 2; mi++)
#pragma unroll
                for (int ni = 0; ni < 8; ni++)
                    mma_tf32(s[mi][ni], a[mi], bf[ni]);
        }

        // online softmax (S already scaled: Q was pre-multiplied by 1/8)
#pragma unroll
        for (int mi = 0; mi < 2; mi++) {
            float mx0 = -1e30f, mx1 = -1e30f;
#pragma unroll
            for (int ni = 0; ni < 8; ni++) {
                mx0 = fmaxf(mx0, fmaxf(s[mi][ni][0], s[mi][ni][1]));
                mx1 = fmaxf(mx1, fmaxf(s[mi][ni][2], s[mi][ni][3]));
            }
            mx0 = fmaxf(mx0, __shfl_xor_sync(0xffffffffu, mx0, 1));
            mx0 = fmaxf(mx0, __shfl_xor_sync(0xffffffffu, mx0, 2));
            mx1 = fmaxf(mx1, __shfl_xor_sync(0xffffffffu, mx1, 1));
            mx1 = fmaxf(mx1, __shfl_xor_sync(0xffffffffu, mx1, 2));
            const float mn0 = fmaxf(m_[mi][0], mx0);
            const float mn1 = fmaxf(m_[mi][1], mx1);
            float sum0 = 0.f, sum1 = 0.f;
#pragma unroll
            for (int ni = 0; ni < 8; ni++) {
                s[mi][ni][0] = __expf(s[mi][ni][0] - mn0);
                s[mi][ni][1] = __expf(s[mi][ni][1] - mn0);
                s[mi][ni][2] = __expf(s[mi][ni][2] - mn1);
                s[mi][ni][3] = __expf(s[mi][ni][3] - mn1);
                sum0 += s[mi][ni][0] + s[mi][ni][1];
                sum1 += s[mi][ni][2] + s[mi][ni][3];
            }
            sum0 += __shfl_xor_sync(0xffffffffu, sum0, 1);
            sum0 += __shfl_xor_sync(0xffffffffu, sum0, 2);
            sum1 += __shfl_xor_sync(0xffffffffu, sum1, 1);
            sum1 += __shfl_xor_sync(0xffffffffu, sum1, 2);
            const float al0 = __expf(m_[mi][0] - mn0);
            const float al1 = __expf(m_[mi][1] - mn1);
            m_[mi][0] = mn0; m_[mi][1] = mn1;
            l_[mi][0] = l_[mi][0] * al0 + sum0;
            l_[mi][1] = l_[mi][1] * al1 + sum1;
#pragma unroll
            for (int ni = 0; ni < 8; ni++) {
                o[mi][ni][0] *= al0; o[mi][ni][1] *= al0;
                o[mi][ni][2] *= al1; o[mi][ni][3] *= al1;
            }
            const int r = w * 32 + 16 * mi + g;
#pragma unroll
            for (int ni = 0; ni < 8; ni++) {
                const int col = 2 * tid4 + 8 * ni;
                Ps[r * AT_STRIDE + col]           = f2tf(s[mi][ni][0]);
                Ps[r * AT_STRIDE + col + 1]       = f2tf(s[mi][ni][1]);
                Ps[(r + 8) * AT_STRIDE + col]     = f2tf(s[mi][ni][2]);
                Ps[(r + 8) * AT_STRIDE + col + 1] = f2tf(s[mi][ni][3]);
            }
        }
        __syncwarp();

#pragma unroll
        for (int ks = 0; ks < 8; ks++) {
            const int kc = tid4 + 8 * ks;
            uint32_t a[2][4], bf[8][2];
#pragma unroll
            for (int mi = 0; mi < 2; mi++) {
                const int r = w * 32 + 16 * mi + g;
                a[mi][0] = Ps[r * AT_STRIDE + kc];
                a[mi][1] = Ps[(r + 8) * AT_STRIDE + kc];
                a[mi][2] = Ps[r * AT_STRIDE + kc + 4];
                a[mi][3] = Ps[(r + 8) * AT_STRIDE + kc + 4];
            }
#pragma unroll
            for (int ni = 0; ni < 8; ni++) {
                const int n = 8 * ni + g;
                bf[ni][0] = Vs[kc * AT_STRIDE + n];
                bf[ni][1] = Vs[(kc + 4) * AT_STRIDE + n];
            }
#pragma unroll
            for (int mi = 0; mi < 2; mi++)
#pragma unroll
                for (int ni = 0; ni < 8; ni++)
                    mma_tf32(o[mi][ni], a[mi], bf[ni]);
        }
        __syncwarp();
    }

#pragma unroll
    for (int mi = 0; mi < 2; mi++) {
        const float inv0 = 1.0f / l_[mi][0];
        const float inv1 = 1.0f / l_[mi][1];
        const int r = qb * BQ + w * 32 + 16 * mi + g;
#pragma unroll
        for (int ni = 0; ni < 8; ni++) {
            const int col = h * HD + 2 * tid4 + 8 * ni;
            float2 v0 = make_float2(o[mi][ni][0] * inv0, o[mi][ni][1] * inv0);
            float2 v1 = make_float2(o[mi][ni][2] * inv1, o[mi][ni][3] * inv1);
            *(float2*)(ctx + ((size_t)b * N1V + r) * DIMV + col)     = v0;
            *(float2*)(ctx + ((size_t)b * N1V + r + 8) * DIMV + col) = v1;
        }
    }
}

// ---------------------------------------------------------------------------
// wbo[a] = sum_k W[a][k] * bo[k]
// ---------------------------------------------------------------------------
__global__ __launch_bounds__(256) void gemv_wbo(
    const float* __restrict__ W, const float* __restrict__ bo,
    float* __restrict__ wbo)
{
    const int a = blockIdx.x * 8 + (threadIdx.x >> 5);
    const int lane = threadIdx.x & 31;
    float s = 0.f;
#pragma unroll
    for (int i = 0; i < 4; i++) {
        const int j = lane + 32 * i;
        float4 wv = ((const float4*)(W + (size_t)a * DIMV))[j];
        float4 bv = ((const float4*)bo)[j];
        s += wv.x * bv.x + wv.y * bv.y + wv.z * bv.z + wv.w * bv.w;
    }
#pragma unroll
    for (int off = 16; off; off >>= 1)
        s += __shfl_xor_sync(0xffffffffu, s, off);
    if (lane == 0) wbo[a] = s;
}

// ---------------------------------------------------------------------------
// out[row] = softplus( (dot(ctx[row],u[row]) + dot(g1[row],wbo)) * scale )
// ---------------------------------------------------------------------------
__global__ __launch_bounds__(128) void score_kernel(
    const float* __restrict__ ctx, const float* __restrict__ u,
    const float* __restrict__ g1, const float* __restrict__ wbo,
    const float* __restrict__ scale, float* __restrict__ out)
{
    const int row = blockIdx.x;
    const int t = threadIdx.x;
    const float4 a = ((const float4*)(ctx + (size_t)row * DIMV))[t];
    const float4 b = ((const float4*)(u   + (size_t)row * DIMV))[t];
    const float4 c = ((const float4*)(g1  + (size_t)row * DIMV))[t];
    const float4 d = ((const float4*)wbo)[t];
    float s = a.x * b.x + a.y * b.y + a.z * b.z + a.w * b.w
            + c.x * d.x + c.y * d.y + c.z * d.z + c.w * d.w;
#pragma unroll
    for (int off = 16; off; off >>= 1)
        s += __shfl_xor_sync(0xffffffffu, s, off);
    __shared__ float red[4];
    if ((t & 31) == 0) red[t >> 5] = s;
    __syncthreads();
    if (t == 0) {
        const float tot = red[0] + red[1] + red[2] + red[3];
        const float z = tot * scale[0];
        out[row] = fmaxf(z, 0.f) + log1pf(__expf(-fabsf(z)));
    }
}

// ---------------------------------------------------------------------------
extern "C" void kernel_launch(void* const* d_in, const int* in_sizes, int n_in,
                              void* d_out, int out_size)
{
    const float* g1    = (const float*)d_in[0];
    const float* g2    = (const float*)d_in[1];
    const float* Wq    = (const float*)d_in[2];
    const float* bq    = (const float*)d_in[3];
    const float* Wk    = (const float*)d_in[4];
    const float* bk    = (const float*)d_in[5];
    const float* Wv    = (const float*)d_in[6];
    const float* bv    = (const float*)d_in[7];
    const float* Wo    = (const float*)d_in[8];
    const float* bo    = (const float*)d_in[9];
    const float* Wb    = (const float*)d_in[10];
    const float* scale = (const float*)d_in[11];
    float* out = (float*)d_out;

    float *Qp, *Kp, *Vp, *CTXp, *Up;
    float *g1r, *g2r, *Wqr, *Wkr, *Wvr, *Wor, *Wr, *Mp, *Mtp, *wbop;
    cudaGetSymbolAddress((void**)&Qp,   g_Q);
    cudaGetSymbolAddress((void**)&Kp,   g_K);
    cudaGetSymbolAddress((void**)&Vp,   g_V);
    cudaGetSymbolAddress((void**)&CTXp, g_CTX);
    cudaGetSymbolAddress((void**)&Up,   g_U);
    cudaGetSymbolAddress((void**)&g1r,  g_g1r);
    cudaGetSymbolAddress((void**)&g2r,  g_g2r);
    cudaGetSymbolAddress((void**)&Wqr,  g_Wqr);
    cudaGetSymbolAddress((void**)&Wkr,  g_Wkr);
    cudaGetSymbolAddress((void**)&Wvr,  g_Wvr);
    cudaGetSymbolAddress((void**)&Wor,  g_Wor);
    cudaGetSymbolAddress((void**)&Wr,   g_Wr);
    cudaGetSymbolAddress((void**)&Mp,   g_M);
    cudaGetSymbolAddress((void**)&Mtp,  g_Mt);
    cudaGetSymbolAddress((void**)&wbop, g_wbo);

    cudaFuncSetAttribute((const void*)gemm_tc<false, false, true>, cudaFuncAttributeMaxDynamicSharedMemorySize, GEMM_SMEM);
    cudaFuncSetAttribute((const void*)gemm_tc2<true, false>, cudaFuncAttributeMaxDynamicSharedMemorySize, GEMM_SMEM);
    cudaFuncSetAttribute((const void*)gemm_tc2<true, true >, cudaFuncAttributeMaxDynamicSharedMemorySize, GEMM_SMEM);
    cudaFuncSetAttribute((const void*)attn_tc, cudaFuncAttributeMaxDynamicSharedMemorySize, ATTN_SMEM);

    const int M = BATCH * N1V;                 // 8192

    // tf32 pre-round inputs + weights
    round2_k<<<dim3((M * DIMV) / 4 / 256, 2), 256>>>(g1, g2, g1r, g2r);
    round5_k<<<dim3(256, 5), 256>>>(Wq, Wk, Wv, Wb, Wo, Wqr, Wkr, Wvr, Wr, Wor);

    gemv_wbo<<<DIMV / 8, 256>>>(Wb, bo, wbop);

    // M = W @ Wo (512^3, NN, rounded), then Mt = M^T (bit-exact)
    gemm_tc<false, false, true><<<dim3(4, 4), 256, GEMM_SMEM>>>(Wr, Wor, nullptr, Mp, DIMV, DIMV, DIMV);
    transpose512<<<dim3(16, 16), dim3(32, 8)>>>(Mp, Mtp);

    // Fused pairs sharing the A operand:
    //   (Q [rounded, pre-scaled 1/8], U [plain fp32]) from g1r
    //   (K [rounded], V [rounded]) from g2r
    dim3 gg2(8, M / 128);                      // 512 blocks each
    gemm_tc2<true, false><<<gg2, 256, GEMM_SMEM>>>(g1r, Wqr, bq, Qp, Mtp, nullptr, Up,
                                                   0.125f, 1.0f, M, DIMV, DIMV);
    gemm_tc2<true, true ><<<gg2, 256, GEMM_SMEM>>>(g2r, Wkr, bk, Kp, Wvr, bv, Vp,
                                                   1.0f, 1.0f, M, DIMV, DIMV);

    attn_tc<<<dim3(N1V / BQ, BATCH * NHEAD), 128, ATTN_SMEM>>>(Qp, Kp, Vp, CTXp);

    score_kernel<<<M, 128>>>(CTXp, Up, g1, wbop, scale, out);
}

// round 12
// speedup vs baseline: 1.5613x; 1.3730x over previous
#include <cuda_runtime.h>
#include <cuda_fp16.h>
#include <math.h>
#include <stdint.h>

#define BATCH 4
#define N1V 2048
#define N2V 2048
#define DIMV 512
#define NHEAD 8
#define HD 64

// Scratch (device globals: no allocation allowed in kernel_launch)
__device__ __align__(256) __half g_Q  [BATCH * N1V * DIMV];
__device__ __align__(256) __half g_K  [BATCH * N2V * DIMV];
__device__ __align__(256) __half g_V  [BATCH * N2V * DIMV];
__device__ __align__(256) float g_CTX [BATCH * N1V * DIMV];
__device__ __align__(256) float g_U   [BATCH * N1V * DIMV];
__device__ __align__(256) float g_g1r [BATCH * N1V * DIMV];
__device__ __align__(256) float g_g2r [BATCH * N2V * DIMV];
__device__ __align__(256) float g_Wqr [DIMV * DIMV];
__device__ __align__(256) float g_Wkr [DIMV * DIMV];
__device__ __align__(256) float g_Wvr [DIMV * DIMV];
__device__ __align__(256) float g_Wor [DIMV * DIMV];
__device__ __align__(256) float g_Wr  [DIMV * DIMV];
__device__ __align__(256) float g_M   [DIMV * DIMV];     // W @ Wo (tf32-rounded)
__device__ __align__(256) float g_Mt  [DIMV * DIMV];     // (W @ Wo)^T
__device__ __align__(256) float g_wbo [DIMV];            // W @ bo

// ---------------------------------------------------------------------------
__device__ __forceinline__ uint32_t f2tf(float x) {
    uint32_t u;
    asm("cvt.rna.tf32.f32 %0, %1;" : "=r"(u) : "f"(x));
    return u;
}

// pack two floats -> half2 (lo = a, hi = b)
__device__ __forceinline__ uint32_t f2h2(float a, float b) {
    uint32_t u;
    asm("cvt.rn.f16x2.f32 %0, %1, %2;" : "=r"(u) : "f"(b), "f"(a));
    return u;
}

__device__ __forceinline__ void mma_tf32(float* c, const uint32_t* a, const uint32_t* b) {
    asm volatile(
        "mma.sync.aligned.m16n8k8.row.col.f32.tf32.tf32.f32 "
        "{%0,%1,%2,%3}, {%4,%5,%6,%7}, {%8,%9}, {%0,%1,%2,%3};\n"
        : "+f"(c[0]), "+f"(c[1]), "+f"(c[2]), "+f"(c[3])
        : "r"(a[0]), "r"(a[1]), "r"(a[2]), "r"(a[3]), "r"(b[0]), "r"(b[1]));
}

__device__ __forceinline__ void mma_f16(float* c, const uint32_t* a, const uint32_t* b) {
    asm volatile(
        "mma.sync.aligned.m16n8k16.row.col.f32.f16.f16.f32 "
        "{%0,%1,%2,%3}, {%4,%5,%6,%7}, {%8,%9}, {%0,%1,%2,%3};\n"
        : "+f"(c[0]), "+f"(c[1]), "+f"(c[2]), "+f"(c[3])
        : "r"(a[0]), "r"(a[1]), "r"(a[2]), "r"(a[3]), "r"(b[0]), "r"(b[1]));
}

__device__ __forceinline__ void ldsm_x2_trans(uint32_t& b0, uint32_t& b1, uint32_t addr) {
    asm volatile("ldmatrix.sync.aligned.m8n8.x2.trans.shared.b16 {%0,%1}, [%2];"
                 : "=r"(b0), "=r"(b1) : "r"(addr));
}

__device__ __forceinline__ void cp16(uint32_t dst_smem, const void* src) {
    asm volatile("cp.async.cg.shared.global [%0], [%1], 16;\n" :: "r"(dst_smem), "l"(src));
}
#define CP_COMMIT() asm volatile("cp.async.commit_group;\n" ::: "memory")
#define CP_WAIT(n)  asm volatile("cp.async.wait_group %0;\n" :: "n"(n) : "memory")

__device__ __forceinline__ uint32_t smaddr(const void* p) {
    return (uint32_t)__cvta_generic_to_shared(p);
}

// ---------------------------------------------------------------------------
// Fused tf32 pre-round for g1, g2 (blockIdx.y selects)
// ---------------------------------------------------------------------------
__global__ __launch_bounds__(256) void round2_k(
    const float* __restrict__ a0, const float* __restrict__ a1,
    float* __restrict__ o0, float* __restrict__ o1)
{
    const float* in = blockIdx.y ? a1 : a0;
    float* out      = blockIdx.y ? o1 : o0;
    const int i = blockIdx.x * 256 + threadIdx.x;
    float4 v = ((const float4*)in)[i];
    float4 r;
    r.x = __uint_as_float(f2tf(v.x));
    r.y = __uint_as_float(f2tf(v.y));
    r.z = __uint_as_float(f2tf(v.z));
    r.w = __uint_as_float(f2tf(v.w));
    ((float4*)out)[i] = r;
}

// Fused tf32 pre-round for the five 512x512 weight matrices
__global__ __launch_bounds__(256) void round5_k(
    const float* __restrict__ w0, const float* __restrict__ w1,
    const float* __restrict__ w2, const float* __restrict__ w3,
    const float* __restrict__ w4,
    float* __restrict__ o0, float* __restrict__ o1,
    float* __restrict__ o2, float* __restrict__ o3,
    float* __restrict__ o4)
{
    const float* in;
    float* out;
    switch (blockIdx.y) {
        case 0: in = w0; out = o0; break;
        case 1: in = w1; out = o1; break;
        case 2: in = w2; out = o2; break;
        case 3: in = w3; out = o3; break;
        default: in = w4; out = o4; break;
    }
    const int i = blockIdx.x * 256 + threadIdx.x;
    float4 v = ((const float4*)in)[i];
    float4 r;
    r.x = __uint_as_float(f2tf(v.x));
    r.y = __uint_as_float(f2tf(v.y));
    r.z = __uint_as_float(f2tf(v.z));
    r.w = __uint_as_float(f2tf(v.w));
    ((float4*)out)[i] = r;
}

// 512x512 transpose (bit-exact), 32x32 tiles
__global__ __launch_bounds__(256) void transpose512(
    const float* __restrict__ in, float* __restrict__ out)
{
    __shared__ float tile[32][33];
    const int tx = threadIdx.x, ty = threadIdx.y;
    const int x = blockIdx.x * 32 + tx;
    const int y0 = blockIdx.y * 32 + ty;
#pragma unroll
    for (int j = 0; j < 4; j++)
        tile[ty + 8 * j][tx] = in[(size_t)(y0 + 8 * j) * DIMV + x];
    __syncthreads();
    const int x2 = blockIdx.y * 32 + tx;
    const int y2 = blockIdx.x * 32 + ty;
#pragma unroll
    for (int j = 0; j < 4; j++)
        out[(size_t)(y2 + 8 * j) * DIMV + x2] = tile[tx][ty + 8 * j];
}

// ---------------------------------------------------------------------------
// tf32 TC GEMM, 2-stage cp.async pipeline. Inputs must be tf32-pre-rounded.
// ---------------------------------------------------------------------------
#define AS_STRIDE 36
#define BS_STRIDE_NT 132
#define STG_U32 4608
#define GEMM_SMEM (4 * STG_U32 * 4)        // 73728 B

template<bool TRANSB>
__device__ __forceinline__ void g_prefetch(
    uint32_t* As, uint32_t* Bs, const float* A, const float* Wt,
    int m0, int n0, int k0, int K, int N, int t)
{
#pragma unroll
    for (int j = 0; j < 4; j++) {
        const int idx = t + 256 * j;
        const int row = idx >> 3, c4 = (idx & 7) << 2;
        cp16(smaddr(&As[row * AS_STRIDE + c4]),
             A + (size_t)(m0 + row) * K + k0 + c4);
    }
    if (TRANSB) {
#pragma unroll
        for (int j = 0; j < 4; j++) {
            const int idx = t + 256 * j;
            const int row = idx >> 3, c4 = (idx & 7) << 2;
            cp16(smaddr(&Bs[row * AS_STRIDE + c4]),
                 Wt + (size_t)(n0 + row) * K + k0 + c4);
        }
    } else {
#pragma unroll
        for (int j = 0; j < 4; j++) {
            const int idx = t + 256 * j;
            const int row = idx >> 5, n4 = (idx & 31) << 2;
            cp16(smaddr(&Bs[row * BS_STRIDE_NT + n4]),
                 Wt + (size_t)(k0 + row) * N + n0 + n4);
        }
    }
}

template<bool TRANSB>
__device__ __forceinline__ void gemm_body(
    uint32_t* sm, const float* A, const float* Wt,
    int m0, int n0, int K, int N, int t, float acc[4][4][4])
{
    const int lane = t & 31;
    const int w    = t >> 5;
    const int g    = lane >> 2;
    const int tid4 = lane & 3;
    const int warpM = (w >> 2) * 64;
    const int warpN = (w & 3) * 32;

    const int nIter = K / 32;

    g_prefetch<TRANSB>(sm, sm + 2 * STG_U32, A, Wt, m0, n0, 0, K, N, t);
    CP_COMMIT();

    int st = 0;
    for (int it = 0; it < nIter; it++) {
        if (it + 1 < nIter) {
            g_prefetch<TRANSB>(sm + (st ^ 1) * STG_U32, sm + (2 + (st ^ 1)) * STG_U32,
                               A, Wt, m0, n0, (it + 1) * 32, K, N, t);
            CP_COMMIT();
            CP_WAIT(1);
        } else {
            CP_WAIT(0);
        }
        __syncthreads();

        uint32_t* As = sm + st * STG_U32;
        uint32_t* Bs = sm + (2 + st) * STG_U32;

#pragma unroll
        for (int ks = 0; ks < 4; ks++) {
            uint32_t a[4][4], b[4][2];
            const int kc = tid4 + 8 * ks;
#pragma unroll
            for (int mi = 0; mi < 4; mi++) {
                const int r = warpM + 16 * mi + g;
                a[mi][0] = As[r * AS_STRIDE + kc];
                a[mi][1] = As[(r + 8) * AS_STRIDE + kc];
                a[mi][2] = As[r * AS_STRIDE + kc + 4];
                a[mi][3] = As[(r + 8) * AS_STRIDE + kc + 4];
            }
#pragma unroll
            for (int ni = 0; ni < 4; ni++) {
                const int n = warpN + 8 * ni + g;
                if (TRANSB) {
                    b[ni][0] = Bs[n * AS_STRIDE + kc];
                    b[ni][1] = Bs[n * AS_STRIDE + kc + 4];
                } else {
                    b[ni][0] = Bs[kc * BS_STRIDE_NT + n];
                    b[ni][1] = Bs[(kc + 4) * BS_STRIDE_NT + n];
                }
            }
#pragma unroll
            for (int mi = 0; mi < 4; mi++)
#pragma unroll
                for (int ni = 0; ni < 4; ni++)
                    mma_tf32(acc[mi][ni], a[mi], b[ni]);
        }
        __syncthreads();
        st ^= 1;
    }
}

template<bool TRANSB, bool HASBIAS, bool ROUND>
__global__ __launch_bounds__(256, 2) void gemm_tc(
    const float* __restrict__ A, const float* __restrict__ Wt,
    const float* __restrict__ bias, float* __restrict__ C,
    int M, int N, int K)
{
    extern __shared__ uint32_t sm[];
    const int t  = threadIdx.x;
    const int m0 = blockIdx.y * 128, n0 = blockIdx.x * 128;

    float acc[4][4][4];
#pragma unroll
    for (int mi = 0; mi < 4; mi++)
#pragma unroll
        for (int ni = 0; ni < 4; ni++)
#pragma unroll
            for (int c = 0; c < 4; c++) acc[mi][ni][c] = 0.f;

    gemm_body<TRANSB>(sm, A, Wt, m0, n0, K, N, t, acc);

    const int lane = t & 31, w = t >> 5;
    const int g = lane >> 2, tid4 = lane & 3;
    const int warpM = (w >> 2) * 64, warpN = (w & 3) * 32;
#pragma unroll
    for (int mi = 0; mi < 4; mi++) {
#pragma unroll
        for (int ni = 0; ni < 4; ni++) {
            const int row = m0 + warpM + 16 * mi + g;
            const int col = n0 + warpN + 8 * ni + 2 * tid4;
            float bx = 0.f, by = 0.f;
            if (HASBIAS) { bx = bias[col]; by = bias[col + 1]; }
            float v00 = acc[mi][ni][0] + bx, v01 = acc[mi][ni][1] + by;
            float v10 = acc[mi][ni][2] + bx, v11 = acc[mi][ni][3] + by;
            if (ROUND) {
                v00 = __uint_as_float(f2tf(v00)); v01 = __uint_as_float(f2tf(v01));
                v10 = __uint_as_float(f2tf(v10)); v11 = __uint_as_float(f2tf(v11));
            }
            *(float2*)(C + (size_t)row * N + col)       = make_float2(v00, v01);
            *(float2*)(C + (size_t)(row + 8) * N + col) = make_float2(v10, v11);
        }
    }
}

// Fused dual-output GEMM (both TRANSB): grid.x = 8.
// blockIdx.x < 4 -> output 0, else output 1.
// HALFx: output scaled by scalex then converted to fp16. else plain fp32.
template<bool HALF0, bool HALF1>
__global__ __launch_bounds__(256, 2) void gemm_tc2(
    const float* __restrict__ A,
    const float* __restrict__ W0, const float* __restrict__ b0, void* __restrict__ C0,
    const float* __restrict__ W1, const float* __restrict__ b1, void* __restrict__ C1,
    float scale0, float scale1,
    int M, int N, int K)
{
    extern __shared__ uint32_t sm[];
    const int t = threadIdx.x;
    const bool second = blockIdx.x >= 4;
    const float* Wt   = second ? W1 : W0;
    const float* bias = second ? b1 : b0;
    void* C           = second ? C1 : C0;
    const float scl   = second ? scale1 : scale0;
    const bool doHalf = second ? HALF1 : HALF0;
    const int m0 = blockIdx.y * 128;
    const int n0 = (blockIdx.x & 3) * 128;

    float acc[4][4][4];
#pragma unroll
    for (int mi = 0; mi < 4; mi++)
#pragma unroll
        for (int ni = 0; ni < 4; ni++)
#pragma unroll
            for (int c = 0; c < 4; c++) acc[mi][ni][c] = 0.f;

    gemm_body<true>(sm, A, Wt, m0, n0, K, N, t, acc);

    const int lane = t & 31, w = t >> 5;
    const int g = lane >> 2, tid4 = lane & 3;
    const int warpM = (w >> 2) * 64, warpN = (w & 3) * 32;
    const bool hb = (bias != nullptr);
#pragma unroll
    for (int mi = 0; mi < 4; mi++) {
#pragma unroll
        for (int ni = 0; ni < 4; ni++) {
            const int row = m0 + warpM + 16 * mi + g;
            const int col = n0 + warpN + 8 * ni + 2 * tid4;
            float bx = 0.f, by = 0.f;
            if (hb) { bx = bias[col]; by = bias[col + 1]; }
            float v00 = acc[mi][ni][0] + bx, v01 = acc[mi][ni][1] + by;
            float v10 = acc[mi][ni][2] + bx, v11 = acc[mi][ni][3] + by;
            if (doHalf) {
                __half* Ch = (__half*)C;
                *(uint32_t*)(Ch + (size_t)row * N + col)       = f2h2(v00 * scl, v01 * scl);
                *(uint32_t*)(Ch + (size_t)(row + 8) * N + col) = f2h2(v10 * scl, v11 * scl);
            } else {
                float* Cf = (float*)C;
                *(float2*)(Cf + (size_t)row * N + col)       = make_float2(v00, v01);
                *(float2*)(Cf + (size_t)(row + 8) * N + col) = make_float2(v10, v11);
            }
        }
    }
}

// ---------------------------------------------------------------------------
// Flash attention, fp16 m16n8k16 TC. Q pre-scaled by 1/8, all fp16 inputs.
// Block = 128 q-rows x (b,h). 4 warps x 32 q-rows. BKV=64.
// Smem rows: 64 halves = 32 u32, stride 36 u32 (144 B; ldmatrix conflict-free).
// ---------------------------------------------------------------------------
#define BQ 128
#define BKV 64
#define HSTR 36
#define ATTN_SMEM ((BQ + BKV + BKV + BQ) * HSTR * 4)   // 55296 B

__global__ __launch_bounds__(128) void attn_tc(
    const __half* __restrict__ Q, const __half* __restrict__ K,
    const __half* __restrict__ V, float* __restrict__ ctx)
{
    extern __shared__ uint32_t smA[];
    uint32_t* Qs = smA;
    uint32_t* Ks = Qs + BQ * HSTR;
    uint32_t* Vs = Ks + BKV * HSTR;
    uint32_t* Ps = Vs + BKV * HSTR;

    const int qb = blockIdx.x;
    const int bh = blockIdx.y;
    const int b  = bh >> 3, h = bh & 7;
    const int t  = threadIdx.x;
    const int w  = t >> 5, lane = t & 31;
    const int g  = lane >> 2, tid4 = lane & 3;

    const __half* Qb = Q + ((size_t)b * N1V + qb * BQ) * DIMV + h * HD;
    const __half* Kb = K + (size_t)b * N2V * DIMV + h * HD;
    const __half* Vb = V + (size_t)b * N2V * DIMV + h * HD;

    // Q tile: 128 rows x 64 halves (8 float4 per row)
#pragma unroll
    for (int j = 0; j < 8; j++) {
        const int idx = t + 128 * j;
        const int row = idx >> 3, c = idx & 7;
        *(float4*)&Qs[row * HSTR + 4 * c] = *(const float4*)(Qb + (size_t)row * DIMV + 8 * c);
    }

    const uint32_t vlbase = smaddr(Vs) + (lane & 15) * (HSTR * 4);

    float m_[2][2], l_[2][2], o[2][8][4];
#pragma unroll
    for (int mi = 0; mi < 2; mi++) {
        m_[mi][0] = -1e30f; m_[mi][1] = -1e30f;
        l_[mi][0] = 0.f;    l_[mi][1] = 0.f;
#pragma unroll
        for (int ni = 0; ni < 8; ni++)
#pragma unroll
            for (int c = 0; c < 4; c++) o[mi][ni][c] = 0.f;
    }

    for (int kt = 0; kt < N2V / BKV; kt++) {
        __syncthreads();
        // K and V tiles: 64 rows x 64 halves each (4 iters each)
#pragma unroll
        for (int j = 0; j < 4; j++) {
            const int idx = t + 128 * j;
            const int row = idx >> 3, c = idx & 7;
            *(float4*)&Ks[row * HSTR + 4 * c] =
                *(const float4*)(Kb + (size_t)(kt * BKV + row) * DIMV + 8 * c);
            *(float4*)&Vs[row * HSTR + 4 * c] =
                *(const float4*)(Vb + (size_t)(kt * BKV + row) * DIMV + 8 * c);
        }
        __syncthreads();

        // S = Q @ K^T  (k=16 per mma, 4 k-steps)
        float s[2][8][4];
#pragma unroll
        for (int mi = 0; mi < 2; mi++)
#pragma unroll
            for (int ni = 0; ni < 8; ni++)
#pragma unroll
                for (int c = 0; c < 4; c++) s[mi][ni][c] = 0.f;

#pragma unroll
        for (int ks = 0; ks < 4; ks++) {
            const int kc = 8 * ks + tid4;
            uint32_t a[2][4], bf[8][2];
#pragma unroll
            for (int mi = 0; mi < 2; mi++) {
                const int r = w * 32 + 16 * mi + g;
                a[mi][0] = Qs[r * HSTR + kc];
                a[mi][1] = Qs[(r + 8) * HSTR + kc];
                a[mi][2] = Qs[r * HSTR + kc + 4];
                a[mi][3] = Qs[(r + 8) * HSTR + kc + 4];
            }
#pragma unroll
            for (int ni = 0; ni < 8; ni++) {
                const int n = 8 * ni + g;
                bf[ni][0] = Ks[n * HSTR + kc];
                bf[ni][1] = Ks[n * HSTR + kc + 4];
            }
#pragma unroll
            for (int mi = 0; mi < 2; mi++)
#pragma unroll
                for (int ni = 0; ni < 8; ni++)
                    mma_f16(s[mi][ni], a[mi], bf[ni]);
        }

        // online softmax (Q pre-scaled by 1/8)
#pragma unroll
        for (int mi = 0; mi < 2; mi++) {
            float mx0 = -1e30f, mx1 = -1e30f;
#pragma unroll
            for (int ni = 0; ni < 8; ni++) {
                mx0 = fmaxf(mx0, fmaxf(s[mi][ni][0], s[mi][ni][1]));
                mx1 = fmaxf(mx1, fmaxf(s[mi][ni][2], s[mi][ni][3]));
            }
            mx0 = fmaxf(mx0, __shfl_xor_sync(0xffffffffu, mx0, 1));
            mx0 = fmaxf(mx0, __shfl_xor_sync(0xffffffffu, mx0, 2));
            mx1 = fmaxf(mx1, __shfl_xor_sync(0xffffffffu, mx1, 1));
            mx1 = fmaxf(mx1, __shfl_xor_sync(0xffffffffu, mx1, 2));
            const float mn0 = fmaxf(m_[mi][0], mx0);
            const float mn1 = fmaxf(m_[mi][1], mx1);
            float sum0 = 0.f, sum1 = 0.f;
#pragma unroll
            for (int ni = 0; ni < 8; ni++) {
                s[mi][ni][0] = __expf(s[mi][ni][0] - mn0);
                s[mi][ni][1] = __expf(s[mi][ni][1] - mn0);
                s[mi][ni][2] = __expf(s[mi][ni][2] - mn1);
                s[mi][ni][3] = __expf(s[mi][ni][3] - mn1);
                sum0 += s[mi][ni][0] + s[mi][ni][1];
                sum1 += s[mi][ni][2] + s[mi][ni][3];
            }
            sum0 += __shfl_xor_sync(0xffffffffu, sum0, 1);
            sum0 += __shfl_xor_sync(0xffffffffu, sum0, 2);
            sum1 += __shfl_xor_sync(0xffffffffu, sum1, 1);
            sum1 += __shfl_xor_sync(0xffffffffu, sum1, 2);
            const float al0 = __expf(m_[mi][0] - mn0);
            const float al1 = __expf(m_[mi][1] - mn1);
            m_[mi][0] = mn0; m_[mi][1] = mn1;
            l_[mi][0] = l_[mi][0] * al0 + sum0;
            l_[mi][1] = l_[mi][1] * al1 + sum1;
#pragma unroll
            for (int ni = 0; ni < 8; ni++) {
                o[mi][ni][0] *= al0; o[mi][ni][1] *= al0;
                o[mi][ni][2] *= al1; o[mi][ni][3] *= al1;
            }
            const int r = w * 32 + 16 * mi + g;
#pragma unroll
            for (int ni = 0; ni < 8; ni++) {
                // cols 2*tid4+8*ni, +1 -> u32 index tid4 + 4*ni (half2 packed)
                Ps[r * HSTR + 4 * ni + tid4]       = f2h2(s[mi][ni][0], s[mi][ni][1]);
                Ps[(r + 8) * HSTR + 4 * ni + tid4] = f2h2(s[mi][ni][2], s[mi][ni][3]);
            }
        }
        __syncwarp();

        // O += P @ V  (V fragments via ldmatrix.trans on [k][n] tile)
#pragma unroll
        for (int ks = 0; ks < 4; ks++) {
            const int kc = 8 * ks + tid4;
            uint32_t a[2][4], bf[8][2];
#pragma unroll
            for (int mi = 0; mi < 2; mi++) {
                const int r = w * 32 + 16 * mi + g;
                a[mi][0] = Ps[r * HSTR + kc];
                a[mi][1] = Ps[(r + 8) * HSTR + kc];
                a[mi][2] = Ps[r * HSTR + kc + 4];
                a[mi][3] = Ps[(r + 8) * HSTR + kc + 4];
            }
            const uint32_t vk = vlbase + ks * 16 * (HSTR * 4);
#pragma unroll
            for (int ni = 0; ni < 8; ni++)
                ldsm_x2_trans(bf[ni][0], bf[ni][1], vk + ni * 16);
#pragma unroll
            for (int mi = 0; mi < 2; mi++)
#pragma unroll
                for (int ni = 0; ni < 8; ni++)
                    mma_f16(o[mi][ni], a[mi], bf[ni]);
        }
        __syncwarp();
    }

#pragma unroll
    for (int mi = 0; mi < 2; mi++) {
        const float inv0 = 1.0f / l_[mi][0];
        const float inv1 = 1.0f / l_[mi][1];
        const int r = qb * BQ + w * 32 + 16 * mi + g;
#pragma unroll
        for (int ni = 0; ni < 8; ni++) {
            const int col = h * HD + 2 * tid4 + 8 * ni;
            float2 v0 = make_float2(o[mi][ni][0] * inv0, o[mi][ni][1] * inv0);
            float2 v1 = make_float2(o[mi][ni][2] * inv1, o[mi][ni][3] * inv1);
            *(float2*)(ctx + ((size_t)b * N1V + r) * DIMV + col)     = v0;
            *(float2*)(ctx + ((size_t)b * N1V + r + 8) * DIMV + col) = v1;
        }
    }
}

// ---------------------------------------------------------------------------
__global__ __launch_bounds__(256) void gemv_wbo(
    const float* __restrict__ W, const float* __restrict__ bo,
    float* __restrict__ wbo)
{
    const int a = blockIdx.x * 8 + (threadIdx.x >> 5);
    const int lane = threadIdx.x & 31;
    float s = 0.f;
#pragma unroll
    for (int i = 0; i < 4; i++) {
        const int j = lane + 32 * i;
        float4 wv = ((const float4*)(W + (size_t)a * DIMV))[j];
        float4 bv = ((const float4*)bo)[j];
        s += wv.x * bv.x + wv.y * bv.y + wv.z * bv.z + wv.w * bv.w;
    }
#pragma unroll
    for (int off = 16; off; off >>= 1)
        s += __shfl_xor_sync(0xffffffffu, s, off);
    if (lane == 0) wbo[a] = s;
}

// ---------------------------------------------------------------------------
__global__ __launch_bounds__(128) void score_kernel(
    const float* __restrict__ ctx, const float* __restrict__ u,
    const float* __restrict__ g1, const float* __restrict__ wbo,
    const float* __restrict__ scale, float* __restrict__ out)
{
    const int row = blockIdx.x;
    const int t = threadIdx.x;
    const float4 a = ((const float4*)(ctx + (size_t)row * DIMV))[t];
    const float4 b = ((const float4*)(u   + (size_t)row * DIMV))[t];
    const float4 c = ((const float4*)(g1  + (size_t)row * DIMV))[t];
    const float4 d = ((const float4*)wbo)[t];
    float s = a.x * b.x + a.y * b.y + a.z * b.z + a.w * b.w
            + c.x * d.x + c.y * d.y + c.z * d.z + c.w * d.w;
#pragma unroll
    for (int off = 16; off; off >>= 1)
        s += __shfl_xor_sync(0xffffffffu, s, off);
    __shared__ float red[4];
    if ((t & 31) == 0) red[t >> 5] = s;
    __syncthreads();
    if (t == 0) {
        const float tot = red[0] + red[1] + red[2] + red[3];
        const float z = tot * scale[0];
        out[row] = fmaxf(z, 0.f) + log1pf(__expf(-fabsf(z)));
    }
}

// ---------------------------------------------------------------------------
extern "C" void kernel_launch(void* const* d_in, const int* in_sizes, int n_in,
                              void* d_out, int out_size)
{
    const float* g1    = (const float*)d_in[0];
    const float* g2    = (const float*)d_in[1];
    const float* Wq    = (const float*)d_in[2];
    const float* bq    = (const float*)d_in[3];
    const float* Wk    = (const float*)d_in[4];
    const float* bk    = (const float*)d_in[5];
    const float* Wv    = (const float*)d_in[6];
    const float* bv    = (const float*)d_in[7];
    const float* Wo    = (const float*)d_in[8];
    const float* bo    = (const float*)d_in[9];
    const float* Wb    = (const float*)d_in[10];
    const float* scale = (const float*)d_in[11];
    float* out = (float*)d_out;

    __half *Qp, *Kp, *Vp;
    float *CTXp, *Up;
    float *g1r, *g2r, *Wqr, *Wkr, *Wvr, *Wor, *Wr, *Mp, *Mtp, *wbop;
    cudaGetSymbolAddress((void**)&Qp,   g_Q);
    cudaGetSymbolAddress((void**)&Kp,   g_K);
    cudaGetSymbolAddress((void**)&Vp,   g_V);
    cudaGetSymbolAddress((void**)&CTXp, g_CTX);
    cudaGetSymbolAddress((void**)&Up,   g_U);
    cudaGetSymbolAddress((void**)&g1r,  g_g1r);
    cudaGetSymbolAddress((void**)&g2r,  g_g2r);
    cudaGetSymbolAddress((void**)&Wqr,  g_Wqr);
    cudaGetSymbolAddress((void**)&Wkr,  g_Wkr);
    cudaGetSymbolAddress((void**)&Wvr,  g_Wvr);
    cudaGetSymbolAddress((void**)&Wor,  g_Wor);
    cudaGetSymbolAddress((void**)&Wr,   g_Wr);
    cudaGetSymbolAddress((void**)&Mp,   g_M);
    cudaGetSymbolAddress((void**)&Mtp,  g_Mt);
    cudaGetSymbolAddress((void**)&wbop, g_wbo);

    cudaFuncSetAttribute((const void*)gemm_tc<false, false, true>, cudaFuncAttributeMaxDynamicSharedMemorySize, GEMM_SMEM);
    cudaFuncSetAttribute((const void*)gemm_tc2<true, false>, cudaFuncAttributeMaxDynamicSharedMemorySize, GEMM_SMEM);
    cudaFuncSetAttribute((const void*)gemm_tc2<true, true >, cudaFuncAttributeMaxDynamicSharedMemorySize, GEMM_SMEM);
    cudaFuncSetAttribute((const void*)attn_tc, cudaFuncAttributeMaxDynamicSharedMemorySize, ATTN_SMEM);

    const int M = BATCH * N1V;                 // 8192

    // tf32 pre-round inputs + weights
    round2_k<<<dim3((M * DIMV) / 4 / 256, 2), 256>>>(g1, g2, g1r, g2r);
    round5_k<<<dim3(256, 5), 256>>>(Wq, Wk, Wv, Wb, Wo, Wqr, Wkr, Wvr, Wr, Wor);

    gemv_wbo<<<DIMV / 8, 256>>>(Wb, bo, wbop);

    // M = W @ Wo (512^3, NN, rounded), then Mt = M^T (bit-exact)
    gemm_tc<false, false, true><<<dim3(4, 4), 256, GEMM_SMEM>>>(Wr, Wor, nullptr, Mp, DIMV, DIMV, DIMV);
    transpose512<<<dim3(16, 16), dim3(32, 8)>>>(Mp, Mtp);

    // Fused pairs sharing the A operand:
    //   (Q [fp16, pre-scaled 1/8], U [fp32]) from g1r
    //   (K [fp16], V [fp16]) from g2r
    dim3 gg2(8, M / 128);
    gemm_tc2<true, false><<<gg2, 256, GEMM_SMEM>>>(g1r, Wqr, bq, (void*)Qp, Mtp, nullptr, (void*)Up,
                                                   0.125f, 1.0f, M, DIMV, DIMV);
    gemm_tc2<true, true ><<<gg2, 256, GEMM_SMEM>>>(g2r, Wkr, bk, (void*)Kp, Wvr, bv, (void*)Vp,
                                                   1.0f, 1.0f, M, DIMV, DIMV);

    attn_tc<<<dim3(N1V / BQ, BATCH * NHEAD), 128, ATTN_SMEM>>>(Qp, Kp, Vp, CTXp);

    score_kernel<<<M, 128>>>(CTXp, Up, g1, wbop, scale, out);
}

// round 13
// speedup vs baseline: 1.8635x; 1.1936x over previous
#include <cuda_runtime.h>
#include <cuda_fp16.h>
#include <math.h>
#include <stdint.h>

#define BATCH 4
#define N1V 2048
#define N2V 2048
#define DIMV 512
#define NHEAD 8
#define HD 64

// Scratch (device globals: no allocation allowed in kernel_launch)
__device__ __align__(256) __half g_Q   [BATCH * N1V * DIMV];
__device__ __align__(256) __half g_K   [BATCH * N2V * DIMV];
__device__ __align__(256) __half g_V   [BATCH * N2V * DIMV];
__device__ __align__(256) float  g_CTX [BATCH * N1V * DIMV];
__device__ __align__(256) float  g_U   [BATCH * N1V * DIMV];
__device__ __align__(256) __half g_g1h [BATCH * N1V * DIMV];
__device__ __align__(256) __half g_g2h [BATCH * N2V * DIMV];
__device__ __align__(256) __half g_Wqh [DIMV * DIMV];
__device__ __align__(256) __half g_Wkh [DIMV * DIMV];
__device__ __align__(256) __half g_Wvh [DIMV * DIMV];
__device__ __align__(256) __half g_Wh  [DIMV * DIMV];    // W  (fp16)
__device__ __align__(256) __half g_WoT [DIMV * DIMV];    // Wo^T (fp16)
__device__ __align__(256) float  g_Mf  [DIMV * DIMV];    // W @ Wo (fp32)
__device__ __align__(256) __half g_Mth [DIMV * DIMV];    // (W @ Wo)^T (fp16)
__device__ __align__(256) float  g_wbo [DIMV];           // W @ bo

// ---------------------------------------------------------------------------
// pack two floats -> half2 (lo = a, hi = b)
__device__ __forceinline__ uint32_t f2h2(float a, float b) {
    uint32_t u;
    asm("cvt.rn.f16x2.f32 %0, %1, %2;" : "=r"(u) : "f"(b), "f"(a));
    return u;
}

__device__ __forceinline__ void mma_f16(float* c, const uint32_t* a, const uint32_t* b) {
    asm volatile(
        "mma.sync.aligned.m16n8k16.row.col.f32.f16.f16.f32 "
        "{%0,%1,%2,%3}, {%4,%5,%6,%7}, {%8,%9}, {%0,%1,%2,%3};\n"
        : "+f"(c[0]), "+f"(c[1]), "+f"(c[2]), "+f"(c[3])
        : "r"(a[0]), "r"(a[1]), "r"(a[2]), "r"(a[3]), "r"(b[0]), "r"(b[1]));
}

__device__ __forceinline__ void ldsm_x2_trans(uint32_t& b0, uint32_t& b1, uint32_t addr) {
    asm volatile("ldmatrix.sync.aligned.m8n8.x2.trans.shared.b16 {%0,%1}, [%2];"
                 : "=r"(b0), "=r"(b1) : "r"(addr));
}

__device__ __forceinline__ void cp16(uint32_t dst_smem, const void* src) {
    asm volatile("cp.async.cg.shared.global [%0], [%1], 16;\n" :: "r"(dst_smem), "l"(src));
}
#define CP_COMMIT() asm volatile("cp.async.commit_group;\n" ::: "memory")
#define CP_WAIT(n)  asm volatile("cp.async.wait_group %0;\n" :: "n"(n) : "memory")

__device__ __forceinline__ uint32_t smaddr(const void* p) {
    return (uint32_t)__cvta_generic_to_shared(p);
}

// ---------------------------------------------------------------------------
// fp16 convert: g1, g2 (blockIdx.y selects)
// ---------------------------------------------------------------------------
__global__ __launch_bounds__(256) void cvt2_k(
    const float* __restrict__ a0, const float* __restrict__ a1,
    __half* __restrict__ o0, __half* __restrict__ o1)
{
    const float* in = blockIdx.y ? a1 : a0;
    __half* out     = blockIdx.y ? o1 : o0;
    const int i = blockIdx.x * 256 + threadIdx.x;
    float4 v = ((const float4*)in)[i];
    uint2 r;
    r.x = f2h2(v.x, v.y);
    r.y = f2h2(v.z, v.w);
    ((uint2*)out)[i] = r;
}

// fp16 convert: 4 weight matrices (blockIdx.y selects)
__global__ __launch_bounds__(256) void cvt4_k(
    const float* __restrict__ w0, const float* __restrict__ w1,
    const float* __restrict__ w2, const float* __restrict__ w3,
    __half* __restrict__ o0, __half* __restrict__ o1,
    __half* __restrict__ o2, __half* __restrict__ o3)
{
    const float* in;
    __half* out;
    switch (blockIdx.y) {
        case 0: in = w0; out = o0; break;
        case 1: in = w1; out = o1; break;
        case 2: in = w2; out = o2; break;
        default: in = w3; out = o3; break;
    }
    const int i = blockIdx.x * 256 + threadIdx.x;   // grid.x = 256
    float4 v = ((const float4*)in)[i];
    uint2 r;
    r.x = f2h2(v.x, v.y);
    r.y = f2h2(v.z, v.w);
    ((uint2*)out)[i] = r;
}

// 512x512 transpose with fp32 -> fp16 convert
__global__ __launch_bounds__(256) void trans_f2h(
    const float* __restrict__ in, __half* __restrict__ out)
{
    __shared__ float tile[32][33];
    const int tx = threadIdx.x, ty = threadIdx.y;   // 32 x 8
    const int x = blockIdx.x * 32 + tx;
    const int y0 = blockIdx.y * 32 + ty;
#pragma unroll
    for (int j = 0; j < 4; j++)
        tile[ty + 8 * j][tx] = in[(size_t)(y0 + 8 * j) * DIMV + x];
    __syncthreads();
    const int x2 = blockIdx.y * 32 + tx;
    const int y2 = blockIdx.x * 32 + ty;
#pragma unroll
    for (int j = 0; j < 4; j++)
        out[(size_t)(y2 + 8 * j) * DIMV + x2] = __float2half_rn(tile[tx][ty + 8 * j]);
}

// ---------------------------------------------------------------------------
// fp16 m16n8k16 TC GEMM, TRANSB only: C[M][N] = A[M][K] @ Wt[n][k]^T (+bias)
// 128x128 block, BK=32 halves, 256 threads (8 warps 2x4), warp tile 64x32.
// Smem row = 32 halves = 16 u32, stride 20 u32; 2 stages A+B = 40960 B.
// ---------------------------------------------------------------------------
#define HS 20
#define HSTG (128 * HS)                    // 2560 u32 per operand-stage
#define GEMMH_SMEM (4 * HSTG * 4)          // 40960 B

__device__ __forceinline__ void h_prefetch(
    uint32_t* As, uint32_t* Bs, const __half* A, const __half* Wt,
    int m0, int n0, int k0, int K, int t)
{
#pragma unroll
    for (int j = 0; j < 2; j++) {
        const int idx = t + 256 * j;
        const int row = idx >> 2, c = idx & 3;
        cp16(smaddr(&As[row * HS + 4 * c]),
             A + (size_t)(m0 + row) * K + k0 + 8 * c);
    }
#pragma unroll
    for (int j = 0; j < 2; j++) {
        const int idx = t + 256 * j;
        const int row = idx >> 2, c = idx & 3;
        cp16(smaddr(&Bs[row * HS + 4 * c]),
             Wt + (size_t)(n0 + row) * K + k0 + 8 * c);
    }
}

__device__ __forceinline__ void gemm_h_body(
    uint32_t* sm, const __half* A, const __half* Wt,
    int m0, int n0, int K, int t, float acc[4][4][4])
{
    const int lane = t & 31;
    const int w    = t >> 5;
    const int g    = lane >> 2;
    const int tid4 = lane & 3;
    const int warpM = (w >> 2) * 64;
    const int warpN = (w & 3) * 32;

    const int nIter = K / 32;

    h_prefetch(sm, sm + 2 * HSTG, A, Wt, m0, n0, 0, K, t);
    CP_COMMIT();

    int st = 0;
    for (int it = 0; it < nIter; it++) {
        if (it + 1 < nIter) {
            h_prefetch(sm + (st ^ 1) * HSTG, sm + (2 + (st ^ 1)) * HSTG,
                       A, Wt, m0, n0, (it + 1) * 32, K, t);
            CP_COMMIT();
            CP_WAIT(1);
        } else {
            CP_WAIT(0);
        }
        __syncthreads();

        uint32_t* As = sm + st * HSTG;
        uint32_t* Bs = sm + (2 + st) * HSTG;

#pragma unroll
        for (int ks = 0; ks < 2; ks++) {
            uint32_t a[4][4], b[4][2];
            const int kc = 8 * ks + tid4;
#pragma unroll
            for (int mi = 0; mi < 4; mi++) {
                const int r = warpM + 16 * mi + g;
                a[mi][0] = As[r * HS + kc];
                a[mi][1] = As[(r + 8) * HS + kc];
                a[mi][2] = As[r * HS + kc + 4];
                a[mi][3] = As[(r + 8) * HS + kc + 4];
            }
#pragma unroll
            for (int ni = 0; ni < 4; ni++) {
                const int n = warpN + 8 * ni + g;
                b[ni][0] = Bs[n * HS + kc];
                b[ni][1] = Bs[n * HS + kc + 4];
            }
#pragma unroll
            for (int mi = 0; mi < 4; mi++)
#pragma unroll
                for (int ni = 0; ni < 4; ni++)
                    mma_f16(acc[mi][ni], a[mi], b[ni]);
        }
        __syncthreads();
        st ^= 1;
    }
}

// Single-output fp16 GEMM (fp32 out), used for M = W @ Wo^T^T
__global__ __launch_bounds__(256, 2) void gemm_h1(
    const __half* __restrict__ A, const __half* __restrict__ Wt,
    float* __restrict__ C, int M, int N, int K)
{
    extern __shared__ uint32_t sm[];
    const int t  = threadIdx.x;
    const int m0 = blockIdx.y * 128, n0 = blockIdx.x * 128;

    float acc[4][4][4];
#pragma unroll
    for (int mi = 0; mi < 4; mi++)
#pragma unroll
        for (int ni = 0; ni < 4; ni++)
#pragma unroll
            for (int c = 0; c < 4; c++) acc[mi][ni][c] = 0.f;

    gemm_h_body(sm, A, Wt, m0, n0, K, t, acc);

    const int lane = t & 31, w = t >> 5;
    const int g = lane >> 2, tid4 = lane & 3;
    const int warpM = (w >> 2) * 64, warpN = (w & 3) * 32;
#pragma unroll
    for (int mi = 0; mi < 4; mi++) {
#pragma unroll
        for (int ni = 0; ni < 4; ni++) {
            const int row = m0 + warpM + 16 * mi + g;
            const int col = n0 + warpN + 8 * ni + 2 * tid4;
            *(float2*)(C + (size_t)row * N + col)       = make_float2(acc[mi][ni][0], acc[mi][ni][1]);
            *(float2*)(C + (size_t)(row + 8) * N + col) = make_float2(acc[mi][ni][2], acc[mi][ni][3]);
        }
    }
}

// Fused dual-output fp16 GEMM: grid.x = 8; blockIdx.x<4 -> output 0 else 1.
// HALFx: output scaled by scalex, stored fp16; else plain fp32.
template<bool HALF0, bool HALF1>
__global__ __launch_bounds__(256, 2) void gemm_h2(
    const __half* __restrict__ A,
    const __half* __restrict__ W0, const float* __restrict__ b0, void* __restrict__ C0,
    const __half* __restrict__ W1, const float* __restrict__ b1, void* __restrict__ C1,
    float scale0, float scale1,
    int M, int N, int K)
{
    extern __shared__ uint32_t sm[];
    const int t = threadIdx.x;
    const bool second = blockIdx.x >= 4;
    const __half* Wt  = second ? W1 : W0;
    const float* bias = second ? b1 : b0;
    void* C           = second ? C1 : C0;
    const float scl   = second ? scale1 : scale0;
    const bool doHalf = second ? HALF1 : HALF0;
    const int m0 = blockIdx.y * 128;
    const int n0 = (blockIdx.x & 3) * 128;

    float acc[4][4][4];
#pragma unroll
    for (int mi = 0; mi < 4; mi++)
#pragma unroll
        for (int ni = 0; ni < 4; ni++)
#pragma unroll
            for (int c = 0; c < 4; c++) acc[mi][ni][c] = 0.f;

    gemm_h_body(sm, A, Wt, m0, n0, K, t, acc);

    const int lane = t & 31, w = t >> 5;
    const int g = lane >> 2, tid4 = lane & 3;
    const int warpM = (w >> 2) * 64, warpN = (w & 3) * 32;
    const bool hb = (bias != nullptr);
#pragma unroll
    for (int mi = 0; mi < 4; mi++) {
#pragma unroll
        for (int ni = 0; ni < 4; ni++) {
            const int row = m0 + warpM + 16 * mi + g;
            const int col = n0 + warpN + 8 * ni + 2 * tid4;
            float bx = 0.f, by = 0.f;
            if (hb) { bx = bias[col]; by = bias[col + 1]; }
            float v00 = acc[mi][ni][0] + bx, v01 = acc[mi][ni][1] + by;
            float v10 = acc[mi][ni][2] + bx, v11 = acc[mi][ni][3] + by;
            if (doHalf) {
                __half* Ch = (__half*)C;
                *(uint32_t*)(Ch + (size_t)row * N + col)       = f2h2(v00 * scl, v01 * scl);
                *(uint32_t*)(Ch + (size_t)(row + 8) * N + col) = f2h2(v10 * scl, v11 * scl);
            } else {
                float* Cf = (float*)C;
                *(float2*)(Cf + (size_t)row * N + col)       = make_float2(v00, v01);
                *(float2*)(Cf + (size_t)(row + 8) * N + col) = make_float2(v10, v11);
            }
        }
    }
}

// ---------------------------------------------------------------------------
// Flash attention, fp16 m16n8k16 TC (round-12 proven version).
// ---------------------------------------------------------------------------
#define BQ 128
#define BKV 64
#define HSTR 36
#define ATTN_SMEM ((BQ + BKV + BKV + BQ) * HSTR * 4)   // 55296 B

__global__ __launch_bounds__(128) void attn_tc(
    const __half* __restrict__ Q, const __half* __restrict__ K,
    const __half* __restrict__ V, float* __restrict__ ctx)
{
    extern __shared__ uint32_t smA[];
    uint32_t* Qs = smA;
    uint32_t* Ks = Qs + BQ * HSTR;
    uint32_t* Vs = Ks + BKV * HSTR;
    uint32_t* Ps = Vs + BKV * HSTR;

    const int qb = blockIdx.x;
    const int bh = blockIdx.y;
    const int b  = bh >> 3, h = bh & 7;
    const int t  = threadIdx.x;
    const int w  = t >> 5, lane = t & 31;
    const int g  = lane >> 2, tid4 = lane & 3;

    const __half* Qb = Q + ((size_t)b * N1V + qb * BQ) * DIMV + h * HD;
    const __half* Kb = K + (size_t)b * N2V * DIMV + h * HD;
    const __half* Vb = V + (size_t)b * N2V * DIMV + h * HD;

#pragma unroll
    for (int j = 0; j < 8; j++) {
        const int idx = t + 128 * j;
        const int row = idx >> 3, c = idx & 7;
        *(float4*)&Qs[row * HSTR + 4 * c] = *(const float4*)(Qb + (size_t)row * DIMV + 8 * c);
    }

    const uint32_t vlbase = smaddr(Vs) + (lane & 15) * (HSTR * 4);

    float m_[2][2], l_[2][2], o[2][8][4];
#pragma unroll
    for (int mi = 0; mi < 2; mi++) {
        m_[mi][0] = -1e30f; m_[mi][1] = -1e30f;
        l_[mi][0] = 0.f;    l_[mi][1] = 0.f;
#pragma unroll
        for (int ni = 0; ni < 8; ni++)
#pragma unroll
            for (int c = 0; c < 4; c++) o[mi][ni][c] = 0.f;
    }

    for (int kt = 0; kt < N2V / BKV; kt++) {
        __syncthreads();
#pragma unroll
        for (int j = 0; j < 4; j++) {
            const int idx = t + 128 * j;
            const int row = idx >> 3, c = idx & 7;
            *(float4*)&Ks[row * HSTR + 4 * c] =
                *(const float4*)(Kb + (size_t)(kt * BKV + row) * DIMV + 8 * c);
            *(float4*)&Vs[row * HSTR + 4 * c] =
                *(const float4*)(Vb + (size_t)(kt * BKV + row) * DIMV + 8 * c);
        }
        __syncthreads();

        float s[2][8][4];
#pragma unroll
        for (int mi = 0; mi < 2; mi++)
#pragma unroll
            for (int ni = 0; ni < 8; ni++)
#pragma unroll
                for (int c = 0; c < 4; c++) s[mi][ni][c] = 0.f;

#pragma unroll
        for (int ks = 0; ks < 4; ks++) {
            const int kc = 8 * ks + tid4;
            uint32_t a[2][4], bf[8][2];
#pragma unroll
            for (int mi = 0; mi < 2; mi++) {
                const int r = w * 32 + 16 * mi + g;
                a[mi][0] = Qs[r * HSTR + kc];
                a[mi][1] = Qs[(r + 8) * HSTR + kc];
                a[mi][2] = Qs[r * HSTR + kc + 4];
                a[mi][3] = Qs[(r + 8) * HSTR + kc + 4];
            }
#pragma unroll
            for (int ni = 0; ni < 8; ni++) {
                const int n = 8 * ni + g;
                bf[ni][0] = Ks[n * HSTR + kc];
                bf[ni][1] = Ks[n * HSTR + kc + 4];
            }
#pragma unroll
            for (int mi = 0; mi < 2; mi++)
#pragma unroll
                for (int ni = 0; ni < 8; ni++)
                    mma_f16(s[mi][ni], a[mi], bf[ni]);
        }

#pragma unroll
        for (int mi = 0; mi < 2; mi++) {
            float mx0 = -1e30f, mx1 = -1e30f;
#pragma unroll
            for (int ni = 0; ni < 8; ni++) {
                mx0 = fmaxf(mx0, fmaxf(s[mi][ni][0], s[mi][ni][1]));
                mx1 = fmaxf(mx1, fmaxf(s[mi][ni][2], s[mi][ni][3]));
            }
            mx0 = fmaxf(mx0, __shfl_xor_sync(0xffffffffu, mx0, 1));
            mx0 = fmaxf(mx0, __shfl_xor_sync(0xffffffffu, mx0, 2));
            mx1 = fmaxf(mx1, __shfl_xor_sync(0xffffffffu, mx1, 1));
            mx1 = fmaxf(mx1, __shfl_xor_sync(0xffffffffu, mx1, 2));
            const float mn0 = fmaxf(m_[mi][0], mx0);
            const float mn1 = fmaxf(m_[mi][1], mx1);
            float sum0 = 0.f, sum1 = 0.f;
#pragma unroll
            for (int ni = 0; ni < 8; ni++) {
                s[mi][ni][0] = __expf(s[mi][ni][0] - mn0);
                s[mi][ni][1] = __expf(s[mi][ni][1] - mn0);
                s[mi][ni][2] = __expf(s[mi][ni][2] - mn1);
                s[mi][ni][3] = __expf(s[mi][ni][3] - mn1);
                sum0 += s[mi][ni][0] + s[mi][ni][1];
                sum1 += s[mi][ni][2] + s[mi][ni][3];
            }
            sum0 += __shfl_xor_sync(0xffffffffu, sum0, 1);
            sum0 += __shfl_xor_sync(0xffffffffu, sum0, 2);
            sum1 += __shfl_xor_sync(0xffffffffu, sum1, 1);
            sum1 += __shfl_xor_sync(0xffffffffu, sum1, 2);
            const float al0 = __expf(m_[mi][0] - mn0);
            const float al1 = __expf(m_[mi][1] - mn1);
            m_[mi][0] = mn0; m_[mi][1] = mn1;
            l_[mi][0] = l_[mi][0] * al0 + sum0;
            l_[mi][1] = l_[mi][1] * al1 + sum1;
#pragma unroll
            for (int ni = 0; ni < 8; ni++) {
                o[mi][ni][0] *= al0; o[mi][ni][1] *= al0;
                o[mi][ni][2] *= al1; o[mi][ni][3] *= al1;
            }
            const int r = w * 32 + 16 * mi + g;
#pragma unroll
            for (int ni = 0; ni < 8; ni++) {
                Ps[r * HSTR + 4 * ni + tid4]       = f2h2(s[mi][ni][0], s[mi][ni][1]);
                Ps[(r + 8) * HSTR + 4 * ni + tid4] = f2h2(s[mi][ni][2], s[mi][ni][3]);
            }
        }
        __syncwarp();

#pragma unroll
        for (int ks = 0; ks < 4; ks++) {
            const int kc = 8 * ks + tid4;
            uint32_t a[2][4], bf[8][2];
#pragma unroll
            for (int mi = 0; mi < 2; mi++) {
                const int r = w * 32 + 16 * mi + g;
                a[mi][0] = Ps[r * HSTR + kc];
                a[mi][1] = Ps[(r + 8) * HSTR + kc];
                a[mi][2] = Ps[r * HSTR + kc + 4];
                a[mi][3] = Ps[(r + 8) * HSTR + kc + 4];
            }
            const uint32_t vk = vlbase + ks * 16 * (HSTR * 4);
#pragma unroll
            for (int ni = 0; ni < 8; ni++)
                ldsm_x2_trans(bf[ni][0], bf[ni][1], vk + ni * 16);
#pragma unroll
            for (int mi = 0; mi < 2; mi++)
#pragma unroll
                for (int ni = 0; ni < 8; ni++)
                    mma_f16(o[mi][ni], a[mi], bf[ni]);
        }
        __syncwarp();
    }

#pragma unroll
    for (int mi = 0; mi < 2; mi++) {
        const float inv0 = 1.0f / l_[mi][0];
        const float inv1 = 1.0f / l_[mi][1];
        const int r = qb * BQ + w * 32 + 16 * mi + g;
#pragma unroll
        for (int ni = 0; ni < 8; ni++) {
            const int col = h * HD + 2 * tid4 + 8 * ni;
            float2 v0 = make_float2(o[mi][ni][0] * inv0, o[mi][ni][1] * inv0);
            float2 v1 = make_float2(o[mi][ni][2] * inv1, o[mi][ni][3] * inv1);
            *(float2*)(ctx + ((size_t)b * N1V + r) * DIMV + col)     = v0;
            *(float2*)(ctx + ((size_t)b * N1V + r + 8) * DIMV + col) = v1;
        }
    }
}

// ---------------------------------------------------------------------------
__global__ __launch_bounds__(256) void gemv_wbo(
    const float* __restrict__ W, const float* __restrict__ bo,
    float* __restrict__ wbo)
{
    const int a = blockIdx.x * 8 + (threadIdx.x >> 5);
    const int lane = threadIdx.x & 31;
    float s = 0.f;
#pragma unroll
    for (int i = 0; i < 4; i++) {
        const int j = lane + 32 * i;
        float4 wv = ((const float4*)(W + (size_t)a * DIMV))[j];
        float4 bv = ((const float4*)bo)[j];
        s += wv.x * bv.x + wv.y * bv.y + wv.z * bv.z + wv.w * bv.w;
    }
#pragma unroll
    for (int off = 16; off; off >>= 1)
        s += __shfl_xor_sync(0xffffffffu, s, off);
    if (lane == 0) wbo[a] = s;
}

// ---------------------------------------------------------------------------
__global__ __launch_bounds__(128) void score_kernel(
    const float* __restrict__ ctx, const float* __restrict__ u,
    const float* __restrict__ g1, const float* __restrict__ wbo,
    const float* __restrict__ scale, float* __restrict__ out)
{
    const int row = blockIdx.x;
    const int t = threadIdx.x;
    const float4 a = ((const float4*)(ctx + (size_t)row * DIMV))[t];
    const float4 b = ((const float4*)(u   + (size_t)row * DIMV))[t];
    const float4 c = ((const float4*)(g1  + (size_t)row * DIMV))[t];
    const float4 d = ((const float4*)wbo)[t];
    float s = a.x * b.x + a.y * b.y + a.z * b.z + a.w * b.w
            + c.x * d.x + c.y * d.y + c.z * d.z + c.w * d.w;
#pragma unroll
    for (int off = 16; off; off >>= 1)
        s += __shfl_xor_sync(0xffffffffu, s, off);
    __shared__ float red[4];
    if ((t & 31) == 0) red[t >> 5] = s;
    __syncthreads();
    if (t == 0) {
        const float tot = red[0] + red[1] + red[2] + red[3];
        const float z = tot * scale[0];
        out[row] = fmaxf(z, 0.f) + log1pf(__expf(-fabsf(z)));
    }
}

// ---------------------------------------------------------------------------
extern "C" void kernel_launch(void* const* d_in, const int* in_sizes, int n_in,
                              void* d_out, int out_size)
{
    const float* g1    = (const float*)d_in[0];
    const float* g2    = (const float*)d_in[1];
    const float* Wq    = (const float*)d_in[2];
    const float* bq    = (const float*)d_in[3];
    const float* Wk    = (const float*)d_in[4];
    const float* bk    = (const float*)d_in[5];
    const float* Wv    = (const float*)d_in[6];
    const float* bv    = (const float*)d_in[7];
    const float* Wo    = (const float*)d_in[8];
    const float* bo    = (const float*)d_in[9];
    const float* Wb    = (const float*)d_in[10];
    const float* scale = (const float*)d_in[11];
    float* out = (float*)d_out;

    __half *Qp, *Kp, *Vp, *g1h, *g2h, *Wqh, *Wkh, *Wvh, *Wh, *WoTp, *Mthp;
    float *CTXp, *Up, *Mfp, *wbop;
    cudaGetSymbolAddress((void**)&Qp,   g_Q);
    cudaGetSymbolAddress((void**)&Kp,   g_K);
    cudaGetSymbolAddress((void**)&Vp,   g_V);
    cudaGetSymbolAddress((void**)&CTXp, g_CTX);
    cudaGetSymbolAddress((void**)&Up,   g_U);
    cudaGetSymbolAddress((void**)&g1h,  g_g1h);
    cudaGetSymbolAddress((void**)&g2h,  g_g2h);
    cudaGetSymbolAddress((void**)&Wqh,  g_Wqh);
    cudaGetSymbolAddress((void**)&Wkh,  g_Wkh);
    cudaGetSymbolAddress((void**)&Wvh,  g_Wvh);
    cudaGetSymbolAddress((void**)&Wh,   g_Wh);
    cudaGetSymbolAddress((void**)&WoTp, g_WoT);
    cudaGetSymbolAddress((void**)&Mfp,  g_Mf);
    cudaGetSymbolAddress((void**)&Mthp, g_Mth);
    cudaGetSymbolAddress((void**)&wbop, g_wbo);

    cudaFuncSetAttribute((const void*)gemm_h1, cudaFuncAttributeMaxDynamicSharedMemorySize, GEMMH_SMEM);
    cudaFuncSetAttribute((const void*)gemm_h2<true, false>, cudaFuncAttributeMaxDynamicSharedMemorySize, GEMMH_SMEM);
    cudaFuncSetAttribute((const void*)gemm_h2<true, true >, cudaFuncAttributeMaxDynamicSharedMemorySize, GEMMH_SMEM);
    cudaFuncSetAttribute((const void*)attn_tc, cudaFuncAttributeMaxDynamicSharedMemorySize, ATTN_SMEM);

    const int M = BATCH * N1V;                 // 8192

    // fp16 convert inputs + weights; Wo transposed-converted
    cvt2_k<<<dim3((M * DIMV) / 4 / 256, 2), 256>>>(g1, g2, g1h, g2h);
    cvt4_k<<<dim3(256, 4), 256>>>(Wq, Wk, Wv, Wb, Wqh, Wkh, Wvh, Wh);
    trans_f2h<<<dim3(16, 16), dim3(32, 8)>>>(Wo, WoTp);

    gemv_wbo<<<DIMV / 8, 256>>>(Wb, bo, wbop);

    // M[a][d] = sum_e W[a][e] * Wo[e][d]  ==  Wh @ (WoT)[d][e]^T   (TRANSB)
    gemm_h1<<<dim3(4, 4), 256, GEMMH_SMEM>>>(Wh, WoTp, Mfp, DIMV, DIMV, DIMV);
    trans_f2h<<<dim3(16, 16), dim3(32, 8)>>>(Mfp, Mthp);

    // Fused pairs sharing the A operand:
    //   (Q [fp16, pre-scaled 1/8], U [fp32]) from g1h
    //   (K [fp16], V [fp16]) from g2h
    dim3 gg2(8, M / 128);
    gemm_h2<true, false><<<gg2, 256, GEMMH_SMEM>>>(g1h, Wqh, bq, (void*)Qp, Mthp, nullptr, (void*)Up,
                                                   0.125f, 1.0f, M, DIMV, DIMV);
    gemm_h2<true, true ><<<gg2, 256, GEMMH_SMEM>>>(g2h, Wkh, bk, (void*)Kp, Wvh, bv, (void*)Vp,
                                                   1.0f, 1.0f, M, DIMV, DIMV);

    attn_tc<<<dim3(N1V / BQ, BATCH * NHEAD), 128, ATTN_SMEM>>>(Qp, Kp, Vp, CTXp);

    score_kernel<<<M, 128>>>(CTXp, Up, g1, wbop, scale, out);
}

// round 15
// speedup vs baseline: 1.9231x; 1.0320x over previous
#include <cuda_runtime.h>
#include <cuda_fp16.h>
#include <math.h>
#include <stdint.h>

#define BATCH 4
#define N1V 2048
#define N2V 2048
#define DIMV 512
#define NHEAD 8
#define HD 64

// Scratch (device globals: no allocation allowed in kernel_launch)
__device__ __align__(256) __half g_Q   [BATCH * N1V * DIMV];
__device__ __align__(256) __half g_K   [BATCH * N2V * DIMV];
__device__ __align__(256) __half g_V   [BATCH * N2V * DIMV];
__device__ __align__(256) float  g_CTX [BATCH * N1V * DIMV];
__device__ __align__(256) float  g_U   [BATCH * N1V * DIMV];
__device__ __align__(256) __half g_g1h [BATCH * N1V * DIMV];
__device__ __align__(256) __half g_g2h [BATCH * N2V * DIMV];
__device__ __align__(256) __half g_Wqh [DIMV * DIMV];
__device__ __align__(256) __half g_Wkh [DIMV * DIMV];
__device__ __align__(256) __half g_Wvh [DIMV * DIMV];
__device__ __align__(256) __half g_Wh  [DIMV * DIMV];    // W  (fp16)
__device__ __align__(256) __half g_WoT [DIMV * DIMV];    // Wo^T (fp16)
__device__ __align__(256) float  g_Mf  [4 * DIMV * DIMV];// W @ Wo split-K partials
__device__ __align__(256) __half g_Mth [DIMV * DIMV];    // (W @ Wo)^T (fp16)
__device__ __align__(256) float  g_wbo [DIMV];           // W @ bo

// ---------------------------------------------------------------------------
__device__ __forceinline__ uint32_t f2h2(float a, float b) {
    uint32_t u;
    asm("cvt.rn.f16x2.f32 %0, %1, %2;" : "=r"(u) : "f"(b), "f"(a));
    return u;
}

__device__ __forceinline__ void mma_f16(float* c, const uint32_t* a, const uint32_t* b) {
    asm volatile(
        "mma.sync.aligned.m16n8k16.row.col.f32.f16.f16.f32 "
        "{%0,%1,%2,%3}, {%4,%5,%6,%7}, {%8,%9}, {%0,%1,%2,%3};\n"
        : "+f"(c[0]), "+f"(c[1]), "+f"(c[2]), "+f"(c[3])
        : "r"(a[0]), "r"(a[1]), "r"(a[2]), "r"(a[3]), "r"(b[0]), "r"(b[1]));
}

__device__ __forceinline__ void ldsm_x2_trans(uint32_t& b0, uint32_t& b1, uint32_t addr) {
    asm volatile("ldmatrix.sync.aligned.m8n8.x2.trans.shared.b16 {%0,%1}, [%2];"
                 : "=r"(b0), "=r"(b1) : "r"(addr));
}

__device__ __forceinline__ void cp16(uint32_t dst_smem, const void* src) {
    asm volatile("cp.async.cg.shared.global [%0], [%1], 16;\n" :: "r"(dst_smem), "l"(src));
}
#define CP_COMMIT() asm volatile("cp.async.commit_group;\n" ::: "memory")
#define CP_WAIT(n)  asm volatile("cp.async.wait_group %0;\n" :: "n"(n) : "memory")

__device__ __forceinline__ uint32_t smaddr(const void* p) {
    return (uint32_t)__cvta_generic_to_shared(p);
}

// ---------------------------------------------------------------------------
// fp16 convert: g1, g2
// ---------------------------------------------------------------------------
__global__ __launch_bounds__(256) void cvt2_k(
    const float* __restrict__ a0, const float* __restrict__ a1,
    __half* __restrict__ o0, __half* __restrict__ o1)
{
    const float* in = blockIdx.y ? a1 : a0;
    __half* out     = blockIdx.y ? o1 : o0;
    const int i = blockIdx.x * 256 + threadIdx.x;
    float4 v = ((const float4*)in)[i];
    uint2 r;
    r.x = f2h2(v.x, v.y);
    r.y = f2h2(v.z, v.w);
    ((uint2*)out)[i] = r;
}

// fp16 convert for 4 weight matrices (y=0..3) + gemv wbo (y=4, x<64)
__global__ __launch_bounds__(256) void cvt4_gemv_k(
    const float* __restrict__ w0, const float* __restrict__ w1,
    const float* __restrict__ w2, const float* __restrict__ w3,
    __half* __restrict__ o0, __half* __restrict__ o1,
    __half* __restrict__ o2, __half* __restrict__ o3,
    const float* __restrict__ bo, float* __restrict__ wbo)
{
    if (blockIdx.y == 4) {
        if (blockIdx.x >= 64) return;
        const int a = blockIdx.x * 8 + (threadIdx.x >> 5);
        const int lane = threadIdx.x & 31;
        float s = 0.f;
#pragma unroll
        for (int i = 0; i < 4; i++) {
            const int j = lane + 32 * i;
            float4 wv = ((const float4*)(w3 + (size_t)a * DIMV))[j];
            float4 bv = ((const float4*)bo)[j];
            s += wv.x * bv.x + wv.y * bv.y + wv.z * bv.z + wv.w * bv.w;
        }
#pragma unroll
        for (int off = 16; off; off >>= 1)
            s += __shfl_xor_sync(0xffffffffu, s, off);
        if (lane == 0) wbo[a] = s;
        return;
    }
    const float* in;
    __half* out;
    switch (blockIdx.y) {
        case 0: in = w0; out = o0; break;
        case 1: in = w1; out = o1; break;
        case 2: in = w2; out = o2; break;
        default: in = w3; out = o3; break;
    }
    const int i = blockIdx.x * 256 + threadIdx.x;
    float4 v = ((const float4*)in)[i];
    uint2 r;
    r.x = f2h2(v.x, v.y);
    r.y = f2h2(v.z, v.w);
    ((uint2*)out)[i] = r;
}

// 512x512 transpose with fp32 -> fp16 convert
__global__ __launch_bounds__(256) void trans_f2h(
    const float* __restrict__ in, __half* __restrict__ out)
{
    __shared__ float tile[32][33];
    const int tx = threadIdx.x, ty = threadIdx.y;
    const int x = blockIdx.x * 32 + tx;
    const int y0 = blockIdx.y * 32 + ty;
#pragma unroll
    for (int j = 0; j < 4; j++)
        tile[ty + 8 * j][tx] = in[(size_t)(y0 + 8 * j) * DIMV + x];
    __syncthreads();
    const int x2 = blockIdx.y * 32 + tx;
    const int y2 = blockIdx.x * 32 + ty;
#pragma unroll
    for (int j = 0; j < 4; j++)
        out[(size_t)(y2 + 8 * j) * DIMV + x2] = __float2half_rn(tile[tx][ty + 8 * j]);
}

// 512x512: sum 4 split-K partials, transpose, convert to fp16
__global__ __launch_bounds__(256) void trans_sum4_f2h(
    const float* __restrict__ in, __half* __restrict__ out)
{
    __shared__ float tile[32][33];
    const int tx = threadIdx.x, ty = threadIdx.y;
    const int x = blockIdx.x * 32 + tx;
    const int y0 = blockIdx.y * 32 + ty;
#pragma unroll
    for (int j = 0; j < 4; j++) {
        const size_t idx = (size_t)(y0 + 8 * j) * DIMV + x;
        tile[ty + 8 * j][tx] = in[idx] + in[idx + DIMV * DIMV]
                             + in[idx + 2 * DIMV * DIMV] + in[idx + 3 * DIMV * DIMV];
    }
    __syncthreads();
    const int x2 = blockIdx.y * 32 + tx;
    const int y2 = blockIdx.x * 32 + ty;
#pragma unroll
    for (int j = 0; j < 4; j++)
        out[(size_t)(y2 + 8 * j) * DIMV + x2] = __float2half_rn(tile[tx][ty + 8 * j]);
}

// ---------------------------------------------------------------------------
// mma.sync fp16 GEMM machinery
// ---------------------------------------------------------------------------
#define HS 20
#define HSTG (128 * HS)
#define GEMMH_SMEM (4 * HSTG * 4)

__device__ __forceinline__ void h_prefetch(
    uint32_t* As, uint32_t* Bs, const __half* A, const __half* Wt,
    int m0, int n0, int k0, int K, int t)
{
#pragma unroll
    for (int j = 0; j < 2; j++) {
        const int idx = t + 256 * j;
        const int row = idx >> 2, c = idx & 3;
        cp16(smaddr(&As[row * HS + 4 * c]),
             A + (size_t)(m0 + row) * K + k0 + 8 * c);
    }
#pragma unroll
    for (int j = 0; j < 2; j++) {
        const int idx = t + 256 * j;
        const int row = idx >> 2, c = idx & 3;
        cp16(smaddr(&Bs[row * HS + 4 * c]),
             Wt + (size_t)(n0 + row) * K + k0 + 8 * c);
    }
}

__device__ __forceinline__ void gemm_h_body(
    uint32_t* sm, const __half* A, const __half* Wt,
    int m0, int n0, int kbase, int kIters, int K, int t, float acc[4][4][4])
{
    const int lane = t & 31;
    const int w    = t >> 5;
    const int g    = lane >> 2;
    const int tid4 = lane & 3;
    const int warpM = (w >> 2) * 64;
    const int warpN = (w & 3) * 32;

    h_prefetch(sm, sm + 2 * HSTG, A, Wt, m0, n0, kbase, K, t);
    CP_COMMIT();

    int st = 0;
    for (int it = 0; it < kIters; it++) {
        if (it + 1 < kIters) {
            h_prefetch(sm + (st ^ 1) * HSTG, sm + (2 + (st ^ 1)) * HSTG,
                       A, Wt, m0, n0, kbase + (it + 1) * 32, K, t);
            CP_COMMIT();
            CP_WAIT(1);
        } else {
            CP_WAIT(0);
        }
        __syncthreads();

        uint32_t* As = sm + st * HSTG;
        uint32_t* Bs = sm + (2 + st) * HSTG;
#pragma unroll
        for (int ks = 0; ks < 2; ks++) {
            uint32_t a[4][4], b[4][2];
            const int kc = 8 * ks + tid4;
#pragma unroll
            for (int mi = 0; mi < 4; mi++) {
                const int r = warpM + 16 * mi + g;
                a[mi][0] = As[r * HS + kc];
                a[mi][1] = As[(r + 8) * HS + kc];
                a[mi][2] = As[r * HS + kc + 4];
                a[mi][3] = As[(r + 8) * HS + kc + 4];
            }
#pragma unroll
            for (int ni = 0; ni < 4; ni++) {
                const int n = warpN + 8 * ni + g;
                b[ni][0] = Bs[n * HS + kc];
                b[ni][1] = Bs[n * HS + kc + 4];
            }
#pragma unroll
            for (int mi = 0; mi < 4; mi++)
#pragma unroll
                for (int ni = 0; ni < 4; ni++)
                    mma_f16(acc[mi][ni], a[mi], b[ni]);
        }
        __syncthreads();
        st ^= 1;
    }
}

// Split-K GEMM for M = W @ WoT^T: grid (4,4,4), z-slab fp32 output
__global__ __launch_bounds__(256, 2) void gemm_h1_splitk(
    const __half* __restrict__ A, const __half* __restrict__ Wt,
    float* __restrict__ C, int N, int K)
{
    extern __shared__ uint32_t sm[];
    const int t  = threadIdx.x;
    const int m0 = blockIdx.y * 128, n0 = blockIdx.x * 128;
    const int z  = blockIdx.z;
    const int lane = t & 31, w = t >> 5;
    const int g = lane >> 2, tid4 = lane & 3;
    const int warpM = (w >> 2) * 64, warpN = (w & 3) * 32;

    float acc[4][4][4];
#pragma unroll
    for (int mi = 0; mi < 4; mi++)
#pragma unroll
        for (int ni = 0; ni < 4; ni++)
#pragma unroll
            for (int c = 0; c < 4; c++) acc[mi][ni][c] = 0.f;

    gemm_h_body(sm, A, Wt, m0, n0, z * 128, 4, K, t, acc);

    float* Cz = C + (size_t)z * DIMV * DIMV;
#pragma unroll
    for (int mi = 0; mi < 4; mi++) {
#pragma unroll
        for (int ni = 0; ni < 4; ni++) {
            const int row = m0 + warpM + 16 * mi + g;
            const int col = n0 + warpN + 8 * ni + 2 * tid4;
            *(float2*)(Cz + (size_t)row * N + col)       = make_float2(acc[mi][ni][0], acc[mi][ni][1]);
            *(float2*)(Cz + (size_t)(row + 8) * N + col) = make_float2(acc[mi][ni][2], acc[mi][ni][3]);
        }
    }
}

// Fused dual-output fp16 GEMM: grid.x = 8; blockIdx.x<4 -> output 0 else 1.
template<bool HALF0, bool HALF1>
__global__ __launch_bounds__(256, 2) void gemm_h2(
    const __half* __restrict__ A,
    const __half* __restrict__ W0, const float* __restrict__ b0, void* __restrict__ C0,
    const __half* __restrict__ W1, const float* __restrict__ b1, void* __restrict__ C1,
    float scale0, float scale1,
    int M, int N, int K)
{
    extern __shared__ uint32_t sm[];
    const int t = threadIdx.x;
    const bool second = blockIdx.x >= 4;
    const __half* Wt  = second ? W1 : W0;
    const float* bias = second ? b1 : b0;
    void* C           = second ? C1 : C0;
    const float scl   = second ? scale1 : scale0;
    const bool doHalf = second ? HALF1 : HALF0;
    const int m0 = blockIdx.y * 128;
    const int n0 = (blockIdx.x & 3) * 128;

    float acc[4][4][4];
#pragma unroll
    for (int mi = 0; mi < 4; mi++)
#pragma unroll
        for (int ni = 0; ni < 4; ni++)
#pragma unroll
            for (int c = 0; c < 4; c++) acc[mi][ni][c] = 0.f;

    gemm_h_body(sm, A, Wt, m0, n0, 0, K / 32, K, t, acc);

    const int lane = t & 31, w = t >> 5;
    const int g = lane >> 2, tid4 = lane & 3;
    const int warpM = (w >> 2) * 64, warpN = (w & 3) * 32;
    const bool hb = (bias != nullptr);
#pragma unroll
    for (int mi = 0; mi < 4; mi++) {
#pragma unroll
        for (int ni = 0; ni < 4; ni++) {
            const int row = m0 + warpM + 16 * mi + g;
            const int col = n0 + warpN + 8 * ni + 2 * tid4;
            float bx = 0.f, by = 0.f;
            if (hb) { bx = bias[col]; by = bias[col + 1]; }
            float v00 = acc[mi][ni][0] + bx, v01 = acc[mi][ni][1] + by;
            float v10 = acc[mi][ni][2] + bx, v11 = acc[mi][ni][3] + by;
            if (doHalf) {
                __half* Ch = (__half*)C;
                *(uint32_t*)(Ch + (size_t)row * N + col)       = f2h2(v00 * scl, v01 * scl);
                *(uint32_t*)(Ch + (size_t)(row + 8) * N + col) = f2h2(v10 * scl, v11 * scl);
            } else {
                float* Cf = (float*)C;
                *(float2*)(Cf + (size_t)row * N + col)       = make_float2(v00, v01);
                *(float2*)(Cf + (size_t)(row + 8) * N + col) = make_float2(v10, v11);
            }
        }
    }
}

// ---------------------------------------------------------------------------
// Flash attention, fp16 m16n8k16 TC (round-12/13 proven version).
// ---------------------------------------------------------------------------
#define BQ 128
#define BKV 64
#define HSTR 36
#define ATTN_SMEM ((BQ + BKV + BKV + BQ) * HSTR * 4)

__global__ __launch_bounds__(128) void attn_tc(
    const __half* __restrict__ Q, const __half* __restrict__ K,
    const __half* __restrict__ V, float* __restrict__ ctx)
{
    extern __shared__ uint32_t smA[];
    uint32_t* Qs = smA;
    uint32_t* Ks = Qs + BQ * HSTR;
    uint32_t* Vs = Ks + BKV * HSTR;
    uint32_t* Ps = Vs + BKV * HSTR;

    const int qb = blockIdx.x;
    const int bh = blockIdx.y;
    const int b  = bh >> 3, h = bh & 7;
    const int t  = threadIdx.x;
    const int w  = t >> 5, lane = t & 31;
    const int g  = lane >> 2, tid4 = lane & 3;

    const __half* Qb = Q + ((size_t)b * N1V + qb * BQ) * DIMV + h * HD;
    const __half* Kb = K + (size_t)b * N2V * DIMV + h * HD;
    const __half* Vb = V + (size_t)b * N2V * DIMV + h * HD;

#pragma unroll
    for (int j = 0; j < 8; j++) {
        const int idx = t + 128 * j;
        const int row = idx >> 3, c = idx & 7;
        *(float4*)&Qs[row * HSTR + 4 * c] = *(const float4*)(Qb + (size_t)row * DIMV + 8 * c);
    }

    const uint32_t vlbase = smaddr(Vs) + (lane & 15) * (HSTR * 4);

    float m_[2][2], l_[2][2], o[2][8][4];
#pragma unroll
    for (int mi = 0; mi < 2; mi++) {
        m_[mi][0] = -1e30f; m_[mi][1] = -1e30f;
        l_[mi][0] = 0.f;    l_[mi][1] = 0.f;
#pragma unroll
        for (int ni = 0; ni < 8; ni++)
#pragma unroll
            for (int c = 0; c < 4; c++) o[mi][ni][c] = 0.f;
    }

    for (int kt = 0; kt < N2V / BKV; kt++) {
        __syncthreads();
#pragma unroll
        for (int j = 0; j < 4; j++) {
            const int idx = t + 128 * j;
            const int row = idx >> 3, c = idx & 7;
            *(float4*)&Ks[row * HSTR + 4 * c] =
                *(const float4*)(Kb + (size_t)(kt * BKV + row) * DIMV + 8 * c);
            *(float4*)&Vs[row * HSTR + 4 * c] =
                *(const float4*)(Vb + (size_t)(kt * BKV + row) * DIMV + 8 * c);
        }
        __syncthreads();

        float s[2][8][4];
#pragma unroll
        for (int mi = 0; mi < 2; mi++)
#pragma unroll
            for (int ni = 0; ni < 8; ni++)
#pragma unroll
                for (int c = 0; c < 4; c++) s[mi][ni][c] = 0.f;

#pragma unroll
        for (int ks = 0; ks < 4; ks++) {
            const int kc = 8 * ks + tid4;
            uint32_t a[2][4], bf[8][2];
#pragma unroll
            for (int mi = 0; mi < 2; mi++) {
                const int r = w * 32 + 16 * mi + g;
                a[mi][0] = Qs[r * HSTR + kc];
                a[mi][1] = Qs[(r + 8) * HSTR + kc];
                a[mi][2] = Qs[r * HSTR + kc + 4];
                a[mi][3] = Qs[(r + 8) * HSTR + kc + 4];
            }
#pragma unroll
            for (int ni = 0; ni < 8; ni++) {
                const int n = 8 * ni + g;
                bf[ni][0] = Ks[n * HSTR + kc];
                bf[ni][1] = Ks[n * HSTR + kc + 4];
            }
#pragma unroll
            for (int mi = 0; mi < 2; mi++)
#pragma unroll
                for (int ni = 0; ni < 8; ni++)
                    mma_f16(s[mi][ni], a[mi], bf[ni]);
        }

#pragma unroll
        for (int mi = 0; mi < 2; mi++) {
            float mx0 = -1e30f, mx1 = -1e30f;
#pragma unroll
            for (int ni = 0; ni < 8; ni++) {
                mx0 = fmaxf(mx0, fmaxf(s[mi][ni][0], s[mi][ni][1]));
                mx1 = fmaxf(mx1, fmaxf(s[mi][ni][2], s[mi][ni][3]));
            }
            mx0 = fmaxf(mx0, __shfl_xor_sync(0xffffffffu, mx0, 1));
            mx0 = fmaxf(mx0, __shfl_xor_sync(0xffffffffu, mx0, 2));
            mx1 = fmaxf(mx1, __shfl_xor_sync(0xffffffffu, mx1, 1));
            mx1 = fmaxf(mx1, __shfl_xor_sync(0xffffffffu, mx1, 2));
            const float mn0 = fmaxf(m_[mi][0], mx0);
            const float mn1 = fmaxf(m_[mi][1], mx1);
            float sum0 = 0.f, sum1 = 0.f;
#pragma unroll
            for (int ni = 0; ni < 8; ni++) {
                s[mi][ni][0] = __expf(s[mi][ni][0] - mn0);
                s[mi][ni][1] = __expf(s[mi][ni][1] - mn0);
                s[mi][ni][2] = __expf(s[mi][ni][2] - mn1);
                s[mi][ni][3] = __expf(s[mi][ni][3] - mn1);
                sum0 += s[mi][ni][0] + s[mi][ni][1];
                sum1 += s[mi][ni][2] + s[mi][ni][3];
            }
            sum0 += __shfl_xor_sync(0xffffffffu, sum0, 1);
            sum0 += __shfl_xor_sync(0xffffffffu, sum0, 2);
            sum1 += __shfl_xor_sync(0xffffffffu, sum1, 1);
            sum1 += __shfl_xor_sync(0xffffffffu, sum1, 2);
            const float al0 = __expf(m_[mi][0] - mn0);
            const float al1 = __expf(m_[mi][1] - mn1);
            m_[mi][0] = mn0; m_[mi][1] = mn1;
            l_[mi][0] = l_[mi][0] * al0 + sum0;
            l_[mi][1] = l_[mi][1] * al1 + sum1;
#pragma unroll
            for (int ni = 0; ni < 8; ni++) {
                o[mi][ni][0] *= al0; o[mi][ni][1] *= al0;
                o[mi][ni][2] *= al1; o[mi][ni][3] *= al1;
            }
            const int r = w * 32 + 16 * mi + g;
#pragma unroll
            for (int ni = 0; ni < 8; ni++) {
                Ps[r * HSTR + 4 * ni + tid4]       = f2h2(s[mi][ni][0], s[mi][ni][1]);
                Ps[(r + 8) * HSTR + 4 * ni + tid4] = f2h2(s[mi][ni][2], s[mi][ni][3]);
            }
        }
        __syncwarp();

#pragma unroll
        for (int ks = 0; ks < 4; ks++) {
            const int kc = 8 * ks + tid4;
            uint32_t a[2][4], bf[8][2];
#pragma unroll
            for (int mi = 0; mi < 2; mi++) {
                const int r = w * 32 + 16 * mi + g;
                a[mi][0] = Ps[r * HSTR + kc];
                a[mi][1] = Ps[(r + 8) * HSTR + kc];
                a[mi][2] = Ps[r * HSTR + kc + 4];
                a[mi][3] = Ps[(r + 8) * HSTR + kc + 4];
            }
            const uint32_t vk = vlbase + ks * 16 * (HSTR * 4);
#pragma unroll
            for (int ni = 0; ni < 8; ni++)
                ldsm_x2_trans(bf[ni][0], bf[ni][1], vk + ni * 16);
#pragma unroll
            for (int mi = 0; mi < 2; mi++)
#pragma unroll
                for (int ni = 0; ni < 8; ni++)
                    mma_f16(o[mi][ni], a[mi], bf[ni]);
        }
        __syncwarp();
    }

#pragma unroll
    for (int mi = 0; mi < 2; mi++) {
        const float inv0 = 1.0f / l_[mi][0];
        const float inv1 = 1.0f / l_[mi][1];
        const int r = qb * BQ + w * 32 + 16 * mi + g;
#pragma unroll
        for (int ni = 0; ni < 8; ni++) {
            const int col = h * HD + 2 * tid4 + 8 * ni;
            float2 v0 = make_float2(o[mi][ni][0] * inv0, o[mi][ni][1] * inv0);
            float2 v1 = make_float2(o[mi][ni][2] * inv1, o[mi][ni][3] * inv1);
            *(float2*)(ctx + ((size_t)b * N1V + r) * DIMV + col)     = v0;
            *(float2*)(ctx + ((size_t)b * N1V + r + 8) * DIMV + col) = v1;
        }
    }
}

// ---------------------------------------------------------------------------
__global__ __launch_bounds__(128) void score_kernel(
    const float* __restrict__ ctx, const float* __restrict__ u,
    const float* __restrict__ g1, const float* __restrict__ wbo,
    const float* __restrict__ scale, float* __restrict__ out)
{
    const int row = blockIdx.x;
    const int t = threadIdx.x;
    const float4 a = ((const float4*)(ctx + (size_t)row * DIMV))[t];
    const float4 b = ((const float4*)(u   + (size_t)row * DIMV))[t];
    const float4 c = ((const float4*)(g1  + (size_t)row * DIMV))[t];
    const float4 d = ((const float4*)wbo)[t];
    float s = a.x * b.x + a.y * b.y + a.z * b.z + a.w * b.w
            + c.x * d.x + c.y * d.y + c.z * d.z + c.w * d.w;
#pragma unroll
    for (int off = 16; off; off >>= 1)
        s += __shfl_xor_sync(0xffffffffu, s, off);
    __shared__ float red[4];
    if ((t & 31) == 0) red[t >> 5] = s;
    __syncthreads();
    if (t == 0) {
        const float tot = red[0] + red[1] + red[2] + red[3];
        const float z = tot * scale[0];
        out[row] = fmaxf(z, 0.f) + log1pf(__expf(-fabsf(z)));
    }
}

// ---------------------------------------------------------------------------
extern "C" void kernel_launch(void* const* d_in, const int* in_sizes, int n_in,
                              void* d_out, int out_size)
{
    const float* g1    = (const float*)d_in[0];
    const float* g2    = (const float*)d_in[1];
    const float* Wq    = (const float*)d_in[2];
    const float* bq    = (const float*)d_in[3];
    const float* Wk    = (const float*)d_in[4];
    const float* bk    = (const float*)d_in[5];
    const float* Wv    = (const float*)d_in[6];
    const float* bv    = (const float*)d_in[7];
    const float* Wo    = (const float*)d_in[8];
    const float* bo    = (const float*)d_in[9];
    const float* Wb    = (const float*)d_in[10];
    const float* scale = (const float*)d_in[11];
    float* out = (float*)d_out;

    __half *Qp, *Kp, *Vp, *g1h, *g2h, *Wqh, *Wkh, *Wvh, *Wh, *WoTp, *Mthp;
    float *CTXp, *Up, *Mfp, *wbop;
    cudaGetSymbolAddress((void**)&Qp,   g_Q);
    cudaGetSymbolAddress((void**)&Kp,   g_K);
    cudaGetSymbolAddress((void**)&Vp,   g_V);
    cudaGetSymbolAddress((void**)&CTXp, g_CTX);
    cudaGetSymbolAddress((void**)&Up,   g_U);
    cudaGetSymbolAddress((void**)&g1h,  g_g1h);
    cudaGetSymbolAddress((void**)&g2h,  g_g2h);
    cudaGetSymbolAddress((void**)&Wqh,  g_Wqh);
    cudaGetSymbolAddress((void**)&Wkh,  g_Wkh);
    cudaGetSymbolAddress((void**)&Wvh,  g_Wvh);
    cudaGetSymbolAddress((void**)&Wh,   g_Wh);
    cudaGetSymbolAddress((void**)&WoTp, g_WoT);
    cudaGetSymbolAddress((void**)&Mfp,  g_Mf);
    cudaGetSymbolAddress((void**)&Mthp, g_Mth);
    cudaGetSymbolAddress((void**)&wbop, g_wbo);

    cudaFuncSetAttribute((const void*)gemm_h1_splitk, cudaFuncAttributeMaxDynamicSharedMemorySize, GEMMH_SMEM);
    cudaFuncSetAttribute((const void*)gemm_h2<true, false>, cudaFuncAttributeMaxDynamicSharedMemorySize, GEMMH_SMEM);
    cudaFuncSetAttribute((const void*)gemm_h2<true, true >, cudaFuncAttributeMaxDynamicSharedMemorySize, GEMMH_SMEM);
    cudaFuncSetAttribute((const void*)attn_tc, cudaFuncAttributeMaxDynamicSharedMemorySize, ATTN_SMEM);

    const int M = BATCH * N1V;                 // 8192

    cvt2_k<<<dim3((M * DIMV) / 4 / 256, 2), 256>>>(g1, g2, g1h, g2h);
    cvt4_gemv_k<<<dim3(256, 5), 256>>>(Wq, Wk, Wv, Wb, Wqh, Wkh, Wvh, Wh, bo, wbop);
    trans_f2h<<<dim3(16, 16), dim3(32, 8)>>>(Wo, WoTp);

    // M = W @ Wo via split-K=4 mma.sync, partials summed in the transpose
    gemm_h1_splitk<<<dim3(4, 4, 4), 256, GEMMH_SMEM>>>(Wh, WoTp, Mfp, DIMV, DIMV);
    trans_sum4_f2h<<<dim3(16, 16), dim3(32, 8)>>>(Mfp, Mthp);

    // Fused pairs sharing the A operand:
    //   (Q [fp16, pre-scaled 1/8], U [fp32]) from g1h
    //   (K [fp16], V [fp16]) from g2h
    dim3 gg2(8, M / 128);
    gemm_h2<true, false><<<gg2, 256, GEMMH_SMEM>>>(g1h, Wqh, bq, (void*)Qp, Mthp, nullptr, (void*)Up,
                                                   0.125f, 1.0f, M, DIMV, DIMV);
    gemm_h2<true, true ><<<gg2, 256, GEMMH_SMEM>>>(g2h, Wkh, bk, (void*)Kp, Wvh, bv, (void*)Vp,
                                                   1.0f, 1.0f, M, DIMV, DIMV);

    attn_tc<<<dim3(N1V / BQ, BATCH * NHEAD), 128, ATTN_SMEM>>>(Qp, Kp, Vp, CTXp);

    score_kernel<<<M, 128>>>(CTXp, Up, g1, wbop, scale, out);
}

// round 16
// speedup vs baseline: 2.0181x; 1.0494x over previous
#include <cuda_runtime.h>
#include <cuda_fp16.h>
#include <math.h>
#include <stdint.h>

#define BATCH 4
#define N1V 2048
#define N2V 2048
#define DIMV 512
#define NHEAD 8
#define HD 64

// Scratch (device globals: no allocation allowed in kernel_launch)
__device__ __align__(256) __half g_Q   [BATCH * N1V * DIMV];
__device__ __align__(256) __half g_K   [BATCH * N2V * DIMV];
__device__ __align__(256) __half g_V   [BATCH * N2V * DIMV];
__device__ __align__(256) float  g_CTX [BATCH * N1V * DIMV];
__device__ __align__(256) float  g_U   [BATCH * N1V * DIMV];
__device__ __align__(256) __half g_g1h [BATCH * N1V * DIMV];
__device__ __align__(256) __half g_g2h [BATCH * N2V * DIMV];
__device__ __align__(256) __half g_Wqh [DIMV * DIMV];
__device__ __align__(256) __half g_Wkh [DIMV * DIMV];
__device__ __align__(256) __half g_Wvh [DIMV * DIMV];
__device__ __align__(256) __half g_Wh  [DIMV * DIMV];    // W  (fp16)
__device__ __align__(256) __half g_WoT [DIMV * DIMV];    // Wo^T (fp16)
__device__ __align__(256) float  g_Mf  [4 * DIMV * DIMV];// W @ Wo split-K partials
__device__ __align__(256) __half g_Mth [DIMV * DIMV];    // (W @ Wo)^T (fp16)
__device__ __align__(256) float  g_wbo [DIMV];           // W @ bo

// ---------------------------------------------------------------------------
__device__ __forceinline__ uint32_t f2h2(float a, float b) {
    uint32_t u;
    asm("cvt.rn.f16x2.f32 %0, %1, %2;" : "=r"(u) : "f"(b), "f"(a));
    return u;
}

__device__ __forceinline__ float ex2f(float x) {
    float r;
    asm("ex2.approx.f32 %0, %1;" : "=f"(r) : "f"(x));
    return r;
}

__device__ __forceinline__ void mma_f16(float* c, const uint32_t* a, const uint32_t* b) {
    asm volatile(
        "mma.sync.aligned.m16n8k16.row.col.f32.f16.f16.f32 "
        "{%0,%1,%2,%3}, {%4,%5,%6,%7}, {%8,%9}, {%0,%1,%2,%3};\n"
        : "+f"(c[0]), "+f"(c[1]), "+f"(c[2]), "+f"(c[3])
        : "r"(a[0]), "r"(a[1]), "r"(a[2]), "r"(a[3]), "r"(b[0]), "r"(b[1]));
}

__device__ __forceinline__ void ldsm_x2_trans(uint32_t& b0, uint32_t& b1, uint32_t addr) {
    asm volatile("ldmatrix.sync.aligned.m8n8.x2.trans.shared.b16 {%0,%1}, [%2];"
                 : "=r"(b0), "=r"(b1) : "r"(addr));
}

__device__ __forceinline__ void ldsm_x4(uint32_t& r0, uint32_t& r1, uint32_t& r2, uint32_t& r3,
                                        uint32_t addr) {
    asm volatile("ldmatrix.sync.aligned.m8n8.x4.shared.b16 {%0,%1,%2,%3}, [%4];"
                 : "=r"(r0), "=r"(r1), "=r"(r2), "=r"(r3) : "r"(addr));
}

__device__ __forceinline__ void cp16(uint32_t dst_smem, const void* src) {
    asm volatile("cp.async.cg.shared.global [%0], [%1], 16;\n" :: "r"(dst_smem), "l"(src));
}
#define CP_COMMIT() asm volatile("cp.async.commit_group;\n" ::: "memory")
#define CP_WAIT(n)  asm volatile("cp.async.wait_group %0;\n" :: "n"(n) : "memory")

__device__ __forceinline__ uint32_t smaddr(const void* p) {
    return (uint32_t)__cvta_generic_to_shared(p);
}

// ---------------------------------------------------------------------------
// fp16 convert: g1, g2
// ---------------------------------------------------------------------------
__global__ __launch_bounds__(256) void cvt2_k(
    const float* __restrict__ a0, const float* __restrict__ a1,
    __half* __restrict__ o0, __half* __restrict__ o1)
{
    const float* in = blockIdx.y ? a1 : a0;
    __half* out     = blockIdx.y ? o1 : o0;
    const int i = blockIdx.x * 256 + threadIdx.x;
    float4 v = ((const float4*)in)[i];
    uint2 r;
    r.x = f2h2(v.x, v.y);
    r.y = f2h2(v.z, v.w);
    ((uint2*)out)[i] = r;
}

// fp16 convert for 4 weight matrices (y=0..3) + gemv wbo (y=4, x<64)
__global__ __launch_bounds__(256) void cvt4_gemv_k(
    const float* __restrict__ w0, const float* __restrict__ w1,
    const float* __restrict__ w2, const float* __restrict__ w3,
    __half* __restrict__ o0, __half* __restrict__ o1,
    __half* __restrict__ o2, __half* __restrict__ o3,
    const float* __restrict__ bo, float* __restrict__ wbo)
{
    if (blockIdx.y == 4) {
        if (blockIdx.x >= 64) return;
        const int a = blockIdx.x * 8 + (threadIdx.x >> 5);
        const int lane = threadIdx.x & 31;
        float s = 0.f;
#pragma unroll
        for (int i = 0; i < 4; i++) {
            const int j = lane + 32 * i;
            float4 wv = ((const float4*)(w3 + (size_t)a * DIMV))[j];
            float4 bv = ((const float4*)bo)[j];
            s += wv.x * bv.x + wv.y * bv.y + wv.z * bv.z + wv.w * bv.w;
        }
#pragma unroll
        for (int off = 16; off; off >>= 1)
            s += __shfl_xor_sync(0xffffffffu, s, off);
        if (lane == 0) wbo[a] = s;
        return;
    }
    const float* in;
    __half* out;
    switch (blockIdx.y) {
        case 0: in = w0; out = o0; break;
        case 1: in = w1; out = o1; break;
        case 2: in = w2; out = o2; break;
        default: in = w3; out = o3; break;
    }
    const int i = blockIdx.x * 256 + threadIdx.x;
    float4 v = ((const float4*)in)[i];
    uint2 r;
    r.x = f2h2(v.x, v.y);
    r.y = f2h2(v.z, v.w);
    ((uint2*)out)[i] = r;
}

// 512x512 transpose with fp32 -> fp16 convert
__global__ __launch_bounds__(256) void trans_f2h(
    const float* __restrict__ in, __half* __restrict__ out)
{
    __shared__ float tile[32][33];
    const int tx = threadIdx.x, ty = threadIdx.y;
    const int x = blockIdx.x * 32 + tx;
    const int y0 = blockIdx.y * 32 + ty;
#pragma unroll
    for (int j = 0; j < 4; j++)
        tile[ty + 8 * j][tx] = in[(size_t)(y0 + 8 * j) * DIMV + x];
    __syncthreads();
    const int x2 = blockIdx.y * 32 + tx;
    const int y2 = blockIdx.x * 32 + ty;
#pragma unroll
    for (int j = 0; j < 4; j++)
        out[(size_t)(y2 + 8 * j) * DIMV + x2] = __float2half_rn(tile[tx][ty + 8 * j]);
}

// 512x512: sum 4 split-K partials, transpose, convert to fp16
__global__ __launch_bounds__(256) void trans_sum4_f2h(
    const float* __restrict__ in, __half* __restrict__ out)
{
    __shared__ float tile[32][33];
    const int tx = threadIdx.x, ty = threadIdx.y;
    const int x = blockIdx.x * 32 + tx;
    const int y0 = blockIdx.y * 32 + ty;
#pragma unroll
    for (int j = 0; j < 4; j++) {
        const size_t idx = (size_t)(y0 + 8 * j) * DIMV + x;
        tile[ty + 8 * j][tx] = in[idx] + in[idx + DIMV * DIMV]
                             + in[idx + 2 * DIMV * DIMV] + in[idx + 3 * DIMV * DIMV];
    }
    __syncthreads();
    const int x2 = blockIdx.y * 32 + tx;
    const int y2 = blockIdx.x * 32 + ty;
#pragma unroll
    for (int j = 0; j < 4; j++)
        out[(size_t)(y2 + 8 * j) * DIMV + x2] = __float2half_rn(tile[tx][ty + 8 * j]);
}

// ---------------------------------------------------------------------------
// mma.sync fp16 GEMM machinery
// ---------------------------------------------------------------------------
#define HS 20
#define HSTG (128 * HS)
#define GEMMH_SMEM (4 * HSTG * 4)

__device__ __forceinline__ void h_prefetch(
    uint32_t* As, uint32_t* Bs, const __half* A, const __half* Wt,
    int m0, int n0, int k0, int K, int t)
{
#pragma unroll
    for (int j = 0; j < 2; j++) {
        const int idx = t + 256 * j;
        const int row = idx >> 2, c = idx & 3;
        cp16(smaddr(&As[row * HS + 4 * c]),
             A + (size_t)(m0 + row) * K + k0 + 8 * c);
    }
#pragma unroll
    for (int j = 0; j < 2; j++) {
        const int idx = t + 256 * j;
        const int row = idx >> 2, c = idx & 3;
        cp16(smaddr(&Bs[row * HS + 4 * c]),
             Wt + (size_t)(n0 + row) * K + k0 + 8 * c);
    }
}

__device__ __forceinline__ void gemm_h_body(
    uint32_t* sm, const __half* A, const __half* Wt,
    int m0, int n0, int kbase, int kIters, int K, int t, float acc[4][4][4])
{
    const int lane = t & 31;
    const int w    = t >> 5;
    const int g    = lane >> 2;
    const int tid4 = lane & 3;
    const int warpM = (w >> 2) * 64;
    const int warpN = (w & 3) * 32;

    h_prefetch(sm, sm + 2 * HSTG, A, Wt, m0, n0, kbase, K, t);
    CP_COMMIT();

    int st = 0;
    for (int it = 0; it < kIters; it++) {
        if (it + 1 < kIters) {
            h_prefetch(sm + (st ^ 1) * HSTG, sm + (2 + (st ^ 1)) * HSTG,
                       A, Wt, m0, n0, kbase + (it + 1) * 32, K, t);
            CP_COMMIT();
            CP_WAIT(1);
        } else {
            CP_WAIT(0);
        }
        __syncthreads();

        uint32_t* As = sm + st * HSTG;
        uint32_t* Bs = sm + (2 + st) * HSTG;
#pragma unroll
        for (int ks = 0; ks < 2; ks++) {
            uint32_t a[4][4], b[4][2];
            const int kc = 8 * ks + tid4;
#pragma unroll
            for (int mi = 0; mi < 4; mi++) {
                const int r = warpM + 16 * mi + g;
                a[mi][0] = As[r * HS + kc];
                a[mi][1] = As[(r + 8) * HS + kc];
                a[mi][2] = As[r * HS + kc + 4];
                a[mi][3] = As[(r + 8) * HS + kc + 4];
            }
#pragma unroll
            for (int ni = 0; ni < 4; ni++) {
                const int n = warpN + 8 * ni + g;
                b[ni][0] = Bs[n * HS + kc];
                b[ni][1] = Bs[n * HS + kc + 4];
            }
#pragma unroll
            for (int mi = 0; mi < 4; mi++)
#pragma unroll
                for (int ni = 0; ni < 4; ni++)
                    mma_f16(acc[mi][ni], a[mi], b[ni]);
        }
        __syncthreads();
        st ^= 1;
    }
}

// Split-K GEMM for M = W @ WoT^T: grid (4,4,4), z-slab fp32 output
__global__ __launch_bounds__(256, 2) void gemm_h1_splitk(
    const __half* __restrict__ A, const __half* __restrict__ Wt,
    float* __restrict__ C, int N, int K)
{
    extern __shared__ uint32_t sm[];
    const int t  = threadIdx.x;
    const int m0 = blockIdx.y * 128, n0 = blockIdx.x * 128;
    const int z  = blockIdx.z;
    const int lane = t & 31, w = t >> 5;
    const int g = lane >> 2, tid4 = lane & 3;
    const int warpM = (w >> 2) * 64, warpN = (w & 3) * 32;

    float acc[4][4][4];
#pragma unroll
    for (int mi = 0; mi < 4; mi++)
#pragma unroll
        for (int ni = 0; ni < 4; ni++)
#pragma unroll
            for (int c = 0; c < 4; c++) acc[mi][ni][c] = 0.f;

    gemm_h_body(sm, A, Wt, m0, n0, z * 128, 4, K, t, acc);

    float* Cz = C + (size_t)z * DIMV * DIMV;
#pragma unroll
    for (int mi = 0; mi < 4; mi++) {
#pragma unroll
        for (int ni = 0; ni < 4; ni++) {
            const int row = m0 + warpM + 16 * mi + g;
            const int col = n0 + warpN + 8 * ni + 2 * tid4;
            *(float2*)(Cz + (size_t)row * N + col)       = make_float2(acc[mi][ni][0], acc[mi][ni][1]);
            *(float2*)(Cz + (size_t)(row + 8) * N + col) = make_float2(acc[mi][ni][2], acc[mi][ni][3]);
        }
    }
}

// Fused dual-output fp16 GEMM: grid.x = 8; blockIdx.x<4 -> output 0 else 1.
template<bool HALF0, bool HALF1>
__global__ __launch_bounds__(256, 2) void gemm_h2(
    const __half* __restrict__ A,
    const __half* __restrict__ W0, const float* __restrict__ b0, void* __restrict__ C0,
    const __half* __restrict__ W1, const float* __restrict__ b1, void* __restrict__ C1,
    float scale0, float scale1,
    int M, int N, int K)
{
    extern __shared__ uint32_t sm[];
    const int t = threadIdx.x;
    const bool second = blockIdx.x >= 4;
    const __half* Wt  = second ? W1 : W0;
    const float* bias = second ? b1 : b0;
    void* C           = second ? C1 : C0;
    const float scl   = second ? scale1 : scale0;
    const bool doHalf = second ? HALF1 : HALF0;
    const int m0 = blockIdx.y * 128;
    const int n0 = (blockIdx.x & 3) * 128;

    float acc[4][4][4];
#pragma unroll
    for (int mi = 0; mi < 4; mi++)
#pragma unroll
        for (int ni = 0; ni < 4; ni++)
#pragma unroll
            for (int c = 0; c < 4; c++) acc[mi][ni][c] = 0.f;

    gemm_h_body(sm, A, Wt, m0, n0, 0, K / 32, K, t, acc);

    const int lane = t & 31, w = t >> 5;
    const int g = lane >> 2, tid4 = lane & 3;
    const int warpM = (w >> 2) * 64, warpN = (w & 3) * 32;
    const bool hb = (bias != nullptr);
#pragma unroll
    for (int mi = 0; mi < 4; mi++) {
#pragma unroll
        for (int ni = 0; ni < 4; ni++) {
            const int row = m0 + warpM + 16 * mi + g;
            const int col = n0 + warpN + 8 * ni + 2 * tid4;
            float bx = 0.f, by = 0.f;
            if (hb) { bx = bias[col]; by = bias[col + 1]; }
            float v00 = acc[mi][ni][0] + bx, v01 = acc[mi][ni][1] + by;
            float v10 = acc[mi][ni][2] + bx, v11 = acc[mi][ni][3] + by;
            if (doHalf) {
                __half* Ch = (__half*)C;
                *(uint32_t*)(Ch + (size_t)row * N + col)       = f2h2(v00 * scl, v01 * scl);
                *(uint32_t*)(Ch + (size_t)(row + 8) * N + col) = f2h2(v10 * scl, v11 * scl);
            } else {
                float* Cf = (float*)C;
                *(float2*)(Cf + (size_t)row * N + col)       = make_float2(v00, v01);
                *(float2*)(Cf + (size_t)(row + 8) * N + col) = make_float2(v10, v11);
            }
        }
    }
}

// ---------------------------------------------------------------------------
// Flash attention, fp16 m16n8k16 TC, ldmatrix fragment loads, base-2 softmax.
// Q is pre-scaled by log2(e)/8 in the producing GEMM epilogue.
// Block = 128 q-rows x (b,h). 4 warps x 32 q-rows. BKV=64. HSTR=36 u32.
// ---------------------------------------------------------------------------
#define BQ 128
#define BKV 64
#define HSTR 36
#define ATTN_SMEM ((BQ + BKV + BKV + BQ) * HSTR * 4)

__global__ __launch_bounds__(128) void attn_tc(
    const __half* __restrict__ Q, const __half* __restrict__ K,
    const __half* __restrict__ V, float* __restrict__ ctx)
{
    extern __shared__ uint32_t smA[];
    uint32_t* Qs = smA;
    uint32_t* Ks = Qs + BQ * HSTR;
    uint32_t* Vs = Ks + BKV * HSTR;
    uint32_t* Ps = Vs + BKV * HSTR;

    const int qb = blockIdx.x;
    const int bh = blockIdx.y;
    const int b  = bh >> 3, h = bh & 7;
    const int t  = threadIdx.x;
    const int w  = t >> 5, lane = t & 31;
    const int g  = lane >> 2, tid4 = lane & 3;

    const __half* Qb = Q + ((size_t)b * N1V + qb * BQ) * DIMV + h * HD;
    const __half* Kb = K + (size_t)b * N2V * DIMV + h * HD;
    const __half* Vb = V + (size_t)b * N2V * DIMV + h * HD;

#pragma unroll
    for (int j = 0; j < 8; j++) {
        const int idx = t + 128 * j;
        const int row = idx >> 3, c = idx & 7;
        *(float4*)&Qs[row * HSTR + 4 * c] = *(const float4*)(Qb + (size_t)row * DIMV + 8 * c);
    }

    // ldmatrix lane-address components (A-type: rows r0+(lane&15), col sel by lane>>4;
    // B-type: n = 16*nb + 8*(lane>>4) + (lane&7), col sel by (lane>>3)&1)
    const int a_row_off = lane & 15;             // + r0
    const int a_col_off = (lane >> 4) * 4;       // + ks*8
    const int b_row_off = 8 * (lane >> 4) + (lane & 7);   // + 16*nb
    const int b_col_off = ((lane >> 3) & 1) * 4;          // + ks*8

    const uint32_t qbase = smaddr(Qs);
    const uint32_t kbase_s = smaddr(Ks);
    const uint32_t pbase = smaddr(Ps);
    const uint32_t vlbase = smaddr(Vs) + (lane & 15) * (HSTR * 4);

    float m_[2][2], l_[2][2], o[2][8][4];
#pragma unroll
    for (int mi = 0; mi < 2; mi++) {
        m_[mi][0] = -1e30f; m_[mi][1] = -1e30f;
        l_[mi][0] = 0.f;    l_[mi][1] = 0.f;
#pragma unroll
        for (int ni = 0; ni < 8; ni++)
#pragma unroll
            for (int c = 0; c < 4; c++) o[mi][ni][c] = 0.f;
    }

    for (int kt = 0; kt < N2V / BKV; kt++) {
        __syncthreads();
#pragma unroll
        for (int j = 0; j < 4; j++) {
            const int idx = t + 128 * j;
            const int row = idx >> 3, c = idx & 7;
            *(float4*)&Ks[row * HSTR + 4 * c] =
                *(const float4*)(Kb + (size_t)(kt * BKV + row) * DIMV + 8 * c);
            *(float4*)&Vs[row * HSTR + 4 * c] =
                *(const float4*)(Vb + (size_t)(kt * BKV + row) * DIMV + 8 * c);
        }
        __syncthreads();

        float s[2][8][4];
#pragma unroll
        for (int mi = 0; mi < 2; mi++)
#pragma unroll
            for (int ni = 0; ni < 8; ni++)
#pragma unroll
                for (int c = 0; c < 4; c++) s[mi][ni][c] = 0.f;

        // S = Q @ K^T  — fragments via ldmatrix.x4
#pragma unroll
        for (int ks = 0; ks < 4; ks++) {
            uint32_t a[2][4], bf[8][2];
#pragma unroll
            for (int mi = 0; mi < 2; mi++) {
                const int r = w * 32 + 16 * mi + a_row_off;
                ldsm_x4(a[mi][0], a[mi][1], a[mi][2], a[mi][3],
                        qbase + (r * HSTR + ks * 8 + a_col_off) * 4);
            }
#pragma unroll
            for (int nb = 0; nb < 4; nb++) {
                const int n = 16 * nb + b_row_off;
                ldsm_x4(bf[2 * nb][0], bf[2 * nb][1], bf[2 * nb + 1][0], bf[2 * nb + 1][1],
                        kbase_s + (n * HSTR + ks * 8 + b_col_off) * 4);
            }
#pragma unroll
            for (int mi = 0; mi < 2; mi++)
#pragma unroll
                for (int ni = 0; ni < 8; ni++)
                    mma_f16(s[mi][ni], a[mi], bf[ni]);
        }

        // base-2 online softmax (Q pre-scaled by log2e/8)
#pragma unroll
        for (int mi = 0; mi < 2; mi++) {
            float mx0 = -1e30f, mx1 = -1e30f;
#pragma unroll
            for (int ni = 0; ni < 8; ni++) {
                mx0 = fmaxf(mx0, fmaxf(s[mi][ni][0], s[mi][ni][1]));
                mx1 = fmaxf(mx1, fmaxf(s[mi][ni][2], s[mi][ni][3]));
            }
            mx0 = fmaxf(mx0, __shfl_xor_sync(0xffffffffu, mx0, 1));
            mx0 = fmaxf(mx0, __shfl_xor_sync(0xffffffffu, mx0, 2));
            mx1 = fmaxf(mx1, __shfl_xor_sync(0xffffffffu, mx1, 1));
            mx1 = fmaxf(mx1, __shfl_xor_sync(0xffffffffu, mx1, 2));
            const float mn0 = fmaxf(m_[mi][0], mx0);
            const float mn1 = fmaxf(m_[mi][1], mx1);
            float sum0 = 0.f, sum1 = 0.f;
#pragma unroll
            for (int ni = 0; ni < 8; ni++) {
                s[mi][ni][0] = ex2f(s[mi][ni][0] - mn0);
                s[mi][ni][1] = ex2f(s[mi][ni][1] - mn0);
                s[mi][ni][2] = ex2f(s[mi][ni][2] - mn1);
                s[mi][ni][3] = ex2f(s[mi][ni][3] - mn1);
                sum0 += s[mi][ni][0] + s[mi][ni][1];
                sum1 += s[mi][ni][2] + s[mi][ni][3];
            }
            sum0 += __shfl_xor_sync(0xffffffffu, sum0, 1);
            sum0 += __shfl_xor_sync(0xffffffffu, sum0, 2);
            sum1 += __shfl_xor_sync(0xffffffffu, sum1, 1);
            sum1 += __shfl_xor_sync(0xffffffffu, sum1, 2);
            const float al0 = ex2f(m_[mi][0] - mn0);
            const float al1 = ex2f(m_[mi][1] - mn1);
            m_[mi][0] = mn0; m_[mi][1] = mn1;
            l_[mi][0] = l_[mi][0] * al0 + sum0;
            l_[mi][1] = l_[mi][1] * al1 + sum1;
#pragma unroll
            for (int ni = 0; ni < 8; ni++) {
                o[mi][ni][0] *= al0; o[mi][ni][1] *= al0;
                o[mi][ni][2] *= al1; o[mi][ni][3] *= al1;
            }
            const int r = w * 32 + 16 * mi + g;
#pragma unroll
            for (int ni = 0; ni < 8; ni++) {
                Ps[r * HSTR + 4 * ni + tid4]       = f2h2(s[mi][ni][0], s[mi][ni][1]);
                Ps[(r + 8) * HSTR + 4 * ni + tid4] = f2h2(s[mi][ni][2], s[mi][ni][3]);
            }
        }
        __syncwarp();

        // O += P @ V  — P via ldmatrix.x4, V via ldmatrix.x2.trans
#pragma unroll
        for (int ks = 0; ks < 4; ks++) {
            uint32_t a[2][4], bf[8][2];
#pragma unroll
            for (int mi = 0; mi < 2; mi++) {
                const int r = w * 32 + 16 * mi + a_row_off;
                ldsm_x4(a[mi][0], a[mi][1], a[mi][2], a[mi][3],
                        pbase + (r * HSTR + ks * 8 + a_col_off) * 4);
            }
            const uint32_t vk = vlbase + ks * 16 * (HSTR * 4);
#pragma unroll
            for (int ni = 0; ni < 8; ni++)
                ldsm_x2_trans(bf[ni][0], bf[ni][1], vk + ni * 16);
#pragma unroll
            for (int mi = 0; mi < 2; mi++)
#pragma unroll
                for (int ni = 0; ni < 8; ni++)
                    mma_f16(o[mi][ni], a[mi], bf[ni]);
        }
        __syncwarp();
    }

#pragma unroll
    for (int mi = 0; mi < 2; mi++) {
        const float inv0 = 1.0f / l_[mi][0];
        const float inv1 = 1.0f / l_[mi][1];
        const int r = qb * BQ + w * 32 + 16 * mi + g;
#pragma unroll
        for (int ni = 0; ni < 8; ni++) {
            const int col = h * HD + 2 * tid4 + 8 * ni;
            float2 v0 = make_float2(o[mi][ni][0] * inv0, o[mi][ni][1] * inv0);
            float2 v1 = make_float2(o[mi][ni][2] * inv1, o[mi][ni][3] * inv1);
            *(float2*)(ctx + ((size_t)b * N1V + r) * DIMV + col)     = v0;
            *(float2*)(ctx + ((size_t)b * N1V + r + 8) * DIMV + col) = v1;
        }
    }
}

// ---------------------------------------------------------------------------
__global__ __launch_bounds__(128) void score_kernel(
    const float* __restrict__ ctx, const float* __restrict__ u,
    const float* __restrict__ g1, const float* __restrict__ wbo,
    const float* __restrict__ scale, float* __restrict__ out)
{
    const int row = blockIdx.x;
    const int t = threadIdx.x;
    const float4 a = ((const float4*)(ctx + (size_t)row * DIMV))[t];
    const float4 b = ((const float4*)(u   + (size_t)row * DIMV))[t];
    const float4 c = ((const float4*)(g1  + (size_t)row * DIMV))[t];
    const float4 d = ((const float4*)wbo)[t];
    float s = a.x * b.x + a.y * b.y + a.z * b.z + a.w * b.w
            + c.x * d.x + c.y * d.y + c.z * d.z + c.w * d.w;
#pragma unroll
    for (int off = 16; off; off >>= 1)
        s += __shfl_xor_sync(0xffffffffu, s, off);
    __shared__ float red[4];
    if ((t & 31) == 0) red[t >> 5] = s;
    __syncthreads();
    if (t == 0) {
        const float tot = red[0] + red[1] + red[2] + red[3];
        const float z = tot * scale[0];
        out[row] = fmaxf(z, 0.f) + log1pf(__expf(-fabsf(z)));
    }
}

// ---------------------------------------------------------------------------
extern "C" void kernel_launch(void* const* d_in, const int* in_sizes, int n_in,
                              void* d_out, int out_size)
{
    const float* g1    = (const float*)d_in[0];
    const float* g2    = (const float*)d_in[1];
    const float* Wq    = (const float*)d_in[2];
    const float* bq    = (const float*)d_in[3];
    const float* Wk    = (const float*)d_in[4];
    const float* bk    = (const float*)d_in[5];
    const float* Wv    = (const float*)d_in[6];
    const float* bv    = (const float*)d_in[7];
    const float* Wo    = (const float*)d_in[8];
    const float* bo    = (const float*)d_in[9];
    const float* Wb    = (const float*)d_in[10];
    const float* scale = (const float*)d_in[11];
    float* out = (float*)d_out;

    __half *Qp, *Kp, *Vp, *g1h, *g2h, *Wqh, *Wkh, *Wvh, *Wh, *WoTp, *Mthp;
    float *CTXp, *Up, *Mfp, *wbop;
    cudaGetSymbolAddress((void**)&Qp,   g_Q);
    cudaGetSymbolAddress((void**)&Kp,   g_K);
    cudaGetSymbolAddress((void**)&Vp,   g_V);
    cudaGetSymbolAddress((void**)&CTXp, g_CTX);
    cudaGetSymbolAddress((void**)&Up,   g_U);
    cudaGetSymbolAddress((void**)&g1h,  g_g1h);
    cudaGetSymbolAddress((void**)&g2h,  g_g2h);
    cudaGetSymbolAddress((void**)&Wqh,  g_Wqh);
    cudaGetSymbolAddress((void**)&Wkh,  g_Wkh);
    cudaGetSymbolAddress((void**)&Wvh,  g_Wvh);
    cudaGetSymbolAddress((void**)&Wh,   g_Wh);
    cudaGetSymbolAddress((void**)&WoTp, g_WoT);
    cudaGetSymbolAddress((void**)&Mfp,  g_Mf);
    cudaGetSymbolAddress((void**)&Mthp, g_Mth);
    cudaGetSymbolAddress((void**)&wbop, g_wbo);

    cudaFuncSetAttribute((const void*)gemm_h1_splitk, cudaFuncAttributeMaxDynamicSharedMemorySize, GEMMH_SMEM);
    cudaFuncSetAttribute((const void*)gemm_h2<true, false>, cudaFuncAttributeMaxDynamicSharedMemorySize, GEMMH_SMEM);
    cudaFuncSetAttribute((const void*)gemm_h2<true, true >, cudaFuncAttributeMaxDynamicSharedMemorySize, GEMMH_SMEM);
    cudaFuncSetAttribute((const void*)attn_tc, cudaFuncAttributeMaxDynamicSharedMemorySize, ATTN_SMEM);

    const int M = BATCH * N1V;                 // 8192

    cvt2_k<<<dim3((M * DIMV) / 4 / 256, 2), 256>>>(g1, g2, g1h, g2h);
    cvt4_gemv_k<<<dim3(256, 5), 256>>>(Wq, Wk, Wv, Wb, Wqh, Wkh, Wvh, Wh, bo, wbop);
    trans_f2h<<<dim3(16, 16), dim3(32, 8)>>>(Wo, WoTp);

    // M = W @ Wo via split-K=4 mma.sync, partials summed in the transpose
    gemm_h1_splitk<<<dim3(4, 4, 4), 256, GEMMH_SMEM>>>(Wh, WoTp, Mfp, DIMV, DIMV);
    trans_sum4_f2h<<<dim3(16, 16), dim3(32, 8)>>>(Mfp, Mthp);

    // Fused pairs sharing the A operand:
    //   (Q [fp16, pre-scaled log2e/8 for base-2 softmax], U [fp32]) from g1h
    //   (K [fp16], V [fp16]) from g2h
    const float QSCALE = 0.125f * 1.4426950408889634f;
    dim3 gg2(8, M / 128);
    gemm_h2<true, false><<<gg2, 256, GEMMH_SMEM>>>(g1h, Wqh, bq, (void*)Qp, Mthp, nullptr, (void*)Up,
                                                   QSCALE, 1.0f, M, DIMV, DIMV);
    gemm_h2<true, true ><<<gg2, 256, GEMMH_SMEM>>>(g2h, Wkh, bk, (void*)Kp, Wvh, bv, (void*)Vp,
                                                   1.0f, 1.0f, M, DIMV, DIMV);

    attn_tc<<<dim3(N1V / BQ, BATCH * NHEAD), 128, ATTN_SMEM>>>(Qp, Kp, Vp, CTXp);

    score_kernel<<<M, 128>>>(CTXp, Up, g1, wbop, scale, out);
}